// round 1
// baseline (speedup 1.0000x reference)
#include <cuda_runtime.h>
#include <math.h>

#define S_LEN 2048
#define D_DIM 1024
#define B_SZ  2
#define NH    16
#define DHE   64
#define WIN   128
#define NTOK  (B_SZ * S_LEN)   // 4096
#define D3    (3 * D_DIM)      // 3072

// ---------------- scratch (no allocs allowed -> device globals) ----------------
__device__ float g_qkv[(size_t)NTOK * D3];       // [B,S,3D]
__device__ float g_attn[(size_t)NTOK * D_DIM];   // attention pre-proj [B,S,D]
__device__ float g_attnout[(size_t)NTOK * D_DIM];
__device__ float g_xattn[(size_t)NTOK * D_DIM];
__device__ float g_xwave[(size_t)NTOK * D_DIM];

// ---------------- SGEMM: C[M,N] = A[M,K] @ W[N,K]^T + bias ----------------
// 128x128 tile, BK=16, 256 threads, 8x8 micro-tile.
__global__ void __launch_bounds__(256) sgemm_nt_bias(
    const float* __restrict__ A, const float* __restrict__ W,
    const float* __restrict__ bias, float* __restrict__ C,
    int M, int N, int K)
{
    __shared__ float As[16][128];
    __shared__ float Bs[16][128];
    const int row0 = blockIdx.y * 128;
    const int col0 = blockIdx.x * 128;
    const int t  = threadIdx.x;
    const int tx = t & 15;
    const int ty = t >> 4;

    float acc[8][8];
#pragma unroll
    for (int i = 0; i < 8; i++)
#pragma unroll
        for (int j = 0; j < 8; j++) acc[i][j] = 0.f;

    for (int k0 = 0; k0 < K; k0 += 16) {
#pragma unroll
        for (int i = 0; i < 2; i++) {
            int idx = t + 256 * i;        // 0..511 float4 slots
            int r   = idx >> 2;           // 0..127
            int c4  = (idx & 3) * 4;      // 0,4,8,12
            float4 a = *(const float4*)(A + (size_t)(row0 + r) * K + k0 + c4);
            float4 w = *(const float4*)(W + (size_t)(col0 + r) * K + k0 + c4);
            As[c4 + 0][r] = a.x; As[c4 + 1][r] = a.y;
            As[c4 + 2][r] = a.z; As[c4 + 3][r] = a.w;
            Bs[c4 + 0][r] = w.x; Bs[c4 + 1][r] = w.y;
            Bs[c4 + 2][r] = w.z; Bs[c4 + 3][r] = w.w;
        }
        __syncthreads();
#pragma unroll
        for (int k = 0; k < 16; k++) {
            float ra[8], rb[8];
#pragma unroll
            for (int i = 0; i < 8; i++) ra[i] = As[k][ty * 8 + i];
#pragma unroll
            for (int j = 0; j < 8; j++) rb[j] = Bs[k][tx * 8 + j];
#pragma unroll
            for (int i = 0; i < 8; i++)
#pragma unroll
                for (int j = 0; j < 8; j++) acc[i][j] += ra[i] * rb[j];
        }
        __syncthreads();
    }

#pragma unroll
    for (int i = 0; i < 8; i++) {
        float* crow = C + (size_t)(row0 + ty * 8 + i) * N + col0 + tx * 8;
#pragma unroll
        for (int j = 0; j < 8; j++)
            crow[j] = acc[i][j] + bias[col0 + tx * 8 + j];
    }
}

// ---------------- windowed attention ----------------
// grid: (S/32, H, B), 256 threads. Thread (qi = t>>3, sub = t&7):
// scores for 4 keys (sub*4..sub*4+3), output dims sub*8..sub*8+7.
__global__ void __launch_bounds__(256) attn_kernel()
{
    __shared__ float Qs[32][68];
    __shared__ float Ks[32][68];
    __shared__ float Vs[32][68];
    __shared__ float P[32][36];

    const int q0 = blockIdx.x * 32;
    const int h  = blockIdx.y;
    const int b  = blockIdx.z;
    const int t  = threadIdx.x;

    // load Q tile (scaled by 1/sqrt(DH))
    {
        int r = t >> 3, off = (t & 7) * 8;
        const float* src = g_qkv + (size_t)(b * S_LEN + q0 + r) * D3 + h * DHE + off;
        float4 v0 = *(const float4*)src;
        float4 v1 = *(const float4*)(src + 4);
        const float sc = 0.125f;
        v0.x *= sc; v0.y *= sc; v0.z *= sc; v0.w *= sc;
        v1.x *= sc; v1.y *= sc; v1.z *= sc; v1.w *= sc;
        *(float4*)&Qs[r][off]     = v0;
        *(float4*)&Qs[r][off + 4] = v1;
    }

    const int qi  = t >> 3;
    const int sub = t & 7;
    const int qg  = q0 + qi;

    float m = -INFINITY, l = 0.f;
    float4 o0 = make_float4(0.f, 0.f, 0.f, 0.f);
    float4 o1 = make_float4(0.f, 0.f, 0.f, 0.f);

    const int kstart = (q0 - WIN) > 0 ? (q0 - WIN) : 0;
    const int kend   = (q0 + 32 + WIN) < S_LEN ? (q0 + 32 + WIN) : S_LEN;

    for (int kc = kstart; kc < kend; kc += 32) {
        __syncthreads();   // protect Ks/Vs/P reuse
        {
            int r = t >> 3, off = (t & 7) * 8;
            const float* kp = g_qkv + (size_t)(b * S_LEN + kc + r) * D3 + D_DIM + h * DHE + off;
            const float* vp = kp + D_DIM;
            *(float4*)&Ks[r][off]     = *(const float4*)kp;
            *(float4*)&Ks[r][off + 4] = *(const float4*)(kp + 4);
            *(float4*)&Vs[r][off]     = *(const float4*)vp;
            *(float4*)&Vs[r][off + 4] = *(const float4*)(vp + 4);
        }
        __syncthreads();

        float s[4];
#pragma unroll
        for (int j = 0; j < 4; j++) s[j] = 0.f;
#pragma unroll
        for (int d4 = 0; d4 < 16; d4++) {
            float4 qv = *(const float4*)&Qs[qi][d4 * 4];
#pragma unroll
            for (int j = 0; j < 4; j++) {
                float4 kv = *(const float4*)&Ks[sub * 4 + j][d4 * 4];
                s[j] += qv.x * kv.x + qv.y * kv.y + qv.z * kv.z + qv.w * kv.w;
            }
        }

        float mloc = -INFINITY;
#pragma unroll
        for (int j = 0; j < 4; j++) {
            int kg = kc + sub * 4 + j;
            if (kg < qg - WIN || kg > qg + WIN) s[j] = -INFINITY;
            mloc = fmaxf(mloc, s[j]);
        }
#pragma unroll
        for (int o = 1; o < 8; o <<= 1)
            mloc = fmaxf(mloc, __shfl_xor_sync(0xffffffffu, mloc, o, 8));

        float mnew  = fmaxf(m, mloc);
        float alpha = (mnew == -INFINITY) ? 1.f : __expf(m - mnew);
        float ps = 0.f;
#pragma unroll
        for (int j = 0; j < 4; j++) {
            float p = (s[j] == -INFINITY) ? 0.f : __expf(s[j] - mnew);
            P[qi][sub * 4 + j] = p;
            ps += p;
        }
#pragma unroll
        for (int o = 1; o < 8; o <<= 1)
            ps += __shfl_xor_sync(0xffffffffu, ps, o, 8);

        l = l * alpha + ps;
        m = mnew;
        o0.x *= alpha; o0.y *= alpha; o0.z *= alpha; o0.w *= alpha;
        o1.x *= alpha; o1.y *= alpha; o1.z *= alpha; o1.w *= alpha;

        __syncthreads();   // P visible
#pragma unroll
        for (int kk = 0; kk < 32; kk++) {
            float p = P[qi][kk];
            float4 v0 = *(const float4*)&Vs[kk][sub * 8];
            float4 v1 = *(const float4*)&Vs[kk][sub * 8 + 4];
            o0.x += p * v0.x; o0.y += p * v0.y; o0.z += p * v0.z; o0.w += p * v0.w;
            o1.x += p * v1.x; o1.y += p * v1.y; o1.z += p * v1.z; o1.w += p * v1.w;
        }
    }

    const float inv = 1.0f / l;
    float* dst = g_attn + (size_t)(b * S_LEN + qg) * D_DIM + h * DHE + sub * 8;
    o0.x *= inv; o0.y *= inv; o0.z *= inv; o0.w *= inv;
    o1.x *= inv; o1.y *= inv; o1.z *= inv; o1.w *= inv;
    *(float4*)dst       = o0;
    *(float4*)(dst + 4) = o1;
}

// ---------------- fused add + LayerNorm ----------------
__global__ void __launch_bounds__(256) add_ln_kernel(
    const float* __restrict__ A, const float* __restrict__ Bv,
    const float* __restrict__ g, const float* __restrict__ beta,
    float* __restrict__ out)
{
    __shared__ float red[8];
    const int row = blockIdx.x;
    const int t   = threadIdx.x;
    const float* pa = A  + (size_t)row * D_DIM;
    const float* pb = Bv + (size_t)row * D_DIM;

    float v[4];
    float s = 0.f;
#pragma unroll
    for (int i = 0; i < 4; i++) { v[i] = pa[t + i * 256] + pb[t + i * 256]; s += v[i]; }
#pragma unroll
    for (int o = 16; o; o >>= 1) s += __shfl_xor_sync(0xffffffffu, s, o);
    if ((t & 31) == 0) red[t >> 5] = s;
    __syncthreads();
    float tot = 0.f;
#pragma unroll
    for (int i = 0; i < 8; i++) tot += red[i];
    const float mu = tot * (1.f / (float)D_DIM);
    __syncthreads();

    float s2 = 0.f;
#pragma unroll
    for (int i = 0; i < 4; i++) { float d = v[i] - mu; s2 += d * d; }
#pragma unroll
    for (int o = 16; o; o >>= 1) s2 += __shfl_xor_sync(0xffffffffu, s2, o);
    if ((t & 31) == 0) red[t >> 5] = s2;
    __syncthreads();
    float tot2 = 0.f;
#pragma unroll
    for (int i = 0; i < 8; i++) tot2 += red[i];
    const float inv = rsqrtf(tot2 * (1.f / (float)D_DIM) + 1e-5f);

    float* po = out + (size_t)row * D_DIM;
#pragma unroll
    for (int i = 0; i < 4; i++) {
        int c = t + i * 256;
        po[c] = (v[i] - mu) * inv * g[c] + beta[c];
    }
}

// ---------------- spectral block: per-(b,d) 2048-pt Stockham FFT ----------------
__device__ __forceinline__ float2 cmulf(float2 a, float2 b) {
    return make_float2(a.x * b.x - a.y * b.y, a.x * b.y + a.y * b.x);
}

// Stockham radix-2 autosort FFT, 2048 points, 256 threads. Returns result buffer.
__device__ float2* fft2048(float2* cur, float2* oth, float sign)
{
    int n = 2048;
    int ls = 0;
    while (n > 1) {
        const int ss = 1 << ls;
#pragma unroll 1
        for (int idx = threadIdx.x; idx < 1024; idx += 256) {
            int p = idx >> ls;
            int q = idx & (ss - 1);
            float2 a  = cur[q + ss * p];
            float2 bb = cur[q + ss * p + 1024];
            float2 sum = make_float2(a.x + bb.x, a.y + bb.y);
            float2 dif = make_float2(a.x - bb.x, a.y - bb.y);
            float sn, cs;
            sincospif(sign * 2.0f * (float)p / (float)n, &sn, &cs);
            oth[q + 2 * ss * p]      = sum;
            oth[q + 2 * ss * p + ss] = cmulf(dif, make_float2(cs, sn));
        }
        __syncthreads();
        float2* tmp = cur; cur = oth; oth = tmp;
        n >>= 1; ls++;
    }
    return cur;
}

__global__ void __launch_bounds__(256) spectral_kernel(
    const float* __restrict__ x, const float* __restrict__ wr,
    const float* __restrict__ wi, float* __restrict__ xwave)
{
    __shared__ float2 bufA[2048];
    __shared__ float2 bufB[2048];
    const int d = blockIdx.x;
    const int b = blockIdx.y;

    const float* xp = x + (size_t)b * S_LEN * D_DIM + d;
    for (int s = threadIdx.x; s < 2048; s += 256)
        bufA[s] = make_float2(xp[(size_t)s * D_DIM], 0.f);
    __syncthreads();

    float2* cur = fft2048(bufA, bufB, -1.0f);          // forward (rfft sign)
    float2* oth = (cur == bufA) ? bufB : bufA;

    // multiply by Hermitian-extended filter
    for (int k = threadIdx.x; k < 2048; k += 256) {
        float cr, ci;
        if (k <= 1024) {
            cr = wr[(size_t)k * D_DIM + d];
            ci = wi[(size_t)k * D_DIM + d];
        } else {
            cr =  wr[(size_t)(2048 - k) * D_DIM + d];
            ci = -wi[(size_t)(2048 - k) * D_DIM + d];
        }
        cur[k] = cmulf(cur[k], make_float2(cr, ci));
    }
    __syncthreads();

    float2* res = fft2048(cur, oth, +1.0f);            // inverse (scale below)

    float* dst = xwave + (size_t)b * S_LEN * D_DIM + d;
    const float invn = 1.0f / 2048.0f;
    for (int s = threadIdx.x; s < 2048; s += 256)
        dst[(size_t)s * D_DIM] = res[s].x * invn;      // Re(IDFT) == irfft
}

// ---------------- launcher ----------------
extern "C" void kernel_launch(void* const* d_in, const int* in_sizes, int n_in,
                              void* d_out, int out_size)
{
    const float* x     = (const float*)d_in[0];
    const float* in_w  = (const float*)d_in[1];
    const float* in_b  = (const float*)d_in[2];
    const float* out_w = (const float*)d_in[3];
    const float* out_b = (const float*)d_in[4];
    const float* ln1g  = (const float*)d_in[5];
    const float* ln1b  = (const float*)d_in[6];
    const float* wr    = (const float*)d_in[7];
    const float* wi    = (const float*)d_in[8];
    const float* ln2g  = (const float*)d_in[9];
    const float* ln2b  = (const float*)d_in[10];
    float* out = (float*)d_out;

    float *qkv, *attn, *attnout, *xattn, *xwave;
    cudaGetSymbolAddress((void**)&qkv,     g_qkv);
    cudaGetSymbolAddress((void**)&attn,    g_attn);
    cudaGetSymbolAddress((void**)&attnout, g_attnout);
    cudaGetSymbolAddress((void**)&xattn,   g_xattn);
    cudaGetSymbolAddress((void**)&xwave,   g_xwave);

    // spectral path first (independent of attention path)
    spectral_kernel<<<dim3(D_DIM, B_SZ), 256>>>(x, wr, wi, xwave);

    // QKV projection: [4096,3072]
    sgemm_nt_bias<<<dim3(D3 / 128, NTOK / 128), 256>>>(x, in_w, in_b, qkv, NTOK, D3, D_DIM);

    // windowed attention
    attn_kernel<<<dim3(S_LEN / 32, NH, B_SZ), 256>>>();

    // output projection
    sgemm_nt_bias<<<dim3(D_DIM / 128, NTOK / 128), 256>>>(attn, out_w, out_b, attnout,
                                                          NTOK, D_DIM, D_DIM);

    // x_attn = LN1(x + attn_out)
    add_ln_kernel<<<NTOK, 256>>>(x, attnout, ln1g, ln1b, xattn);

    // out = LN2(x_attn + x_wave)
    add_ln_kernel<<<NTOK, 256>>>(xattn, xwave, ln2g, ln2b, out);
}

// round 4
// speedup vs baseline: 1.0333x; 1.0333x over previous
#include <cuda_runtime.h>
#include <math.h>

#define S_LEN 2048
#define D_DIM 1024
#define B_SZ  2
#define NH    16
#define DHE   64
#define WIN   128
#define NTOK  (B_SZ * S_LEN)   // 4096
#define D3    (3 * D_DIM)      // 3072

// padded smem index to break Stockham store bank conflicts
#define SMAP(i) ((i) + ((i) >> 4))

// ---------------- scratch (no allocs allowed -> device globals) ----------------
__device__ float g_qkv[(size_t)NTOK * D3];       // [B,S,3D]
__device__ float g_attn[(size_t)NTOK * D_DIM];   // attention pre-proj [B,S,D]
__device__ float g_attnout[(size_t)NTOK * D_DIM];
__device__ float g_xattn[(size_t)NTOK * D_DIM];
__device__ float g_xwave[(size_t)NTOK * D_DIM];

// ---------------- SGEMM: C[M,N] = A[M,K] @ W[N,K]^T + bias ----------------
// 128x128 tile, BK=16, 256 threads, 8x8 micro-tile, double-buffered smem.
__global__ void __launch_bounds__(256) sgemm_nt_bias(
    const float* __restrict__ A, const float* __restrict__ W,
    const float* __restrict__ bias, float* __restrict__ C,
    int M, int N, int K)
{
    __shared__ float As[2][16][128];
    __shared__ float Bs[2][16][128];
    const int row0 = blockIdx.y * 128;
    const int col0 = blockIdx.x * 128;
    const int t  = threadIdx.x;
    const int tx = t & 15;
    const int ty = t >> 4;

    // load mapping: idx = t + 256*i -> r = idx>>2 (0..127), c4 = (idx&3)*4
    const int r0l = t >> 2;
    const int c0l = (t & 3) * 4;
    const int r1l = (t + 256) >> 2;
    const int c1l = ((t + 256) & 3) * 4;

    float acc[8][8];
#pragma unroll
    for (int i = 0; i < 8; i++)
#pragma unroll
        for (int j = 0; j < 8; j++) acc[i][j] = 0.f;

    float4 pa0, pa1, pw0, pw1;

    // prologue: load tile 0 into regs, store to buf 0
    pa0 = *(const float4*)(A + (size_t)(row0 + r0l) * K + c0l);
    pa1 = *(const float4*)(A + (size_t)(row0 + r1l) * K + c1l);
    pw0 = *(const float4*)(W + (size_t)(col0 + r0l) * K + c0l);
    pw1 = *(const float4*)(W + (size_t)(col0 + r1l) * K + c1l);
    As[0][c0l + 0][r0l] = pa0.x; As[0][c0l + 1][r0l] = pa0.y;
    As[0][c0l + 2][r0l] = pa0.z; As[0][c0l + 3][r0l] = pa0.w;
    As[0][c1l + 0][r1l] = pa1.x; As[0][c1l + 1][r1l] = pa1.y;
    As[0][c1l + 2][r1l] = pa1.z; As[0][c1l + 3][r1l] = pa1.w;
    Bs[0][c0l + 0][r0l] = pw0.x; Bs[0][c0l + 1][r0l] = pw0.y;
    Bs[0][c0l + 2][r0l] = pw0.z; Bs[0][c0l + 3][r0l] = pw0.w;
    Bs[0][c1l + 0][r1l] = pw1.x; Bs[0][c1l + 1][r1l] = pw1.y;
    Bs[0][c1l + 2][r1l] = pw1.z; Bs[0][c1l + 3][r1l] = pw1.w;
    __syncthreads();

    const int ntiles = K >> 4;
    for (int kt = 0; kt < ntiles; kt++) {
        const int cb = kt & 1;
        const bool hasnext = (kt + 1 < ntiles);
        if (hasnext) {
            const int k0 = (kt + 1) << 4;
            pa0 = *(const float4*)(A + (size_t)(row0 + r0l) * K + k0 + c0l);
            pa1 = *(const float4*)(A + (size_t)(row0 + r1l) * K + k0 + c1l);
            pw0 = *(const float4*)(W + (size_t)(col0 + r0l) * K + k0 + c0l);
            pw1 = *(const float4*)(W + (size_t)(col0 + r1l) * K + k0 + c1l);
        }
#pragma unroll
        for (int k = 0; k < 16; k++) {
            float ra[8], rb[8];
#pragma unroll
            for (int i = 0; i < 8; i++) ra[i] = As[cb][k][ty * 8 + i];
#pragma unroll
            for (int j = 0; j < 8; j++) rb[j] = Bs[cb][k][tx * 8 + j];
#pragma unroll
            for (int i = 0; i < 8; i++)
#pragma unroll
                for (int j = 0; j < 8; j++) acc[i][j] += ra[i] * rb[j];
        }
        if (hasnext) {
            const int nb = cb ^ 1;
            As[nb][c0l + 0][r0l] = pa0.x; As[nb][c0l + 1][r0l] = pa0.y;
            As[nb][c0l + 2][r0l] = pa0.z; As[nb][c0l + 3][r0l] = pa0.w;
            As[nb][c1l + 0][r1l] = pa1.x; As[nb][c1l + 1][r1l] = pa1.y;
            As[nb][c1l + 2][r1l] = pa1.z; As[nb][c1l + 3][r1l] = pa1.w;
            Bs[nb][c0l + 0][r0l] = pw0.x; Bs[nb][c0l + 1][r0l] = pw0.y;
            Bs[nb][c0l + 2][r0l] = pw0.z; Bs[nb][c0l + 3][r0l] = pw0.w;
            Bs[nb][c1l + 0][r1l] = pw1.x; Bs[nb][c1l + 1][r1l] = pw1.y;
            Bs[nb][c1l + 2][r1l] = pw1.z; Bs[nb][c1l + 3][r1l] = pw1.w;
        }
        __syncthreads();
    }

#pragma unroll
    for (int i = 0; i < 8; i++) {
        float* crow = C + (size_t)(row0 + ty * 8 + i) * N + col0 + tx * 8;
#pragma unroll
        for (int j = 0; j < 8; j++)
            crow[j] = acc[i][j] + bias[col0 + tx * 8 + j];
    }
}

// ---------------- windowed attention ----------------
__global__ void __launch_bounds__(256) attn_kernel()
{
    __shared__ float Qs[32][68];
    __shared__ float Ks[32][68];
    __shared__ float Vs[32][68];
    __shared__ float P[32][36];

    const int q0 = blockIdx.x * 32;
    const int h  = blockIdx.y;
    const int b  = blockIdx.z;
    const int t  = threadIdx.x;

    {
        int r = t >> 3, off = (t & 7) * 8;
        const float* src = g_qkv + (size_t)(b * S_LEN + q0 + r) * D3 + h * DHE + off;
        float4 v0 = *(const float4*)src;
        float4 v1 = *(const float4*)(src + 4);
        const float sc = 0.125f;
        v0.x *= sc; v0.y *= sc; v0.z *= sc; v0.w *= sc;
        v1.x *= sc; v1.y *= sc; v1.z *= sc; v1.w *= sc;
        *(float4*)&Qs[r][off]     = v0;
        *(float4*)&Qs[r][off + 4] = v1;
    }

    const int qi  = t >> 3;
    const int sub = t & 7;
    const int qg  = q0 + qi;

    float m = -INFINITY, l = 0.f;
    float4 o0 = make_float4(0.f, 0.f, 0.f, 0.f);
    float4 o1 = make_float4(0.f, 0.f, 0.f, 0.f);

    const int kstart = (q0 - WIN) > 0 ? (q0 - WIN) : 0;
    const int kend   = (q0 + 32 + WIN) < S_LEN ? (q0 + 32 + WIN) : S_LEN;

    for (int kc = kstart; kc < kend; kc += 32) {
        __syncthreads();
        {
            int r = t >> 3, off = (t & 7) * 8;
            const float* kp = g_qkv + (size_t)(b * S_LEN + kc + r) * D3 + D_DIM + h * DHE + off;
            const float* vp = kp + D_DIM;
            *(float4*)&Ks[r][off]     = *(const float4*)kp;
            *(float4*)&Ks[r][off + 4] = *(const float4*)(kp + 4);
            *(float4*)&Vs[r][off]     = *(const float4*)vp;
            *(float4*)&Vs[r][off + 4] = *(const float4*)(vp + 4);
        }
        __syncthreads();

        float s[4];
#pragma unroll
        for (int j = 0; j < 4; j++) s[j] = 0.f;
#pragma unroll
        for (int d4 = 0; d4 < 16; d4++) {
            float4 qv = *(const float4*)&Qs[qi][d4 * 4];
#pragma unroll
            for (int j = 0; j < 4; j++) {
                float4 kv = *(const float4*)&Ks[sub * 4 + j][d4 * 4];
                s[j] += qv.x * kv.x + qv.y * kv.y + qv.z * kv.z + qv.w * kv.w;
            }
        }

        float mloc = -INFINITY;
#pragma unroll
        for (int j = 0; j < 4; j++) {
            int kg = kc + sub * 4 + j;
            if (kg < qg - WIN || kg > qg + WIN) s[j] = -INFINITY;
            mloc = fmaxf(mloc, s[j]);
        }
#pragma unroll
        for (int o = 1; o < 8; o <<= 1)
            mloc = fmaxf(mloc, __shfl_xor_sync(0xffffffffu, mloc, o, 8));

        float mnew  = fmaxf(m, mloc);
        float alpha = (mnew == -INFINITY) ? 1.f : __expf(m - mnew);
        float ps = 0.f;
#pragma unroll
        for (int j = 0; j < 4; j++) {
            float p = (s[j] == -INFINITY) ? 0.f : __expf(s[j] - mnew);
            P[qi][sub * 4 + j] = p;
            ps += p;
        }
#pragma unroll
        for (int o = 1; o < 8; o <<= 1)
            ps += __shfl_xor_sync(0xffffffffu, ps, o, 8);

        l = l * alpha + ps;
        m = mnew;
        o0.x *= alpha; o0.y *= alpha; o0.z *= alpha; o0.w *= alpha;
        o1.x *= alpha; o1.y *= alpha; o1.z *= alpha; o1.w *= alpha;

        __syncthreads();
#pragma unroll
        for (int kk = 0; kk < 32; kk++) {
            float p = P[qi][kk];
            float4 v0 = *(const float4*)&Vs[kk][sub * 8];
            float4 v1 = *(const float4*)&Vs[kk][sub * 8 + 4];
            o0.x += p * v0.x; o0.y += p * v0.y; o0.z += p * v0.z; o0.w += p * v0.w;
            o1.x += p * v1.x; o1.y += p * v1.y; o1.z += p * v1.z; o1.w += p * v1.w;
        }
    }

    const float inv = 1.0f / l;
    float* dst = g_attn + (size_t)(b * S_LEN + qg) * D_DIM + h * DHE + sub * 8;
    o0.x *= inv; o0.y *= inv; o0.z *= inv; o0.w *= inv;
    o1.x *= inv; o1.y *= inv; o1.z *= inv; o1.w *= inv;
    *(float4*)dst       = o0;
    *(float4*)(dst + 4) = o1;
}

// ---------------- fused add + LayerNorm ----------------
__global__ void __launch_bounds__(256) add_ln_kernel(
    const float* __restrict__ A, const float* __restrict__ Bv,
    const float* __restrict__ g, const float* __restrict__ beta,
    float* __restrict__ out)
{
    __shared__ float red[8];
    const int row = blockIdx.x;
    const int t   = threadIdx.x;
    const float* pa = A  + (size_t)row * D_DIM;
    const float* pb = Bv + (size_t)row * D_DIM;

    float v[4];
    float s = 0.f;
#pragma unroll
    for (int i = 0; i < 4; i++) { v[i] = pa[t + i * 256] + pb[t + i * 256]; s += v[i]; }
#pragma unroll
    for (int o = 16; o; o >>= 1) s += __shfl_xor_sync(0xffffffffu, s, o);
    if ((t & 31) == 0) red[t >> 5] = s;
    __syncthreads();
    float tot = 0.f;
#pragma unroll
    for (int i = 0; i < 8; i++) tot += red[i];
    const float mu = tot * (1.f / (float)D_DIM);
    __syncthreads();

    float s2 = 0.f;
#pragma unroll
    for (int i = 0; i < 4; i++) { float d = v[i] - mu; s2 += d * d; }
#pragma unroll
    for (int o = 16; o; o >>= 1) s2 += __shfl_xor_sync(0xffffffffu, s2, o);
    if ((t & 31) == 0) red[t >> 5] = s2;
    __syncthreads();
    float tot2 = 0.f;
#pragma unroll
    for (int i = 0; i < 8; i++) tot2 += red[i];
    const float inv = rsqrtf(tot2 * (1.f / (float)D_DIM) + 1e-5f);

    float* po = out + (size_t)row * D_DIM;
#pragma unroll
    for (int i = 0; i < 4; i++) {
        int c = t + i * 256;
        po[c] = (v[i] - mu) * inv * g[c] + beta[c];
    }
}

// ---------------- spectral block ----------------
// Pack two real d-columns as one complex sequence; one fwd + one inv FFT per pair.
// Radix-4 fused Stockham: 5 radix-4 stages + 1 radix-2, 1 sincospif per quartet.
__device__ __forceinline__ float2 cmul(float2 a, float2 b) {
    return make_float2(a.x * b.x - a.y * b.y, a.x * b.y + a.y * b.x);
}

template<int SIGN>
__device__ __forceinline__ void fft2048_r4(float2*& cur, float2*& oth)
{
    int n = 2048, ls = 0;
#pragma unroll
    for (int st = 0; st < 5; st++) {
        const int ss = 1 << ls;
        const float fn = (2.0f * (float)SIGN) / (float)n;
#pragma unroll
        for (int ii = 0; ii < 2; ii++) {
            const int idx = threadIdx.x + 256 * ii;      // base = q + ss*p == idx
            const int p = idx >> ls;
            const int q = idx & (ss - 1);
            float2 x0 = cur[SMAP(idx)];
            float2 x1 = cur[SMAP(idx + 512)];
            float2 x2 = cur[SMAP(idx + 1024)];
            float2 x3 = cur[SMAP(idx + 1536)];
            float sn, cs;
            sincospif(fn * (float)p, &sn, &cs);
            const float2 wA = make_float2(cs, sn);
            const float2 wB = cmul(wA, wA);
            float2 a0 = make_float2(x0.x + x2.x, x0.y + x2.y);
            float2 a1 = make_float2(x0.x - x2.x, x0.y - x2.y);
            float2 b0 = make_float2(x1.x + x3.x, x1.y + x3.y);
            float2 u  = make_float2(x1.x - x3.x, x1.y - x3.y);
            float2 b1 = make_float2(-(float)SIGN * u.y, (float)SIGN * u.x); // u * (SIGN*i)
            float2 A1p = cmul(a1, wA);
            float2 A1q = cmul(b1, wA);
            const int ob = q + 4 * ss * p;
            oth[SMAP(ob)]          = make_float2(a0.x + b0.x, a0.y + b0.y);
            float2 d0v = make_float2(a0.x - b0.x, a0.y - b0.y);
            oth[SMAP(ob + 2 * ss)] = cmul(d0v, wB);
            oth[SMAP(ob + ss)]     = make_float2(A1p.x + A1q.x, A1p.y + A1q.y);
            float2 d1v = make_float2(A1p.x - A1q.x, A1p.y - A1q.y);
            oth[SMAP(ob + 3 * ss)] = cmul(d1v, wB);
        }
        __syncthreads();
        float2* t = cur; cur = oth; oth = t;
        n >>= 2; ls += 2;
    }
    // final radix-2 stage: ss=1024, n=2, twiddle=1
#pragma unroll
    for (int ii = 0; ii < 4; ii++) {
        const int q = threadIdx.x + 256 * ii;
        float2 a = cur[SMAP(q)];
        float2 b = cur[SMAP(q + 1024)];
        oth[SMAP(q)]        = make_float2(a.x + b.x, a.y + b.y);
        oth[SMAP(q + 1024)] = make_float2(a.x - b.x, a.y - b.y);
    }
    __syncthreads();
    { float2* t = cur; cur = oth; oth = t; }
}

__global__ void __launch_bounds__(256) spectral_kernel(
    const float* __restrict__ x, const float* __restrict__ wr,
    const float* __restrict__ wi, float* __restrict__ xwave)
{
    __shared__ float2 bufA[2176];
    __shared__ float2 bufB[2176];
    const int d0 = blockIdx.x * 2;      // column pair (d0, d0+1)
    const int b  = blockIdx.y;

    // z[s] = x[s][d0] + i*x[s][d0+1]
    const float* xp = x + (size_t)b * S_LEN * D_DIM + d0;
    for (int s = threadIdx.x; s < 2048; s += 256)
        bufA[SMAP(s)] = *(const float2*)(xp + (size_t)s * D_DIM);
    __syncthreads();

    float2* cur = bufA;
    float2* oth = bufB;
    fft2048_r4<-1>(cur, oth);   // forward

    // Hermitian split -> filter -> repack W = Y1 + i*Y2
    for (int k = threadIdx.x; k < 2048; k += 256) {
        const int km = (2048 - k) & 2047;
        float2 Zk = cur[SMAP(k)];
        float2 Zm = cur[SMAP(km)];
        // A = 0.5*(Zk + conj(Zm)),  Bc = -0.5i*(Zk - conj(Zm))
        float2 Av = make_float2(0.5f * (Zk.x + Zm.x), 0.5f * (Zk.y - Zm.y));
        float2 Bc = make_float2(0.5f * (Zk.y + Zm.y), -0.5f * (Zk.x - Zm.x));
        const int   kf  = (k <= 1024) ? k : 2048 - k;
        const float sgn = (k <= 1024) ? 1.f : -1.f;
        float2 wrp = *(const float2*)(wr + (size_t)kf * D_DIM + d0);
        float2 wip = *(const float2*)(wi + (size_t)kf * D_DIM + d0);
        float2 c1 = make_float2(wrp.x, sgn * wip.x);
        float2 c2 = make_float2(wrp.y, sgn * wip.y);
        float2 Y1 = cmul(Av, c1);
        float2 Y2 = cmul(Bc, c2);
        oth[SMAP(k)] = make_float2(Y1.x - Y2.y, Y1.y + Y2.x);   // Y1 + i*Y2
    }
    __syncthreads();
    { float2* t = cur; cur = oth; oth = t; }

    fft2048_r4<1>(cur, oth);    // inverse (scale below)

    float* dst = xwave + (size_t)b * S_LEN * D_DIM + d0;
    const float invn = 1.0f / 2048.0f;
    for (int s = threadIdx.x; s < 2048; s += 256) {
        float2 r = cur[SMAP(s)];
        *(float2*)(dst + (size_t)s * D_DIM) = make_float2(r.x * invn, r.y * invn);
    }
}

// ---------------- launcher ----------------
extern "C" void kernel_launch(void* const* d_in, const int* in_sizes, int n_in,
                              void* d_out, int out_size)
{
    const float* x     = (const float*)d_in[0];
    const float* in_w  = (const float*)d_in[1];
    const float* in_b  = (const float*)d_in[2];
    const float* out_w = (const float*)d_in[3];
    const float* out_b = (const float*)d_in[4];
    const float* ln1g  = (const float*)d_in[5];
    const float* ln1b  = (const float*)d_in[6];
    const float* wr    = (const float*)d_in[7];
    const float* wi    = (const float*)d_in[8];
    const float* ln2g  = (const float*)d_in[9];
    const float* ln2b  = (const float*)d_in[10];
    float* out = (float*)d_out;

    float *qkv, *attn, *attnout, *xattn, *xwave;
    cudaGetSymbolAddress((void**)&qkv,     g_qkv);
    cudaGetSymbolAddress((void**)&attn,    g_attn);
    cudaGetSymbolAddress((void**)&attnout, g_attnout);
    cudaGetSymbolAddress((void**)&xattn,   g_xattn);
    cudaGetSymbolAddress((void**)&xwave,   g_xwave);

    // spectral path (independent): 512 column-pairs x 2 batches
    spectral_kernel<<<dim3(D_DIM / 2, B_SZ), 256>>>(x, wr, wi, xwave);

    // QKV projection: [4096,3072]
    sgemm_nt_bias<<<dim3(D3 / 128, NTOK / 128), 256>>>(x, in_w, in_b, qkv, NTOK, D3, D_DIM);

    // windowed attention
    attn_kernel<<<dim3(S_LEN / 32, NH, B_SZ), 256>>>();

    // output projection
    sgemm_nt_bias<<<dim3(D_DIM / 128, NTOK / 128), 256>>>(attn, out_w, out_b, attnout,
                                                          NTOK, D_DIM, D_DIM);

    // x_attn = LN1(x + attn_out)
    add_ln_kernel<<<NTOK, 256>>>(x, attnout, ln1g, ln1b, xattn);

    // out = LN2(x_attn + x_wave)
    add_ln_kernel<<<NTOK, 256>>>(xattn, xwave, ln2g, ln2b, out);
}

// round 5
// speedup vs baseline: 1.5712x; 1.5206x over previous
#include <cuda_runtime.h>
#include <math.h>
#include <stdint.h>

#define S_LEN 2048
#define D_DIM 1024
#define B_SZ  2
#define NH    16
#define DHE   64
#define WIN   128
#define NTOK  (B_SZ * S_LEN)   // 4096
#define D3    (3 * D_DIM)      // 3072

#define SMAP(i) ((i) + ((i) >> 4))

// ---------------- scratch ----------------
__device__ float g_qkv[(size_t)NTOK * D3];
__device__ float g_attn[(size_t)NTOK * D_DIM];
__device__ float g_attnout[(size_t)NTOK * D_DIM];
__device__ float g_xattn[(size_t)NTOK * D_DIM];
__device__ float g_xwave[(size_t)NTOK * D_DIM];

// ---------------- tf32 helpers ----------------
__device__ __forceinline__ uint32_t f2tf(float f) {
    uint32_t u;
    asm("cvt.rna.tf32.f32 %0, %1;" : "=r"(u) : "f"(f));
    return u;
}

__device__ __forceinline__ void mma_tf32(
    float& c0, float& c1, float& c2, float& c3,
    uint32_t a0, uint32_t a1, uint32_t a2, uint32_t a3,
    uint32_t b0, uint32_t b1)
{
    asm volatile(
        "mma.sync.aligned.m16n8k8.row.col.f32.tf32.tf32.f32 "
        "{%0,%1,%2,%3}, {%4,%5,%6,%7}, {%8,%9}, {%0,%1,%2,%3};\n"
        : "+f"(c0), "+f"(c1), "+f"(c2), "+f"(c3)
        : "r"(a0), "r"(a1), "r"(a2), "r"(a3), "r"(b0), "r"(b1));
}

// ---------------- tf32 GEMM: C[M,N] = A[M,K] @ W[N,K]^T + bias ----------------
// BM=128, BN=128, BK=16, 256 threads = 8 warps (2x4), warp tile 64x32.
#define LDK 20
__global__ void __launch_bounds__(256) sgemm_tf32_nt_bias(
    const float* __restrict__ A, const float* __restrict__ W,
    const float* __restrict__ bias, float* __restrict__ C,
    int M, int N, int K)
{
    __shared__ uint32_t As[2][128][LDK];
    __shared__ uint32_t Ws[2][128][LDK];

    const int row0 = blockIdx.y * 128;
    const int col0 = blockIdx.x * 128;
    const int t    = threadIdx.x;
    const int warp = t >> 5;
    const int lane = t & 31;
    const int gr   = lane >> 2;       // 0..7
    const int tc   = lane & 3;        // 0..3
    const int m0w  = (warp >> 2) * 64;
    const int n0w  = (warp & 3) * 32;

    const int r0l = t >> 2;            const int c0l = (t & 3) * 4;
    const int r1l = (t + 256) >> 2;    const int c1l = ((t + 256) & 3) * 4;

    float acc[4][4][4];
#pragma unroll
    for (int mi = 0; mi < 4; mi++)
#pragma unroll
        for (int ni = 0; ni < 4; ni++)
#pragma unroll
            for (int r = 0; r < 4; r++) acc[mi][ni][r] = 0.f;

    float4 pa0, pa1, pw0, pw1;

    // prologue: tile 0
    pa0 = *(const float4*)(A + (size_t)(row0 + r0l) * K + c0l);
    pa1 = *(const float4*)(A + (size_t)(row0 + r1l) * K + c1l);
    pw0 = *(const float4*)(W + (size_t)(col0 + r0l) * K + c0l);
    pw1 = *(const float4*)(W + (size_t)(col0 + r1l) * K + c1l);
    {
        uint4 ua0 = make_uint4(f2tf(pa0.x), f2tf(pa0.y), f2tf(pa0.z), f2tf(pa0.w));
        uint4 ua1 = make_uint4(f2tf(pa1.x), f2tf(pa1.y), f2tf(pa1.z), f2tf(pa1.w));
        uint4 uw0 = make_uint4(f2tf(pw0.x), f2tf(pw0.y), f2tf(pw0.z), f2tf(pw0.w));
        uint4 uw1 = make_uint4(f2tf(pw1.x), f2tf(pw1.y), f2tf(pw1.z), f2tf(pw1.w));
        *(uint4*)&As[0][r0l][c0l] = ua0;
        *(uint4*)&As[0][r1l][c1l] = ua1;
        *(uint4*)&Ws[0][r0l][c0l] = uw0;
        *(uint4*)&Ws[0][r1l][c1l] = uw1;
    }
    __syncthreads();

    const int ntiles = K >> 4;
    for (int kt = 0; kt < ntiles; kt++) {
        const int cb = kt & 1;
        const bool hasnext = (kt + 1 < ntiles);
        if (hasnext) {
            const int k0 = (kt + 1) << 4;
            pa0 = *(const float4*)(A + (size_t)(row0 + r0l) * K + k0 + c0l);
            pa1 = *(const float4*)(A + (size_t)(row0 + r1l) * K + k0 + c1l);
            pw0 = *(const float4*)(W + (size_t)(col0 + r0l) * K + k0 + c0l);
            pw1 = *(const float4*)(W + (size_t)(col0 + r1l) * K + k0 + c1l);
        }

#pragma unroll
        for (int kk = 0; kk < 2; kk++) {
            uint32_t af[4][4];
#pragma unroll
            for (int mi = 0; mi < 4; mi++) {
                const int br = m0w + mi * 16;
                af[mi][0] = As[cb][br + gr][kk * 8 + tc];
                af[mi][1] = As[cb][br + gr + 8][kk * 8 + tc];
                af[mi][2] = As[cb][br + gr][kk * 8 + tc + 4];
                af[mi][3] = As[cb][br + gr + 8][kk * 8 + tc + 4];
            }
            uint32_t bf[4][2];
#pragma unroll
            for (int ni = 0; ni < 4; ni++) {
                const int bn = n0w + ni * 8 + gr;
                bf[ni][0] = Ws[cb][bn][kk * 8 + tc];
                bf[ni][1] = Ws[cb][bn][kk * 8 + tc + 4];
            }
#pragma unroll
            for (int mi = 0; mi < 4; mi++)
#pragma unroll
                for (int ni = 0; ni < 4; ni++)
                    mma_tf32(acc[mi][ni][0], acc[mi][ni][1], acc[mi][ni][2], acc[mi][ni][3],
                             af[mi][0], af[mi][1], af[mi][2], af[mi][3],
                             bf[ni][0], bf[ni][1]);
        }

        if (hasnext) {
            const int nb = cb ^ 1;
            uint4 ua0 = make_uint4(f2tf(pa0.x), f2tf(pa0.y), f2tf(pa0.z), f2tf(pa0.w));
            uint4 ua1 = make_uint4(f2tf(pa1.x), f2tf(pa1.y), f2tf(pa1.z), f2tf(pa1.w));
            uint4 uw0 = make_uint4(f2tf(pw0.x), f2tf(pw0.y), f2tf(pw0.z), f2tf(pw0.w));
            uint4 uw1 = make_uint4(f2tf(pw1.x), f2tf(pw1.y), f2tf(pw1.z), f2tf(pw1.w));
            *(uint4*)&As[nb][r0l][c0l] = ua0;
            *(uint4*)&As[nb][r1l][c1l] = ua1;
            *(uint4*)&Ws[nb][r0l][c0l] = uw0;
            *(uint4*)&Ws[nb][r1l][c1l] = uw1;
        }
        __syncthreads();
    }

    // epilogue
#pragma unroll
    for (int mi = 0; mi < 4; mi++) {
#pragma unroll
        for (int ni = 0; ni < 4; ni++) {
            const int r = row0 + m0w + mi * 16 + gr;
            const int c = col0 + n0w + ni * 8 + tc * 2;
            float2 bs = *(const float2*)(bias + c);
            float2 v0 = make_float2(acc[mi][ni][0] + bs.x, acc[mi][ni][1] + bs.y);
            float2 v1 = make_float2(acc[mi][ni][2] + bs.x, acc[mi][ni][3] + bs.y);
            *(float2*)(C + (size_t)r * N + c)       = v0;
            *(float2*)(C + (size_t)(r + 8) * N + c) = v1;
        }
    }
}

// ---------------- windowed attention (unchanged) ----------------
__global__ void __launch_bounds__(256) attn_kernel()
{
    __shared__ float Qs[32][68];
    __shared__ float Ks[32][68];
    __shared__ float Vs[32][68];
    __shared__ float P[32][36];

    const int q0 = blockIdx.x * 32;
    const int h  = blockIdx.y;
    const int b  = blockIdx.z;
    const int t  = threadIdx.x;

    {
        int r = t >> 3, off = (t & 7) * 8;
        const float* src = g_qkv + (size_t)(b * S_LEN + q0 + r) * D3 + h * DHE + off;
        float4 v0 = *(const float4*)src;
        float4 v1 = *(const float4*)(src + 4);
        const float sc = 0.125f;
        v0.x *= sc; v0.y *= sc; v0.z *= sc; v0.w *= sc;
        v1.x *= sc; v1.y *= sc; v1.z *= sc; v1.w *= sc;
        *(float4*)&Qs[r][off]     = v0;
        *(float4*)&Qs[r][off + 4] = v1;
    }

    const int qi  = t >> 3;
    const int sub = t & 7;
    const int qg  = q0 + qi;

    float m = -INFINITY, l = 0.f;
    float4 o0 = make_float4(0.f, 0.f, 0.f, 0.f);
    float4 o1 = make_float4(0.f, 0.f, 0.f, 0.f);

    const int kstart = (q0 - WIN) > 0 ? (q0 - WIN) : 0;
    const int kend   = (q0 + 32 + WIN) < S_LEN ? (q0 + 32 + WIN) : S_LEN;

    for (int kc = kstart; kc < kend; kc += 32) {
        __syncthreads();
        {
            int r = t >> 3, off = (t & 7) * 8;
            const float* kp = g_qkv + (size_t)(b * S_LEN + kc + r) * D3 + D_DIM + h * DHE + off;
            const float* vp = kp + D_DIM;
            *(float4*)&Ks[r][off]     = *(const float4*)kp;
            *(float4*)&Ks[r][off + 4] = *(const float4*)(kp + 4);
            *(float4*)&Vs[r][off]     = *(const float4*)vp;
            *(float4*)&Vs[r][off + 4] = *(const float4*)(vp + 4);
        }
        __syncthreads();

        float s[4];
#pragma unroll
        for (int j = 0; j < 4; j++) s[j] = 0.f;
#pragma unroll
        for (int d4 = 0; d4 < 16; d4++) {
            float4 qv = *(const float4*)&Qs[qi][d4 * 4];
#pragma unroll
            for (int j = 0; j < 4; j++) {
                float4 kv = *(const float4*)&Ks[sub * 4 + j][d4 * 4];
                s[j] += qv.x * kv.x + qv.y * kv.y + qv.z * kv.z + qv.w * kv.w;
            }
        }

        float mloc = -INFINITY;
#pragma unroll
        for (int j = 0; j < 4; j++) {
            int kg = kc + sub * 4 + j;
            if (kg < qg - WIN || kg > qg + WIN) s[j] = -INFINITY;
            mloc = fmaxf(mloc, s[j]);
        }
#pragma unroll
        for (int o = 1; o < 8; o <<= 1)
            mloc = fmaxf(mloc, __shfl_xor_sync(0xffffffffu, mloc, o, 8));

        float mnew  = fmaxf(m, mloc);
        float alpha = (mnew == -INFINITY) ? 1.f : __expf(m - mnew);
        float ps = 0.f;
#pragma unroll
        for (int j = 0; j < 4; j++) {
            float p = (s[j] == -INFINITY) ? 0.f : __expf(s[j] - mnew);
            P[qi][sub * 4 + j] = p;
            ps += p;
        }
#pragma unroll
        for (int o = 1; o < 8; o <<= 1)
            ps += __shfl_xor_sync(0xffffffffu, ps, o, 8);

        l = l * alpha + ps;
        m = mnew;
        o0.x *= alpha; o0.y *= alpha; o0.z *= alpha; o0.w *= alpha;
        o1.x *= alpha; o1.y *= alpha; o1.z *= alpha; o1.w *= alpha;

        __syncthreads();
#pragma unroll
        for (int kk = 0; kk < 32; kk++) {
            float p = P[qi][kk];
            float4 v0 = *(const float4*)&Vs[kk][sub * 8];
            float4 v1 = *(const float4*)&Vs[kk][sub * 8 + 4];
            o0.x += p * v0.x; o0.y += p * v0.y; o0.z += p * v0.z; o0.w += p * v0.w;
            o1.x += p * v1.x; o1.y += p * v1.y; o1.z += p * v1.z; o1.w += p * v1.w;
        }
    }

    const float inv = 1.0f / l;
    float* dst = g_attn + (size_t)(b * S_LEN + qg) * D_DIM + h * DHE + sub * 8;
    o0.x *= inv; o0.y *= inv; o0.z *= inv; o0.w *= inv;
    o1.x *= inv; o1.y *= inv; o1.z *= inv; o1.w *= inv;
    *(float4*)dst       = o0;
    *(float4*)(dst + 4) = o1;
}

// ---------------- fused add + LayerNorm (float4) ----------------
__global__ void __launch_bounds__(256) add_ln_kernel(
    const float* __restrict__ A, const float* __restrict__ Bv,
    const float* __restrict__ g, const float* __restrict__ beta,
    float* __restrict__ out)
{
    __shared__ float red[8];
    const int row = blockIdx.x;
    const int t   = threadIdx.x;

    float4 a = *(const float4*)(A  + (size_t)row * D_DIM + t * 4);
    float4 b = *(const float4*)(Bv + (size_t)row * D_DIM + t * 4);
    float4 v = make_float4(a.x + b.x, a.y + b.y, a.z + b.z, a.w + b.w);

    float s = v.x + v.y + v.z + v.w;
#pragma unroll
    for (int o = 16; o; o >>= 1) s += __shfl_xor_sync(0xffffffffu, s, o);
    if ((t & 31) == 0) red[t >> 5] = s;
    __syncthreads();
    float tot = 0.f;
#pragma unroll
    for (int i = 0; i < 8; i++) tot += red[i];
    const float mu = tot * (1.f / (float)D_DIM);
    __syncthreads();

    float dx = v.x - mu, dy = v.y - mu, dz = v.z - mu, dw = v.w - mu;
    float s2 = dx * dx + dy * dy + dz * dz + dw * dw;
#pragma unroll
    for (int o = 16; o; o >>= 1) s2 += __shfl_xor_sync(0xffffffffu, s2, o);
    if ((t & 31) == 0) red[t >> 5] = s2;
    __syncthreads();
    float tot2 = 0.f;
#pragma unroll
    for (int i = 0; i < 8; i++) tot2 += red[i];
    const float inv = rsqrtf(tot2 * (1.f / (float)D_DIM) + 1e-5f);

    float4 gg = *(const float4*)(g    + t * 4);
    float4 bb = *(const float4*)(beta + t * 4);
    float4 o4 = make_float4(dx * inv * gg.x + bb.x, dy * inv * gg.y + bb.y,
                            dz * inv * gg.z + bb.z, dw * inv * gg.w + bb.w);
    *(float4*)(out + (size_t)row * D_DIM + t * 4) = o4;
}

// ---------------- spectral block ----------------
__device__ __forceinline__ float2 cmul(float2 a, float2 b) {
    return make_float2(a.x * b.x - a.y * b.y, a.x * b.y + a.y * b.x);
}

template<int SIGN>
__device__ __forceinline__ void fft2048_r4(float2*& cur, float2*& oth)
{
    int n = 2048, ls = 0;
#pragma unroll
    for (int st = 0; st < 5; st++) {
        const int ss = 1 << ls;
        const float fn = (2.0f * (float)SIGN) / (float)n;
#pragma unroll
        for (int ii = 0; ii < 2; ii++) {
            const int idx = threadIdx.x + 256 * ii;
            const int p = idx >> ls;
            const int q = idx & (ss - 1);
            float2 x0 = cur[SMAP(idx)];
            float2 x1 = cur[SMAP(idx + 512)];
            float2 x2 = cur[SMAP(idx + 1024)];
            float2 x3 = cur[SMAP(idx + 1536)];
            float sn, cs;
            sincospif(fn * (float)p, &sn, &cs);
            const float2 wA = make_float2(cs, sn);
            const float2 wB = cmul(wA, wA);
            float2 a0 = make_float2(x0.x + x2.x, x0.y + x2.y);
            float2 a1 = make_float2(x0.x - x2.x, x0.y - x2.y);
            float2 b0 = make_float2(x1.x + x3.x, x1.y + x3.y);
            float2 u  = make_float2(x1.x - x3.x, x1.y - x3.y);
            float2 b1 = make_float2(-(float)SIGN * u.y, (float)SIGN * u.x);
            float2 A1p = cmul(a1, wA);
            float2 A1q = cmul(b1, wA);
            const int ob = q + 4 * ss * p;
            oth[SMAP(ob)]          = make_float2(a0.x + b0.x, a0.y + b0.y);
            float2 d0v = make_float2(a0.x - b0.x, a0.y - b0.y);
            oth[SMAP(ob + 2 * ss)] = cmul(d0v, wB);
            oth[SMAP(ob + ss)]     = make_float2(A1p.x + A1q.x, A1p.y + A1q.y);
            float2 d1v = make_float2(A1p.x - A1q.x, A1p.y - A1q.y);
            oth[SMAP(ob + 3 * ss)] = cmul(d1v, wB);
        }
        __syncthreads();
        float2* t = cur; cur = oth; oth = t;
        n >>= 2; ls += 2;
    }
#pragma unroll
    for (int ii = 0; ii < 4; ii++) {
        const int q = threadIdx.x + 256 * ii;
        float2 a = cur[SMAP(q)];
        float2 b = cur[SMAP(q + 1024)];
        oth[SMAP(q)]        = make_float2(a.x + b.x, a.y + b.y);
        oth[SMAP(q + 1024)] = make_float2(a.x - b.x, a.y - b.y);
    }
    __syncthreads();
    { float2* t = cur; cur = oth; oth = t; }
}

__global__ void __launch_bounds__(256) spectral_kernel(
    const float* __restrict__ x, const float* __restrict__ wr,
    const float* __restrict__ wi, float* __restrict__ xwave)
{
    __shared__ float2 bufA[2176];
    __shared__ float2 bufB[2176];
    const int d0 = blockIdx.x * 2;
    const int b  = blockIdx.y;

    const float* xp = x + (size_t)b * S_LEN * D_DIM + d0;
    for (int s = threadIdx.x; s < 2048; s += 256)
        bufA[SMAP(s)] = *(const float2*)(xp + (size_t)s * D_DIM);
    __syncthreads();

    float2* cur = bufA;
    float2* oth = bufB;
    fft2048_r4<-1>(cur, oth);

    for (int k = threadIdx.x; k < 2048; k += 256) {
        const int km = (2048 - k) & 2047;
        float2 Zk = cur[SMAP(k)];
        float2 Zm = cur[SMAP(km)];
        float2 Av = make_float2(0.5f * (Zk.x + Zm.x), 0.5f * (Zk.y - Zm.y));
        float2 Bc = make_float2(0.5f * (Zk.y + Zm.y), -0.5f * (Zk.x - Zm.x));
        const int   kf  = (k <= 1024) ? k : 2048 - k;
        const float sgn = (k <= 1024) ? 1.f : -1.f;
        float2 wrp = *(const float2*)(wr + (size_t)kf * D_DIM + d0);
        float2 wip = *(const float2*)(wi + (size_t)kf * D_DIM + d0);
        float2 c1 = make_float2(wrp.x, sgn * wip.x);
        float2 c2 = make_float2(wrp.y, sgn * wip.y);
        // irfft drops the imaginary part of bins 0 and N/2: effective filter
        // there is Re(Wc). Keeps Y1/Y2 Hermitian so the pair-unpack is exact.
        if (k == 0 || k == 1024) { c1.y = 0.f; c2.y = 0.f; }
        float2 Y1 = cmul(Av, c1);
        float2 Y2 = cmul(Bc, c2);
        oth[SMAP(k)] = make_float2(Y1.x - Y2.y, Y1.y + Y2.x);
    }
    __syncthreads();
    { float2* t = cur; cur = oth; oth = t; }

    fft2048_r4<1>(cur, oth);

    float* dst = xwave + (size_t)b * S_LEN * D_DIM + d0;
    const float invn = 1.0f / 2048.0f;
    for (int s = threadIdx.x; s < 2048; s += 256) {
        float2 r = cur[SMAP(s)];
        *(float2*)(dst + (size_t)s * D_DIM) = make_float2(r.x * invn, r.y * invn);
    }
}

// ---------------- launcher ----------------
extern "C" void kernel_launch(void* const* d_in, const int* in_sizes, int n_in,
                              void* d_out, int out_size)
{
    const float* x     = (const float*)d_in[0];
    const float* in_w  = (const float*)d_in[1];
    const float* in_b  = (const float*)d_in[2];
    const float* out_w = (const float*)d_in[3];
    const float* out_b = (const float*)d_in[4];
    const float* ln1g  = (const float*)d_in[5];
    const float* ln1b  = (const float*)d_in[6];
    const float* wr    = (const float*)d_in[7];
    const float* wi    = (const float*)d_in[8];
    const float* ln2g  = (const float*)d_in[9];
    const float* ln2b  = (const float*)d_in[10];
    float* out = (float*)d_out;

    float *qkv, *attn, *attnout, *xattn, *xwave;
    cudaGetSymbolAddress((void**)&qkv,     g_qkv);
    cudaGetSymbolAddress((void**)&attn,    g_attn);
    cudaGetSymbolAddress((void**)&attnout, g_attnout);
    cudaGetSymbolAddress((void**)&xattn,   g_xattn);
    cudaGetSymbolAddress((void**)&xwave,   g_xwave);

    // spectral path (independent)
    spectral_kernel<<<dim3(D_DIM / 2, B_SZ), 256>>>(x, wr, wi, xwave);

    // QKV projection: [4096,3072] (tf32 tensor cores)
    sgemm_tf32_nt_bias<<<dim3(D3 / 128, NTOK / 128), 256>>>(x, in_w, in_b, qkv,
                                                            NTOK, D3, D_DIM);

    // windowed attention
    attn_kernel<<<dim3(S_LEN / 32, NH, B_SZ), 256>>>();

    // output projection (tf32 tensor cores)
    sgemm_tf32_nt_bias<<<dim3(D_DIM / 128, NTOK / 128), 256>>>(attn, out_w, out_b, attnout,
                                                               NTOK, D_DIM, D_DIM);

    // x_attn = LN1(x + attn_out)
    add_ln_kernel<<<NTOK, 256>>>(x, attnout, ln1g, ln1b, xattn);

    // out = LN2(x_attn + x_wave)
    add_ln_kernel<<<NTOK, 256>>>(xattn, xwave, ln2g, ln2b, out);
}

// round 6
// speedup vs baseline: 4.0393x; 2.5708x over previous
#include <cuda_runtime.h>
#include <math.h>
#include <stdint.h>

#define S_LEN 2048
#define D_DIM 1024
#define B_SZ  2
#define NH    16
#define DHE   64
#define WIN   128
#define NTOK  (B_SZ * S_LEN)   // 4096
#define D3    (3 * D_DIM)      // 3072

#define SMAP(i) ((i) + ((i) >> 4))

// ---------------- scratch ----------------
__device__ float g_qkv[(size_t)NTOK * D3];
__device__ float g_attn[(size_t)NTOK * D_DIM];
__device__ float g_attnout[(size_t)NTOK * D_DIM];
__device__ float g_xattn[(size_t)NTOK * D_DIM];
__device__ float g_xwave[(size_t)NTOK * D_DIM];

// ---------------- tf32 helpers ----------------
__device__ __forceinline__ uint32_t f2tf(float f) {
    uint32_t u;
    asm("cvt.rna.tf32.f32 %0, %1;" : "=r"(u) : "f"(f));
    return u;
}

__device__ __forceinline__ void mma_tf32(
    float& c0, float& c1, float& c2, float& c3,
    uint32_t a0, uint32_t a1, uint32_t a2, uint32_t a3,
    uint32_t b0, uint32_t b1)
{
    asm volatile(
        "mma.sync.aligned.m16n8k8.row.col.f32.tf32.tf32.f32 "
        "{%0,%1,%2,%3}, {%4,%5,%6,%7}, {%8,%9}, {%0,%1,%2,%3};\n"
        : "+f"(c0), "+f"(c1), "+f"(c2), "+f"(c3)
        : "r"(a0), "r"(a1), "r"(a2), "r"(a3), "r"(b0), "r"(b1));
}

// ---------------- tf32 GEMM: C[M,N] = A[M,K] @ W[N,K]^T + bias ----------------
#define LDK 20
__global__ void __launch_bounds__(256) sgemm_tf32_nt_bias(
    const float* __restrict__ A, const float* __restrict__ W,
    const float* __restrict__ bias, float* __restrict__ C,
    int M, int N, int K)
{
    __shared__ uint32_t As[2][128][LDK];
    __shared__ uint32_t Ws[2][128][LDK];

    const int row0 = blockIdx.y * 128;
    const int col0 = blockIdx.x * 128;
    const int t    = threadIdx.x;
    const int warp = t >> 5;
    const int lane = t & 31;
    const int gr   = lane >> 2;
    const int tc   = lane & 3;
    const int m0w  = (warp >> 2) * 64;
    const int n0w  = (warp & 3) * 32;

    const int r0l = t >> 2;            const int c0l = (t & 3) * 4;
    const int r1l = (t + 256) >> 2;    const int c1l = ((t + 256) & 3) * 4;

    float acc[4][4][4];
#pragma unroll
    for (int mi = 0; mi < 4; mi++)
#pragma unroll
        for (int ni = 0; ni < 4; ni++)
#pragma unroll
            for (int r = 0; r < 4; r++) acc[mi][ni][r] = 0.f;

    float4 pa0, pa1, pw0, pw1;

    pa0 = *(const float4*)(A + (size_t)(row0 + r0l) * K + c0l);
    pa1 = *(const float4*)(A + (size_t)(row0 + r1l) * K + c1l);
    pw0 = *(const float4*)(W + (size_t)(col0 + r0l) * K + c0l);
    pw1 = *(const float4*)(W + (size_t)(col0 + r1l) * K + c1l);
    {
        uint4 ua0 = make_uint4(f2tf(pa0.x), f2tf(pa0.y), f2tf(pa0.z), f2tf(pa0.w));
        uint4 ua1 = make_uint4(f2tf(pa1.x), f2tf(pa1.y), f2tf(pa1.z), f2tf(pa1.w));
        uint4 uw0 = make_uint4(f2tf(pw0.x), f2tf(pw0.y), f2tf(pw0.z), f2tf(pw0.w));
        uint4 uw1 = make_uint4(f2tf(pw1.x), f2tf(pw1.y), f2tf(pw1.z), f2tf(pw1.w));
        *(uint4*)&As[0][r0l][c0l] = ua0;
        *(uint4*)&As[0][r1l][c1l] = ua1;
        *(uint4*)&Ws[0][r0l][c0l] = uw0;
        *(uint4*)&Ws[0][r1l][c1l] = uw1;
    }
    __syncthreads();

    const int ntiles = K >> 4;
    for (int kt = 0; kt < ntiles; kt++) {
        const int cb = kt & 1;
        const bool hasnext = (kt + 1 < ntiles);
        if (hasnext) {
            const int k0 = (kt + 1) << 4;
            pa0 = *(const float4*)(A + (size_t)(row0 + r0l) * K + k0 + c0l);
            pa1 = *(const float4*)(A + (size_t)(row0 + r1l) * K + k0 + c1l);
            pw0 = *(const float4*)(W + (size_t)(col0 + r0l) * K + k0 + c0l);
            pw1 = *(const float4*)(W + (size_t)(col0 + r1l) * K + k0 + c1l);
        }

#pragma unroll
        for (int kk = 0; kk < 2; kk++) {
            uint32_t af[4][4];
#pragma unroll
            for (int mi = 0; mi < 4; mi++) {
                const int br = m0w + mi * 16;
                af[mi][0] = As[cb][br + gr][kk * 8 + tc];
                af[mi][1] = As[cb][br + gr + 8][kk * 8 + tc];
                af[mi][2] = As[cb][br + gr][kk * 8 + tc + 4];
                af[mi][3] = As[cb][br + gr + 8][kk * 8 + tc + 4];
            }
            uint32_t bf[4][2];
#pragma unroll
            for (int ni = 0; ni < 4; ni++) {
                const int bn = n0w + ni * 8 + gr;
                bf[ni][0] = Ws[cb][bn][kk * 8 + tc];
                bf[ni][1] = Ws[cb][bn][kk * 8 + tc + 4];
            }
#pragma unroll
            for (int mi = 0; mi < 4; mi++)
#pragma unroll
                for (int ni = 0; ni < 4; ni++)
                    mma_tf32(acc[mi][ni][0], acc[mi][ni][1], acc[mi][ni][2], acc[mi][ni][3],
                             af[mi][0], af[mi][1], af[mi][2], af[mi][3],
                             bf[ni][0], bf[ni][1]);
        }

        if (hasnext) {
            const int nb = cb ^ 1;
            uint4 ua0 = make_uint4(f2tf(pa0.x), f2tf(pa0.y), f2tf(pa0.z), f2tf(pa0.w));
            uint4 ua1 = make_uint4(f2tf(pa1.x), f2tf(pa1.y), f2tf(pa1.z), f2tf(pa1.w));
            uint4 uw0 = make_uint4(f2tf(pw0.x), f2tf(pw0.y), f2tf(pw0.z), f2tf(pw0.w));
            uint4 uw1 = make_uint4(f2tf(pw1.x), f2tf(pw1.y), f2tf(pw1.z), f2tf(pw1.w));
            *(uint4*)&As[nb][r0l][c0l] = ua0;
            *(uint4*)&As[nb][r1l][c1l] = ua1;
            *(uint4*)&Ws[nb][r0l][c0l] = uw0;
            *(uint4*)&Ws[nb][r1l][c1l] = uw1;
        }
        __syncthreads();
    }

#pragma unroll
    for (int mi = 0; mi < 4; mi++) {
#pragma unroll
        for (int ni = 0; ni < 4; ni++) {
            const int r = row0 + m0w + mi * 16 + gr;
            const int c = col0 + n0w + ni * 8 + tc * 2;
            float2 bs = *(const float2*)(bias + c);
            float2 v0 = make_float2(acc[mi][ni][0] + bs.x, acc[mi][ni][1] + bs.y);
            float2 v1 = make_float2(acc[mi][ni][2] + bs.x, acc[mi][ni][3] + bs.y);
            *(float2*)(C + (size_t)r * N + c)       = v0;
            *(float2*)(C + (size_t)(r + 8) * N + c) = v1;
        }
    }
}

// ---------------- tensor-core windowed flash attention ----------------
// CTA = 128 threads (4 warps), 64-query tile, one (b,h). 64-key chunks.
// Warp w owns query rows [w*16, w*16+16).
#define QPAD 68
#define VPAD 72
__global__ void __launch_bounds__(128) attn_tc_kernel()
{
    __shared__ uint32_t Qs[64][QPAD];
    __shared__ uint32_t Ks[64][QPAD];
    __shared__ uint32_t Vs[64][VPAD];
    __shared__ uint32_t Ps[64][QPAD];

    const int q0  = blockIdx.x * 64;
    const int h   = blockIdx.y;
    const int b   = blockIdx.z;
    const int t   = threadIdx.x;
    const int wid = t >> 5;
    const int lane = t & 31;
    const int gr  = lane >> 2;     // 0..7
    const int tc  = lane & 3;      // 0..3

    // load Q tile (scaled by 1/sqrt(DH)=0.125), convert to tf32
#pragma unroll
    for (int i = 0; i < 8; i++) {
        int lin = t + 128 * i;             // 0..1023 float4 slots
        int row = lin >> 4;
        int c4  = (lin & 15) * 4;
        const float* src = g_qkv + (size_t)(b * S_LEN + q0 + row) * D3 + h * DHE + c4;
        float4 v = *(const float4*)src;
        *(uint4*)&Qs[row][c4] = make_uint4(f2tf(v.x * 0.125f), f2tf(v.y * 0.125f),
                                           f2tf(v.z * 0.125f), f2tf(v.w * 0.125f));
    }

    const int qr0 = q0 + wid * 16 + gr;    // this thread's query rows
    const int qr1 = qr0 + 8;

    float m0 = -1e30f, m1 = -1e30f, l0 = 0.f, l1 = 0.f;
    float oacc[8][4];
#pragma unroll
    for (int nt = 0; nt < 8; nt++)
#pragma unroll
        for (int r = 0; r < 4; r++) oacc[nt][r] = 0.f;

    const int kstart = (q0 - WIN > 0) ? (q0 - WIN) : 0;
    const int kend   = (q0 + 64 + WIN < S_LEN) ? (q0 + 64 + WIN) : S_LEN;

    for (int kc = kstart; kc < kend; kc += 64) {
        __syncthreads();
        // load K/V chunk (tf32)
#pragma unroll
        for (int i = 0; i < 8; i++) {
            int lin = t + 128 * i;
            int row = lin >> 4;
            int c4  = (lin & 15) * 4;
            const float* kp = g_qkv + (size_t)(b * S_LEN + kc + row) * D3 + D_DIM + h * DHE + c4;
            float4 kv = *(const float4*)kp;
            float4 vv = *(const float4*)(kp + D_DIM);
            *(uint4*)&Ks[row][c4] = make_uint4(f2tf(kv.x), f2tf(kv.y), f2tf(kv.z), f2tf(kv.w));
            *(uint4*)&Vs[row][c4] = make_uint4(f2tf(vv.x), f2tf(vv.y), f2tf(vv.z), f2tf(vv.w));
        }
        __syncthreads();

        // S = Q @ K^T  (16x64 per warp)
        float sacc[8][4];
#pragma unroll
        for (int nt = 0; nt < 8; nt++)
#pragma unroll
            for (int r = 0; r < 4; r++) sacc[nt][r] = 0.f;

#pragma unroll
        for (int ks = 0; ks < 8; ks++) {
            const int qrow = wid * 16 + gr;
            uint32_t af0 = Qs[qrow][ks * 8 + tc];
            uint32_t af1 = Qs[qrow + 8][ks * 8 + tc];
            uint32_t af2 = Qs[qrow][ks * 8 + tc + 4];
            uint32_t af3 = Qs[qrow + 8][ks * 8 + tc + 4];
#pragma unroll
            for (int nt = 0; nt < 8; nt++) {
                uint32_t b0 = Ks[nt * 8 + gr][ks * 8 + tc];
                uint32_t b1 = Ks[nt * 8 + gr][ks * 8 + tc + 4];
                mma_tf32(sacc[nt][0], sacc[nt][1], sacc[nt][2], sacc[nt][3],
                         af0, af1, af2, af3, b0, b1);
            }
        }

        // band mask + running row max
        float mx0 = m0, mx1 = m1;
#pragma unroll
        for (int nt = 0; nt < 8; nt++) {
            const int c = kc + nt * 8 + 2 * tc;
            if (c     < qr0 - WIN || c     > qr0 + WIN) sacc[nt][0] = -1e30f;
            if (c + 1 < qr0 - WIN || c + 1 > qr0 + WIN) sacc[nt][1] = -1e30f;
            if (c     < qr1 - WIN || c     > qr1 + WIN) sacc[nt][2] = -1e30f;
            if (c + 1 < qr1 - WIN || c + 1 > qr1 + WIN) sacc[nt][3] = -1e30f;
            mx0 = fmaxf(mx0, fmaxf(sacc[nt][0], sacc[nt][1]));
            mx1 = fmaxf(mx1, fmaxf(sacc[nt][2], sacc[nt][3]));
        }
        mx0 = fmaxf(mx0, __shfl_xor_sync(0xffffffffu, mx0, 1));
        mx0 = fmaxf(mx0, __shfl_xor_sync(0xffffffffu, mx0, 2));
        mx1 = fmaxf(mx1, __shfl_xor_sync(0xffffffffu, mx1, 1));
        mx1 = fmaxf(mx1, __shfl_xor_sync(0xffffffffu, mx1, 2));

        const float alpha0 = __expf(m0 - mx0);   // m0=-1e30 first time -> 0
        const float alpha1 = __expf(m1 - mx1);

        // p = exp(s - mx), store tf32 P, accumulate row sums
        float ps0 = 0.f, ps1 = 0.f;
        const int prow = wid * 16 + gr;
#pragma unroll
        for (int nt = 0; nt < 8; nt++) {
            float p00 = __expf(sacc[nt][0] - mx0);
            float p01 = __expf(sacc[nt][1] - mx0);
            float p10 = __expf(sacc[nt][2] - mx1);
            float p11 = __expf(sacc[nt][3] - mx1);
            ps0 += p00 + p01;
            ps1 += p10 + p11;
            *(uint2*)&Ps[prow][nt * 8 + 2 * tc]     = make_uint2(f2tf(p00), f2tf(p01));
            *(uint2*)&Ps[prow + 8][nt * 8 + 2 * tc] = make_uint2(f2tf(p10), f2tf(p11));
        }
        ps0 += __shfl_xor_sync(0xffffffffu, ps0, 1);
        ps0 += __shfl_xor_sync(0xffffffffu, ps0, 2);
        ps1 += __shfl_xor_sync(0xffffffffu, ps1, 1);
        ps1 += __shfl_xor_sync(0xffffffffu, ps1, 2);

        l0 = l0 * alpha0 + ps0;  m0 = mx0;
        l1 = l1 * alpha1 + ps1;  m1 = mx1;

        // rescale O accum
#pragma unroll
        for (int nt = 0; nt < 8; nt++) {
            oacc[nt][0] *= alpha0; oacc[nt][1] *= alpha0;
            oacc[nt][2] *= alpha1; oacc[nt][3] *= alpha1;
        }

        __syncwarp();   // Ps rows are warp-private: warp-level sync suffices

        // O += P @ V  (16x64 per warp)
#pragma unroll
        for (int ks = 0; ks < 8; ks++) {
            uint32_t af0 = Ps[prow][ks * 8 + tc];
            uint32_t af1 = Ps[prow + 8][ks * 8 + tc];
            uint32_t af2 = Ps[prow][ks * 8 + tc + 4];
            uint32_t af3 = Ps[prow + 8][ks * 8 + tc + 4];
#pragma unroll
            for (int nt = 0; nt < 8; nt++) {
                uint32_t b0 = Vs[ks * 8 + tc][nt * 8 + gr];
                uint32_t b1 = Vs[ks * 8 + tc + 4][nt * 8 + gr];
                mma_tf32(oacc[nt][0], oacc[nt][1], oacc[nt][2], oacc[nt][3],
                         af0, af1, af2, af3, b0, b1);
            }
        }
    }

    // epilogue: divide by l, write to g_attn
    const float inv0 = 1.0f / l0;
    const float inv1 = 1.0f / l1;
    const size_t row0g = (size_t)(b * S_LEN) + qr0;
#pragma unroll
    for (int nt = 0; nt < 8; nt++) {
        const int col = h * DHE + nt * 8 + 2 * tc;
        *(float2*)(g_attn + row0g * D_DIM + col) =
            make_float2(oacc[nt][0] * inv0, oacc[nt][1] * inv0);
        *(float2*)(g_attn + (row0g + 8) * D_DIM + col) =
            make_float2(oacc[nt][2] * inv1, oacc[nt][3] * inv1);
    }
}

// ---------------- fused add + LayerNorm (float4) ----------------
__global__ void __launch_bounds__(256) add_ln_kernel(
    const float* __restrict__ A, const float* __restrict__ Bv,
    const float* __restrict__ g, const float* __restrict__ beta,
    float* __restrict__ out)
{
    __shared__ float red[8];
    const int row = blockIdx.x;
    const int t   = threadIdx.x;

    float4 a = *(const float4*)(A  + (size_t)row * D_DIM + t * 4);
    float4 b = *(const float4*)(Bv + (size_t)row * D_DIM + t * 4);
    float4 v = make_float4(a.x + b.x, a.y + b.y, a.z + b.z, a.w + b.w);

    float s = v.x + v.y + v.z + v.w;
#pragma unroll
    for (int o = 16; o; o >>= 1) s += __shfl_xor_sync(0xffffffffu, s, o);
    if ((t & 31) == 0) red[t >> 5] = s;
    __syncthreads();
    float tot = 0.f;
#pragma unroll
    for (int i = 0; i < 8; i++) tot += red[i];
    const float mu = tot * (1.f / (float)D_DIM);
    __syncthreads();

    float dx = v.x - mu, dy = v.y - mu, dz = v.z - mu, dw = v.w - mu;
    float s2 = dx * dx + dy * dy + dz * dz + dw * dw;
#pragma unroll
    for (int o = 16; o; o >>= 1) s2 += __shfl_xor_sync(0xffffffffu, s2, o);
    if ((t & 31) == 0) red[t >> 5] = s2;
    __syncthreads();
    float tot2 = 0.f;
#pragma unroll
    for (int i = 0; i < 8; i++) tot2 += red[i];
    const float inv = rsqrtf(tot2 * (1.f / (float)D_DIM) + 1e-5f);

    float4 gg = *(const float4*)(g    + t * 4);
    float4 bb = *(const float4*)(beta + t * 4);
    float4 o4 = make_float4(dx * inv * gg.x + bb.x, dy * inv * gg.y + bb.y,
                            dz * inv * gg.z + bb.z, dw * inv * gg.w + bb.w);
    *(float4*)(out + (size_t)row * D_DIM + t * 4) = o4;
}

// ---------------- spectral block ----------------
__device__ __forceinline__ float2 cmul(float2 a, float2 b) {
    return make_float2(a.x * b.x - a.y * b.y, a.x * b.y + a.y * b.x);
}

template<int SIGN>
__device__ __forceinline__ void fft2048_r4(float2*& cur, float2*& oth)
{
    int n = 2048, ls = 0;
#pragma unroll
    for (int st = 0; st < 5; st++) {
        const int ss = 1 << ls;
        const float fn = (2.0f * 3.14159265358979f * (float)SIGN) / (float)n;
#pragma unroll
        for (int ii = 0; ii < 2; ii++) {
            const int idx = threadIdx.x + 256 * ii;
            const int p = idx >> ls;
            const int q = idx & (ss - 1);
            float2 x0 = cur[SMAP(idx)];
            float2 x1 = cur[SMAP(idx + 512)];
            float2 x2 = cur[SMAP(idx + 1024)];
            float2 x3 = cur[SMAP(idx + 1536)];
            float sn, cs;
            __sincosf(fn * (float)p, &sn, &cs);
            const float2 wA = make_float2(cs, sn);
            const float2 wB = cmul(wA, wA);
            float2 a0 = make_float2(x0.x + x2.x, x0.y + x2.y);
            float2 a1 = make_float2(x0.x - x2.x, x0.y - x2.y);
            float2 b0 = make_float2(x1.x + x3.x, x1.y + x3.y);
            float2 u  = make_float2(x1.x - x3.x, x1.y - x3.y);
            float2 b1 = make_float2(-(float)SIGN * u.y, (float)SIGN * u.x);
            float2 A1p = cmul(a1, wA);
            float2 A1q = cmul(b1, wA);
            const int ob = q + 4 * ss * p;
            oth[SMAP(ob)]          = make_float2(a0.x + b0.x, a0.y + b0.y);
            float2 d0v = make_float2(a0.x - b0.x, a0.y - b0.y);
            oth[SMAP(ob + 2 * ss)] = cmul(d0v, wB);
            oth[SMAP(ob + ss)]     = make_float2(A1p.x + A1q.x, A1p.y + A1q.y);
            float2 d1v = make_float2(A1p.x - A1q.x, A1p.y - A1q.y);
            oth[SMAP(ob + 3 * ss)] = cmul(d1v, wB);
        }
        __syncthreads();
        float2* t = cur; cur = oth; oth = t;
        n >>= 2; ls += 2;
    }
#pragma unroll
    for (int ii = 0; ii < 4; ii++) {
        const int q = threadIdx.x + 256 * ii;
        float2 a = cur[SMAP(q)];
        float2 b = cur[SMAP(q + 1024)];
        oth[SMAP(q)]        = make_float2(a.x + b.x, a.y + b.y);
        oth[SMAP(q + 1024)] = make_float2(a.x - b.x, a.y - b.y);
    }
    __syncthreads();
    { float2* t = cur; cur = oth; oth = t; }
}

__global__ void __launch_bounds__(256) spectral_kernel(
    const float* __restrict__ x, const float* __restrict__ wr,
    const float* __restrict__ wi, float* __restrict__ xwave)
{
    __shared__ float2 bufA[2176];
    __shared__ float2 bufB[2176];
    const int d0 = blockIdx.x * 2;
    const int b  = blockIdx.y;

    const float* xp = x + (size_t)b * S_LEN * D_DIM + d0;
    for (int s = threadIdx.x; s < 2048; s += 256)
        bufA[SMAP(s)] = *(const float2*)(xp + (size_t)s * D_DIM);
    __syncthreads();

    float2* cur = bufA;
    float2* oth = bufB;
    fft2048_r4<-1>(cur, oth);

    for (int k = threadIdx.x; k < 2048; k += 256) {
        const int km = (2048 - k) & 2047;
        float2 Zk = cur[SMAP(k)];
        float2 Zm = cur[SMAP(km)];
        float2 Av = make_float2(0.5f * (Zk.x + Zm.x), 0.5f * (Zk.y - Zm.y));
        float2 Bc = make_float2(0.5f * (Zk.y + Zm.y), -0.5f * (Zk.x - Zm.x));
        const int   kf  = (k <= 1024) ? k : 2048 - k;
        const float sgn = (k <= 1024) ? 1.f : -1.f;
        float2 wrp = *(const float2*)(wr + (size_t)kf * D_DIM + d0);
        float2 wip = *(const float2*)(wi + (size_t)kf * D_DIM + d0);
        float2 c1 = make_float2(wrp.x, sgn * wip.x);
        float2 c2 = make_float2(wrp.y, sgn * wip.y);
        // irfft drops Im at bins 0 and N/2 -> effective filter there is Re(Wc)
        if (k == 0 || k == 1024) { c1.y = 0.f; c2.y = 0.f; }
        float2 Y1 = cmul(Av, c1);
        float2 Y2 = cmul(Bc, c2);
        oth[SMAP(k)] = make_float2(Y1.x - Y2.y, Y1.y + Y2.x);
    }
    __syncthreads();
    { float2* t = cur; cur = oth; oth = t; }

    fft2048_r4<1>(cur, oth);

    float* dst = xwave + (size_t)b * S_LEN * D_DIM + d0;
    const float invn = 1.0f / 2048.0f;
    for (int s = threadIdx.x; s < 2048; s += 256) {
        float2 r = cur[SMAP(s)];
        *(float2*)(dst + (size_t)s * D_DIM) = make_float2(r.x * invn, r.y * invn);
    }
}

// ---------------- launcher ----------------
extern "C" void kernel_launch(void* const* d_in, const int* in_sizes, int n_in,
                              void* d_out, int out_size)
{
    const float* x     = (const float*)d_in[0];
    const float* in_w  = (const float*)d_in[1];
    const float* in_b  = (const float*)d_in[2];
    const float* out_w = (const float*)d_in[3];
    const float* out_b = (const float*)d_in[4];
    const float* ln1g  = (const float*)d_in[5];
    const float* ln1b  = (const float*)d_in[6];
    const float* wr    = (const float*)d_in[7];
    const float* wi    = (const float*)d_in[8];
    const float* ln2g  = (const float*)d_in[9];
    const float* ln2b  = (const float*)d_in[10];
    float* out = (float*)d_out;

    float *qkv, *attn, *attnout, *xattn, *xwave;
    cudaGetSymbolAddress((void**)&qkv,     g_qkv);
    cudaGetSymbolAddress((void**)&attn,    g_attn);
    cudaGetSymbolAddress((void**)&attnout, g_attnout);
    cudaGetSymbolAddress((void**)&xattn,   g_xattn);
    cudaGetSymbolAddress((void**)&xwave,   g_xwave);

    // spectral path (independent)
    spectral_kernel<<<dim3(D_DIM / 2, B_SZ), 256>>>(x, wr, wi, xwave);

    // QKV projection (tf32 tensor cores)
    sgemm_tf32_nt_bias<<<dim3(D3 / 128, NTOK / 128), 256>>>(x, in_w, in_b, qkv,
                                                            NTOK, D3, D_DIM);

    // windowed flash attention (tf32 tensor cores)
    attn_tc_kernel<<<dim3(S_LEN / 64, NH, B_SZ), 128>>>();

    // output projection (tf32 tensor cores)
    sgemm_tf32_nt_bias<<<dim3(D_DIM / 128, NTOK / 128), 256>>>(attn, out_w, out_b, attnout,
                                                               NTOK, D_DIM, D_DIM);

    // x_attn = LN1(x + attn_out)
    add_ln_kernel<<<NTOK, 256>>>(x, attnout, ln1g, ln1b, xattn);

    // out = LN2(x_attn + x_wave)
    add_ln_kernel<<<NTOK, 256>>>(xattn, xwave, ln2g, ln2b, out);
}

// round 8
// speedup vs baseline: 4.4801x; 1.1091x over previous
#include <cuda_runtime.h>
#include <math.h>
#include <stdint.h>

#define S_LEN 2048
#define D_DIM 1024
#define B_SZ  2
#define NH    16
#define DHE   64
#define WIN   128
#define NTOK  (B_SZ * S_LEN)   // 4096
#define D3    (3 * D_DIM)      // 3072

#define SMAP(i) ((i) + ((i) >> 4))

// ---------------- scratch ----------------
__device__ float g_qkv[(size_t)NTOK * D3];
__device__ float g_attn[(size_t)NTOK * D_DIM];
__device__ float g_attnout[(size_t)NTOK * D_DIM];
__device__ float g_xattn[(size_t)NTOK * D_DIM];
__device__ float g_xwave[(size_t)NTOK * D_DIM];

// ---------------- helpers ----------------
__device__ __forceinline__ uint32_t smem_u32(const void* p) {
    uint32_t a;
    asm("{ .reg .u64 t; cvta.to.shared.u64 t, %1; cvt.u32.u64 %0, t; }" : "=r"(a) : "l"(p));
    return a;
}
__device__ __forceinline__ void cpasync16(uint32_t dst, const void* src) {
    asm volatile("cp.async.ca.shared.global [%0], [%1], 16;" :: "r"(dst), "l"(src));
}
#define CP_COMMIT() asm volatile("cp.async.commit_group;" ::: "memory")
#define CP_WAIT1()  asm volatile("cp.async.wait_group 1;" ::: "memory")
#define CP_WAIT0()  asm volatile("cp.async.wait_group 0;" ::: "memory")

__device__ __forceinline__ uint32_t f2tf(float f) {
    uint32_t u;
    asm("cvt.rna.tf32.f32 %0, %1;" : "=r"(u) : "f"(f));
    return u;
}
__device__ __forceinline__ void mma_tf32(
    float& c0, float& c1, float& c2, float& c3,
    uint32_t a0, uint32_t a1, uint32_t a2, uint32_t a3,
    uint32_t b0, uint32_t b1)
{
    asm volatile(
        "mma.sync.aligned.m16n8k8.row.col.f32.tf32.tf32.f32 "
        "{%0,%1,%2,%3}, {%4,%5,%6,%7}, {%8,%9}, {%0,%1,%2,%3};\n"
        : "+f"(c0), "+f"(c1), "+f"(c2), "+f"(c3)
        : "r"(a0), "r"(a1), "r"(a2), "r"(a3), "r"(b0), "r"(b1));
}

// ---------------- tf32 GEMM, 3-stage cp.async pipeline ----------------
// C[M,N] = A[M,K] @ W[N,K]^T + bias. BM=BN=128, BK=16, 256 thr = 8 warps,
// warp tile 64x32. Raw f32 bits fed to tf32 MMA (HW truncates mantissa).
#define LDK 20
#define STG 3
__global__ void __launch_bounds__(256, 2) sgemm_tf32_pipe(
    const float* __restrict__ A, const float* __restrict__ W,
    const float* __restrict__ bias, float* __restrict__ C,
    int M, int N, int K)
{
    __shared__ uint32_t As[STG][128][LDK];
    __shared__ uint32_t Ws[STG][128][LDK];

    const int row0 = blockIdx.y * 128;
    const int col0 = blockIdx.x * 128;
    const int t    = threadIdx.x;
    const int warp = t >> 5;
    const int lane = t & 31;
    const int gr   = lane >> 2;
    const int tc   = lane & 3;
    const int m0w  = (warp >> 2) * 64;
    const int n0w  = (warp & 3) * 32;

    // 512 float4 slots per matrix: slot s -> row = s>>2, c4 = (s&3)*4; 2 per thread
    const int r0l = t >> 2;            const int c0l = (t & 3) * 4;
    const int r1l = (t + 256) >> 2;    const int c1l = ((t + 256) & 3) * 4;

    const float* Ar0 = A + (size_t)(row0 + r0l) * K + c0l;
    const float* Ar1 = A + (size_t)(row0 + r1l) * K + c1l;
    const float* Wr0 = W + (size_t)(col0 + r0l) * K + c0l;
    const float* Wr1 = W + (size_t)(col0 + r1l) * K + c1l;

    float acc[4][4][4];
#pragma unroll
    for (int mi = 0; mi < 4; mi++)
#pragma unroll
        for (int ni = 0; ni < 4; ni++)
#pragma unroll
            for (int r = 0; r < 4; r++) acc[mi][ni][r] = 0.f;

    const int ntiles = K >> 4;

    // prologue: stages 0 and 1 in flight
#pragma unroll
    for (int s = 0; s < 2; s++) {
        const int k0 = s << 4;
        cpasync16(smem_u32(&As[s][r0l][c0l]), Ar0 + k0);
        cpasync16(smem_u32(&As[s][r1l][c1l]), Ar1 + k0);
        cpasync16(smem_u32(&Ws[s][r0l][c0l]), Wr0 + k0);
        cpasync16(smem_u32(&Ws[s][r1l][c1l]), Wr1 + k0);
        CP_COMMIT();
    }

    int cb = 0, nst = 2;
    for (int kt = 0; kt < ntiles; kt++) {
        CP_WAIT1();            // stage kt complete (kt+1 may still be in flight)
        __syncthreads();       // all threads' waits done -> tile visible; prev compute done

        if (kt + 2 < ntiles) { // prefetch kt+2 into the slot freed by compute kt-1
            const int k0 = (kt + 2) << 4;
            cpasync16(smem_u32(&As[nst][r0l][c0l]), Ar0 + k0);
            cpasync16(smem_u32(&As[nst][r1l][c1l]), Ar1 + k0);
            cpasync16(smem_u32(&Ws[nst][r0l][c0l]), Wr0 + k0);
            cpasync16(smem_u32(&Ws[nst][r1l][c1l]), Wr1 + k0);
        }
        CP_COMMIT();           // commit every iter (possibly empty) keeps group count in sync

#pragma unroll
        for (int kk = 0; kk < 2; kk++) {
            uint32_t af[4][4];
#pragma unroll
            for (int mi = 0; mi < 4; mi++) {
                const int br = m0w + mi * 16;
                af[mi][0] = As[cb][br + gr][kk * 8 + tc];
                af[mi][1] = As[cb][br + gr + 8][kk * 8 + tc];
                af[mi][2] = As[cb][br + gr][kk * 8 + tc + 4];
                af[mi][3] = As[cb][br + gr + 8][kk * 8 + tc + 4];
            }
            uint32_t bf[4][2];
#pragma unroll
            for (int ni = 0; ni < 4; ni++) {
                const int bn = n0w + ni * 8 + gr;
                bf[ni][0] = Ws[cb][bn][kk * 8 + tc];
                bf[ni][1] = Ws[cb][bn][kk * 8 + tc + 4];
            }
#pragma unroll
            for (int mi = 0; mi < 4; mi++)
#pragma unroll
                for (int ni = 0; ni < 4; ni++)
                    mma_tf32(acc[mi][ni][0], acc[mi][ni][1], acc[mi][ni][2], acc[mi][ni][3],
                             af[mi][0], af[mi][1], af[mi][2], af[mi][3],
                             bf[ni][0], bf[ni][1]);
        }

        cb  = (cb  + 1) % STG;
        nst = (nst + 1) % STG;
    }

    // epilogue
#pragma unroll
    for (int mi = 0; mi < 4; mi++) {
#pragma unroll
        for (int ni = 0; ni < 4; ni++) {
            const int r = row0 + m0w + mi * 16 + gr;
            const int c = col0 + n0w + ni * 8 + tc * 2;
            float2 bs = *(const float2*)(bias + c);
            float2 v0 = make_float2(acc[mi][ni][0] + bs.x, acc[mi][ni][1] + bs.y);
            float2 v1 = make_float2(acc[mi][ni][2] + bs.x, acc[mi][ni][3] + bs.y);
            *(float2*)(C + (size_t)r * N + c)       = v0;
            *(float2*)(C + (size_t)(r + 8) * N + c) = v1;
        }
    }
}

// ---------------- tensor-core windowed flash attention ----------------
#define QPAD 68
#define VPAD 72
__global__ void __launch_bounds__(128) attn_tc_kernel()
{
    __shared__ uint32_t Qs[64][QPAD];
    __shared__ uint32_t Ks[64][QPAD];
    __shared__ uint32_t Vs[64][VPAD];
    __shared__ uint32_t Ps[64][QPAD];

    const int q0  = blockIdx.x * 64;
    const int h   = blockIdx.y;
    const int b   = blockIdx.z;
    const int t   = threadIdx.x;
    const int wid = t >> 5;
    const int lane = t & 31;
    const int gr  = lane >> 2;
    const int tc  = lane & 3;

#pragma unroll
    for (int i = 0; i < 8; i++) {
        int lin = t + 128 * i;
        int row = lin >> 4;
        int c4  = (lin & 15) * 4;
        const float* src = g_qkv + (size_t)(b * S_LEN + q0 + row) * D3 + h * DHE + c4;
        float4 v = *(const float4*)src;
        *(uint4*)&Qs[row][c4] = make_uint4(f2tf(v.x * 0.125f), f2tf(v.y * 0.125f),
                                           f2tf(v.z * 0.125f), f2tf(v.w * 0.125f));
    }

    const int qr0 = q0 + wid * 16 + gr;
    const int qr1 = qr0 + 8;

    float m0 = -1e30f, m1 = -1e30f, l0 = 0.f, l1 = 0.f;
    float oacc[8][4];
#pragma unroll
    for (int nt = 0; nt < 8; nt++)
#pragma unroll
        for (int r = 0; r < 4; r++) oacc[nt][r] = 0.f;

    const int kstart = (q0 - WIN > 0) ? (q0 - WIN) : 0;
    const int kend   = (q0 + 64 + WIN < S_LEN) ? (q0 + 64 + WIN) : S_LEN;

    for (int kc = kstart; kc < kend; kc += 64) {
        __syncthreads();
#pragma unroll
        for (int i = 0; i < 8; i++) {
            int lin = t + 128 * i;
            int row = lin >> 4;
            int c4  = (lin & 15) * 4;
            const float* kp = g_qkv + (size_t)(b * S_LEN + kc + row) * D3 + D_DIM + h * DHE + c4;
            float4 kv = *(const float4*)kp;
            float4 vv = *(const float4*)(kp + D_DIM);
            *(uint4*)&Ks[row][c4] = make_uint4(f2tf(kv.x), f2tf(kv.y), f2tf(kv.z), f2tf(kv.w));
            *(uint4*)&Vs[row][c4] = make_uint4(f2tf(vv.x), f2tf(vv.y), f2tf(vv.z), f2tf(vv.w));
        }
        __syncthreads();

        float sacc[8][4];
#pragma unroll
        for (int nt = 0; nt < 8; nt++)
#pragma unroll
            for (int r = 0; r < 4; r++) sacc[nt][r] = 0.f;

#pragma unroll
        for (int ks = 0; ks < 8; ks++) {
            const int qrow = wid * 16 + gr;
            uint32_t af0 = Qs[qrow][ks * 8 + tc];
            uint32_t af1 = Qs[qrow + 8][ks * 8 + tc];
            uint32_t af2 = Qs[qrow][ks * 8 + tc + 4];
            uint32_t af3 = Qs[qrow + 8][ks * 8 + tc + 4];
#pragma unroll
            for (int nt = 0; nt < 8; nt++) {
                uint32_t b0 = Ks[nt * 8 + gr][ks * 8 + tc];
                uint32_t b1 = Ks[nt * 8 + gr][ks * 8 + tc + 4];
                mma_tf32(sacc[nt][0], sacc[nt][1], sacc[nt][2], sacc[nt][3],
                         af0, af1, af2, af3, b0, b1);
            }
        }

        float mx0 = m0, mx1 = m1;
#pragma unroll
        for (int nt = 0; nt < 8; nt++) {
            const int c = kc + nt * 8 + 2 * tc;
            if (c     < qr0 - WIN || c     > qr0 + WIN) sacc[nt][0] = -1e30f;
            if (c + 1 < qr0 - WIN || c + 1 > qr0 + WIN) sacc[nt][1] = -1e30f;
            if (c     < qr1 - WIN || c     > qr1 + WIN) sacc[nt][2] = -1e30f;
            if (c + 1 < qr1 - WIN || c + 1 > qr1 + WIN) sacc[nt][3] = -1e30f;
            mx0 = fmaxf(mx0, fmaxf(sacc[nt][0], sacc[nt][1]));
            mx1 = fmaxf(mx1, fmaxf(sacc[nt][2], sacc[nt][3]));
        }
        mx0 = fmaxf(mx0, __shfl_xor_sync(0xffffffffu, mx0, 1));
        mx0 = fmaxf(mx0, __shfl_xor_sync(0xffffffffu, mx0, 2));
        mx1 = fmaxf(mx1, __shfl_xor_sync(0xffffffffu, mx1, 1));
        mx1 = fmaxf(mx1, __shfl_xor_sync(0xffffffffu, mx1, 2));

        const float alpha0 = __expf(m0 - mx0);
        const float alpha1 = __expf(m1 - mx1);

        float ps0 = 0.f, ps1 = 0.f;
        const int prow = wid * 16 + gr;
#pragma unroll
        for (int nt = 0; nt < 8; nt++) {
            float p00 = __expf(sacc[nt][0] - mx0);
            float p01 = __expf(sacc[nt][1] - mx0);
            float p10 = __expf(sacc[nt][2] - mx1);
            float p11 = __expf(sacc[nt][3] - mx1);
            ps0 += p00 + p01;
            ps1 += p10 + p11;
            *(uint2*)&Ps[prow][nt * 8 + 2 * tc]     = make_uint2(f2tf(p00), f2tf(p01));
            *(uint2*)&Ps[prow + 8][nt * 8 + 2 * tc] = make_uint2(f2tf(p10), f2tf(p11));
        }
        ps0 += __shfl_xor_sync(0xffffffffu, ps0, 1);
        ps0 += __shfl_xor_sync(0xffffffffu, ps0, 2);
        ps1 += __shfl_xor_sync(0xffffffffu, ps1, 1);
        ps1 += __shfl_xor_sync(0xffffffffu, ps1, 2);

        l0 = l0 * alpha0 + ps0;  m0 = mx0;
        l1 = l1 * alpha1 + ps1;  m1 = mx1;

#pragma unroll
        for (int nt = 0; nt < 8; nt++) {
            oacc[nt][0] *= alpha0; oacc[nt][1] *= alpha0;
            oacc[nt][2] *= alpha1; oacc[nt][3] *= alpha1;
        }

        __syncwarp();

#pragma unroll
        for (int ks = 0; ks < 8; ks++) {
            uint32_t af0 = Ps[prow][ks * 8 + tc];
            uint32_t af1 = Ps[prow + 8][ks * 8 + tc];
            uint32_t af2 = Ps[prow][ks * 8 + tc + 4];
            uint32_t af3 = Ps[prow + 8][ks * 8 + tc + 4];
#pragma unroll
            for (int nt = 0; nt < 8; nt++) {
                uint32_t b0 = Vs[ks * 8 + tc][nt * 8 + gr];
                uint32_t b1 = Vs[ks * 8 + tc + 4][nt * 8 + gr];
                mma_tf32(oacc[nt][0], oacc[nt][1], oacc[nt][2], oacc[nt][3],
                         af0, af1, af2, af3, b0, b1);
            }
        }
    }

    const float inv0 = 1.0f / l0;
    const float inv1 = 1.0f / l1;
    const size_t row0g = (size_t)(b * S_LEN) + qr0;
#pragma unroll
    for (int nt = 0; nt < 8; nt++) {
        const int col = h * DHE + nt * 8 + 2 * tc;
        *(float2*)(g_attn + row0g * D_DIM + col) =
            make_float2(oacc[nt][0] * inv0, oacc[nt][1] * inv0);
        *(float2*)(g_attn + (row0g + 8) * D_DIM + col) =
            make_float2(oacc[nt][2] * inv1, oacc[nt][3] * inv1);
    }
}

// ---------------- fused add + LayerNorm (float4) ----------------
__global__ void __launch_bounds__(256) add_ln_kernel(
    const float* __restrict__ A, const float* __restrict__ Bv,
    const float* __restrict__ g, const float* __restrict__ beta,
    float* __restrict__ out)
{
    __shared__ float red[8];
    const int row = blockIdx.x;
    const int t   = threadIdx.x;

    float4 a = *(const float4*)(A  + (size_t)row * D_DIM + t * 4);
    float4 b = *(const float4*)(Bv + (size_t)row * D_DIM + t * 4);
    float4 v = make_float4(a.x + b.x, a.y + b.y, a.z + b.z, a.w + b.w);

    float s = v.x + v.y + v.z + v.w;
#pragma unroll
    for (int o = 16; o; o >>= 1) s += __shfl_xor_sync(0xffffffffu, s, o);
    if ((t & 31) == 0) red[t >> 5] = s;
    __syncthreads();
    float tot = 0.f;
#pragma unroll
    for (int i = 0; i < 8; i++) tot += red[i];
    const float mu = tot * (1.f / (float)D_DIM);
    __syncthreads();

    float dx = v.x - mu, dy = v.y - mu, dz = v.z - mu, dw = v.w - mu;
    float s2 = dx * dx + dy * dy + dz * dz + dw * dw;
#pragma unroll
    for (int o = 16; o; o >>= 1) s2 += __shfl_xor_sync(0xffffffffu, s2, o);
    if ((t & 31) == 0) red[t >> 5] = s2;
    __syncthreads();
    float tot2 = 0.f;
#pragma unroll
    for (int i = 0; i < 8; i++) tot2 += red[i];
    const float inv = rsqrtf(tot2 * (1.f / (float)D_DIM) + 1e-5f);

    float4 gg = *(const float4*)(g    + t * 4);
    float4 bb = *(const float4*)(beta + t * 4);
    float4 o4 = make_float4(dx * inv * gg.x + bb.x, dy * inv * gg.y + bb.y,
                            dz * inv * gg.z + bb.z, dw * inv * gg.w + bb.w);
    *(float4*)(out + (size_t)row * D_DIM + t * 4) = o4;
}

// ---------------- spectral block ----------------
__device__ __forceinline__ float2 cmul(float2 a, float2 b) {
    return make_float2(a.x * b.x - a.y * b.y, a.x * b.y + a.y * b.x);
}

template<int SIGN>
__device__ __forceinline__ void fft2048_r4(float2*& cur, float2*& oth)
{
    int n = 2048, ls = 0;
#pragma unroll
    for (int st = 0; st < 5; st++) {
        const int ss = 1 << ls;
        const float fn = (2.0f * 3.14159265358979f * (float)SIGN) / (float)n;
#pragma unroll
        for (int ii = 0; ii < 2; ii++) {
            const int idx = threadIdx.x + 256 * ii;
            const int p = idx >> ls;
            const int q = idx & (ss - 1);
            float2 x0 = cur[SMAP(idx)];
            float2 x1 = cur[SMAP(idx + 512)];
            float2 x2 = cur[SMAP(idx + 1024)];
            float2 x3 = cur[SMAP(idx + 1536)];
            float sn, cs;
            __sincosf(fn * (float)p, &sn, &cs);
            const float2 wA = make_float2(cs, sn);
            const float2 wB = cmul(wA, wA);
            float2 a0 = make_float2(x0.x + x2.x, x0.y + x2.y);
            float2 a1 = make_float2(x0.x - x2.x, x0.y - x2.y);
            float2 b0 = make_float2(x1.x + x3.x, x1.y + x3.y);
            float2 u  = make_float2(x1.x - x3.x, x1.y - x3.y);
            float2 b1 = make_float2(-(float)SIGN * u.y, (float)SIGN * u.x);
            float2 A1p = cmul(a1, wA);
            float2 A1q = cmul(b1, wA);
            const int ob = q + 4 * ss * p;
            oth[SMAP(ob)]          = make_float2(a0.x + b0.x, a0.y + b0.y);
            float2 d0v = make_float2(a0.x - b0.x, a0.y - b0.y);
            oth[SMAP(ob + 2 * ss)] = cmul(d0v, wB);
            oth[SMAP(ob + ss)]     = make_float2(A1p.x + A1q.x, A1p.y + A1q.y);
            float2 d1v = make_float2(A1p.x - A1q.x, A1p.y - A1q.y);
            oth[SMAP(ob + 3 * ss)] = cmul(d1v, wB);
        }
        __syncthreads();
        float2* t = cur; cur = oth; oth = t;
        n >>= 2; ls += 2;
    }
#pragma unroll
    for (int ii = 0; ii < 4; ii++) {
        const int q = threadIdx.x + 256 * ii;
        float2 a = cur[SMAP(q)];
        float2 b = cur[SMAP(q + 1024)];
        oth[SMAP(q)]        = make_float2(a.x + b.x, a.y + b.y);
        oth[SMAP(q + 1024)] = make_float2(a.x - b.x, a.y - b.y);
    }
    __syncthreads();
    { float2* t = cur; cur = oth; oth = t; }
}

__global__ void __launch_bounds__(256) spectral_kernel(
    const float* __restrict__ x, const float* __restrict__ wr,
    const float* __restrict__ wi, float* __restrict__ xwave)
{
    __shared__ float2 bufA[2176];
    __shared__ float2 bufB[2176];
    const int d0 = blockIdx.x * 2;
    const int b  = blockIdx.y;

    const float* xp = x + (size_t)b * S_LEN * D_DIM + d0;
    for (int s = threadIdx.x; s < 2048; s += 256)
        bufA[SMAP(s)] = *(const float2*)(xp + (size_t)s * D_DIM);
    __syncthreads();

    float2* cur = bufA;
    float2* oth = bufB;
    fft2048_r4<-1>(cur, oth);

    for (int k = threadIdx.x; k < 2048; k += 256) {
        const int km = (2048 - k) & 2047;
        float2 Zk = cur[SMAP(k)];
        float2 Zm = cur[SMAP(km)];
        float2 Av = make_float2(0.5f * (Zk.x + Zm.x), 0.5f * (Zk.y - Zm.y));
        float2 Bc = make_float2(0.5f * (Zk.y + Zm.y), -0.5f * (Zk.x - Zm.x));
        const int   kf  = (k <= 1024) ? k : 2048 - k;
        const float sgn = (k <= 1024) ? 1.f : -1.f;
        float2 wrp = *(const float2*)(wr + (size_t)kf * D_DIM + d0);
        float2 wip = *(const float2*)(wi + (size_t)kf * D_DIM + d0);
        float2 c1 = make_float2(wrp.x, sgn * wip.x);
        float2 c2 = make_float2(wrp.y, sgn * wip.y);
        if (k == 0 || k == 1024) { c1.y = 0.f; c2.y = 0.f; }
        float2 Y1 = cmul(Av, c1);
        float2 Y2 = cmul(Bc, c2);
        oth[SMAP(k)] = make_float2(Y1.x - Y2.y, Y1.y + Y2.x);
    }
    __syncthreads();
    { float2* t = cur; cur = oth; oth = t; }

    fft2048_r4<1>(cur, oth);

    float* dst = xwave + (size_t)b * S_LEN * D_DIM + d0;
    const float invn = 1.0f / 2048.0f;
    for (int s = threadIdx.x; s < 2048; s += 256) {
        float2 r = cur[SMAP(s)];
        *(float2*)(dst + (size_t)s * D_DIM) = make_float2(r.x * invn, r.y * invn);
    }
}

// ---------------- launcher ----------------
extern "C" void kernel_launch(void* const* d_in, const int* in_sizes, int n_in,
                              void* d_out, int out_size)
{
    const float* x     = (const float*)d_in[0];
    const float* in_w  = (const float*)d_in[1];
    const float* in_b  = (const float*)d_in[2];
    const float* out_w = (const float*)d_in[3];
    const float* out_b = (const float*)d_in[4];
    const float* ln1g  = (const float*)d_in[5];
    const float* ln1b  = (const float*)d_in[6];
    const float* wr    = (const float*)d_in[7];
    const float* wi    = (const float*)d_in[8];
    const float* ln2g  = (const float*)d_in[9];
    const float* ln2b  = (const float*)d_in[10];
    float* out = (float*)d_out;

    float *qkv, *attn, *attnout, *xattn, *xwave;
    cudaGetSymbolAddress((void**)&qkv,     g_qkv);
    cudaGetSymbolAddress((void**)&attn,    g_attn);
    cudaGetSymbolAddress((void**)&attnout, g_attnout);
    cudaGetSymbolAddress((void**)&xattn,   g_xattn);
    cudaGetSymbolAddress((void**)&xwave,   g_xwave);

    // spectral path (independent)
    spectral_kernel<<<dim3(D_DIM / 2, B_SZ), 256>>>(x, wr, wi, xwave);

    // QKV projection (tf32 mma.sync, cp.async pipeline)
    sgemm_tf32_pipe<<<dim3(D3 / 128, NTOK / 128), 256>>>(x, in_w, in_b, qkv,
                                                         NTOK, D3, D_DIM);

    // windowed flash attention (tf32 mma.sync)
    attn_tc_kernel<<<dim3(S_LEN / 64, NH, B_SZ), 128>>>();

    // output projection
    sgemm_tf32_pipe<<<dim3(D_DIM / 128, NTOK / 128), 256>>>(attn, out_w, out_b, attnout,
                                                            NTOK, D_DIM, D_DIM);

    // x_attn = LN1(x + attn_out)
    add_ln_kernel<<<NTOK, 256>>>(x, attnout, ln1g, ln1b, xattn);

    // out = LN2(x_attn + x_wave)
    add_ln_kernel<<<NTOK, 256>>>(xattn, xwave, ln2g, ln2b, out);
}

// round 11
// speedup vs baseline: 5.8826x; 1.3130x over previous
#include <cuda_runtime.h>
#include <cuda_fp16.h>
#include <math.h>
#include <stdint.h>

#define S_LEN 2048
#define D_DIM 1024
#define B_SZ  2
#define NH    16
#define DHE   64
#define WIN   128
#define NTOK  (B_SZ * S_LEN)   // 4096
#define D3    (3 * D_DIM)      // 3072

#define SMAP(i) ((i) + ((i) >> 4))

// ---------------- scratch ----------------
__device__ float g_qkv[(size_t)NTOK * D3];
__device__ float g_attn[(size_t)NTOK * D_DIM];
__device__ float g_attnout[(size_t)NTOK * D_DIM];
__device__ float g_xattn[(size_t)NTOK * D_DIM];
__device__ float g_xwave[(size_t)NTOK * D_DIM];

// ---------------- helpers ----------------
__device__ __forceinline__ uint32_t f22h2(float a, float b) {
    __half2 h = __floats2half2_rn(a, b);
    return *(uint32_t*)&h;
}
__device__ __forceinline__ uint32_t f2tf(float f) {
    uint32_t u;
    asm("cvt.rna.tf32.f32 %0, %1;" : "=r"(u) : "f"(f));
    return u;
}
__device__ __forceinline__ void mma_fp16(
    float& c0, float& c1, float& c2, float& c3,
    uint32_t a0, uint32_t a1, uint32_t a2, uint32_t a3,
    uint32_t b0, uint32_t b1)
{
    asm volatile(
        "mma.sync.aligned.m16n8k16.row.col.f32.f16.f16.f32 "
        "{%0,%1,%2,%3}, {%4,%5,%6,%7}, {%8,%9}, {%0,%1,%2,%3};\n"
        : "+f"(c0), "+f"(c1), "+f"(c2), "+f"(c3)
        : "r"(a0), "r"(a1), "r"(a2), "r"(a3), "r"(b0), "r"(b1));
}
__device__ __forceinline__ void mma_tf32(
    float& c0, float& c1, float& c2, float& c3,
    uint32_t a0, uint32_t a1, uint32_t a2, uint32_t a3,
    uint32_t b0, uint32_t b1)
{
    asm volatile(
        "mma.sync.aligned.m16n8k8.row.col.f32.tf32.tf32.f32 "
        "{%0,%1,%2,%3}, {%4,%5,%6,%7}, {%8,%9}, {%0,%1,%2,%3};\n"
        : "+f"(c0), "+f"(c1), "+f"(c2), "+f"(c3)
        : "r"(a0), "r"(a1), "r"(a2), "r"(a3), "r"(b0), "r"(b1));
}

// ---------------- fp16 GEMM: C[M,N] = A[M,K] @ W[N,K]^T + bias ----------------
// BM=BN=128, BK=32 (2 x k16 MMA steps/tile), 256 thr = 8 warps, warp tile 64x32.
// Double-buffered smem of half2 (rows padded to LDP u32 for conflict-free frags).
#define LDP 20
__global__ void __launch_bounds__(256, 2) gemm_fp16_db(
    const float* __restrict__ A, const float* __restrict__ W,
    const float* __restrict__ bias, float* __restrict__ C,
    int M, int N, int K)
{
    __shared__ uint32_t As2[2][128][LDP];
    __shared__ uint32_t Ws2[2][128][LDP];

    const int row0 = blockIdx.y * 128;
    const int col0 = blockIdx.x * 128;
    const int t    = threadIdx.x;
    const int warp = t >> 5;
    const int lane = t & 31;
    const int gr   = lane >> 2;
    const int tc   = lane & 3;
    const int m0w  = (warp >> 2) * 64;
    const int n0w  = (warp & 3) * 32;

    // 1024 float4 slots per matrix-tile (128 rows x 8 f4); 4 per thread
    int rr[4], cc[4];
#pragma unroll
    for (int i = 0; i < 4; i++) { int s = t + 256 * i; rr[i] = s >> 3; cc[i] = (s & 7) * 4; }

    float acc[4][4][4];
#pragma unroll
    for (int mi = 0; mi < 4; mi++)
#pragma unroll
        for (int ni = 0; ni < 4; ni++)
#pragma unroll
            for (int r = 0; r < 4; r++) acc[mi][ni][r] = 0.f;

    float4 pa[4], pw[4];

    // prologue: tile 0 -> stage 0
#pragma unroll
    for (int i = 0; i < 4; i++) {
        pa[i] = *(const float4*)(A + (size_t)(row0 + rr[i]) * K + cc[i]);
        pw[i] = *(const float4*)(W + (size_t)(col0 + rr[i]) * K + cc[i]);
    }
#pragma unroll
    for (int i = 0; i < 4; i++) {
        *(uint2*)&As2[0][rr[i]][cc[i] >> 1] =
            make_uint2(f22h2(pa[i].x, pa[i].y), f22h2(pa[i].z, pa[i].w));
        *(uint2*)&Ws2[0][rr[i]][cc[i] >> 1] =
            make_uint2(f22h2(pw[i].x, pw[i].y), f22h2(pw[i].z, pw[i].w));
    }
    __syncthreads();

    const int ntiles = K >> 5;          // BK = 32
    for (int kt = 0; kt < ntiles; kt++) {
        const int cb = kt & 1;
        const bool hasnext = (kt + 1 < ntiles);
        if (hasnext) {
            const int k0 = (kt + 1) << 5;
#pragma unroll
            for (int i = 0; i < 4; i++) {
                pa[i] = *(const float4*)(A + (size_t)(row0 + rr[i]) * K + k0 + cc[i]);
                pw[i] = *(const float4*)(W + (size_t)(col0 + rr[i]) * K + k0 + cc[i]);
            }
        }

#pragma unroll
        for (int kk = 0; kk < 2; kk++) {       // two k16 steps
            uint32_t af[4][4];
#pragma unroll
            for (int mi = 0; mi < 4; mi++) {
                const int br = m0w + mi * 16;
                af[mi][0] = As2[cb][br + gr][kk * 8 + tc];
                af[mi][1] = As2[cb][br + gr + 8][kk * 8 + tc];
                af[mi][2] = As2[cb][br + gr][kk * 8 + tc + 4];
                af[mi][3] = As2[cb][br + gr + 8][kk * 8 + tc + 4];
            }
            uint32_t bf[4][2];
#pragma unroll
            for (int ni = 0; ni < 4; ni++) {
                const int bn = n0w + ni * 8 + gr;
                bf[ni][0] = Ws2[cb][bn][kk * 8 + tc];
                bf[ni][1] = Ws2[cb][bn][kk * 8 + tc + 4];
            }
#pragma unroll
            for (int mi = 0; mi < 4; mi++)
#pragma unroll
                for (int ni = 0; ni < 4; ni++)
                    mma_fp16(acc[mi][ni][0], acc[mi][ni][1], acc[mi][ni][2], acc[mi][ni][3],
                             af[mi][0], af[mi][1], af[mi][2], af[mi][3],
                             bf[ni][0], bf[ni][1]);
        }

        if (hasnext) {
            const int nb = cb ^ 1;
#pragma unroll
            for (int i = 0; i < 4; i++) {
                *(uint2*)&As2[nb][rr[i]][cc[i] >> 1] =
                    make_uint2(f22h2(pa[i].x, pa[i].y), f22h2(pa[i].z, pa[i].w));
                *(uint2*)&Ws2[nb][rr[i]][cc[i] >> 1] =
                    make_uint2(f22h2(pw[i].x, pw[i].y), f22h2(pw[i].z, pw[i].w));
            }
        }
        __syncthreads();
    }

    // epilogue (C frag layout: rows gr/gr+8, cols 2tc,2tc+1)
#pragma unroll
    for (int mi = 0; mi < 4; mi++) {
#pragma unroll
        for (int ni = 0; ni < 4; ni++) {
            const int r = row0 + m0w + mi * 16 + gr;
            const int c = col0 + n0w + ni * 8 + tc * 2;
            float2 bs = *(const float2*)(bias + c);
            float2 v0 = make_float2(acc[mi][ni][0] + bs.x, acc[mi][ni][1] + bs.y);
            float2 v1 = make_float2(acc[mi][ni][2] + bs.x, acc[mi][ni][3] + bs.y);
            *(float2*)(C + (size_t)r * N + c)       = v0;
            *(float2*)(C + (size_t)(r + 8) * N + c) = v1;
        }
    }
}

// ---------------- tensor-core windowed flash attention (tf32, unchanged) ----------------
#define QPAD 68
#define VPAD 72
__global__ void __launch_bounds__(128) attn_tc_kernel()
{
    __shared__ uint32_t Qs[64][QPAD];
    __shared__ uint32_t Ks[64][QPAD];
    __shared__ uint32_t Vs[64][VPAD];
    __shared__ uint32_t Ps[64][QPAD];

    const int q0  = blockIdx.x * 64;
    const int h   = blockIdx.y;
    const int b   = blockIdx.z;
    const int t   = threadIdx.x;
    const int wid = t >> 5;
    const int lane = t & 31;
    const int gr  = lane >> 2;
    const int tc  = lane & 3;

#pragma unroll
    for (int i = 0; i < 8; i++) {
        int lin = t + 128 * i;
        int row = lin >> 4;
        int c4  = (lin & 15) * 4;
        const float* src = g_qkv + (size_t)(b * S_LEN + q0 + row) * D3 + h * DHE + c4;
        float4 v = *(const float4*)src;
        *(uint4*)&Qs[row][c4] = make_uint4(f2tf(v.x * 0.125f), f2tf(v.y * 0.125f),
                                           f2tf(v.z * 0.125f), f2tf(v.w * 0.125f));
    }

    const int qr0 = q0 + wid * 16 + gr;
    const int qr1 = qr0 + 8;

    float m0 = -1e30f, m1 = -1e30f, l0 = 0.f, l1 = 0.f;
    float oacc[8][4];
#pragma unroll
    for (int nt = 0; nt < 8; nt++)
#pragma unroll
        for (int r = 0; r < 4; r++) oacc[nt][r] = 0.f;

    const int kstart = (q0 - WIN > 0) ? (q0 - WIN) : 0;
    const int kend   = (q0 + 64 + WIN < S_LEN) ? (q0 + 64 + WIN) : S_LEN;

    for (int kc = kstart; kc < kend; kc += 64) {
        __syncthreads();
#pragma unroll
        for (int i = 0; i < 8; i++) {
            int lin = t + 128 * i;
            int row = lin >> 4;
            int c4  = (lin & 15) * 4;
            const float* kp = g_qkv + (size_t)(b * S_LEN + kc + row) * D3 + D_DIM + h * DHE + c4;
            float4 kv = *(const float4*)kp;
            float4 vv = *(const float4*)(kp + D_DIM);
            *(uint4*)&Ks[row][c4] = make_uint4(f2tf(kv.x), f2tf(kv.y), f2tf(kv.z), f2tf(kv.w));
            *(uint4*)&Vs[row][c4] = make_uint4(f2tf(vv.x), f2tf(vv.y), f2tf(vv.z), f2tf(vv.w));
        }
        __syncthreads();

        float sacc[8][4];
#pragma unroll
        for (int nt = 0; nt < 8; nt++)
#pragma unroll
            for (int r = 0; r < 4; r++) sacc[nt][r] = 0.f;

#pragma unroll
        for (int ks = 0; ks < 8; ks++) {
            const int qrow = wid * 16 + gr;
            uint32_t af0 = Qs[qrow][ks * 8 + tc];
            uint32_t af1 = Qs[qrow + 8][ks * 8 + tc];
            uint32_t af2 = Qs[qrow][ks * 8 + tc + 4];
            uint32_t af3 = Qs[qrow + 8][ks * 8 + tc + 4];
#pragma unroll
            for (int nt = 0; nt < 8; nt++) {
                uint32_t b0 = Ks[nt * 8 + gr][ks * 8 + tc];
                uint32_t b1 = Ks[nt * 8 + gr][ks * 8 + tc + 4];
                mma_tf32(sacc[nt][0], sacc[nt][1], sacc[nt][2], sacc[nt][3],
                         af0, af1, af2, af3, b0, b1);
            }
        }

        float mx0 = m0, mx1 = m1;
#pragma unroll
        for (int nt = 0; nt < 8; nt++) {
            const int c = kc + nt * 8 + 2 * tc;
            if (c     < qr0 - WIN || c     > qr0 + WIN) sacc[nt][0] = -1e30f;
            if (c + 1 < qr0 - WIN || c + 1 > qr0 + WIN) sacc[nt][1] = -1e30f;
            if (c     < qr1 - WIN || c     > qr1 + WIN) sacc[nt][2] = -1e30f;
            if (c + 1 < qr1 - WIN || c + 1 > qr1 + WIN) sacc[nt][3] = -1e30f;
            mx0 = fmaxf(mx0, fmaxf(sacc[nt][0], sacc[nt][1]));
            mx1 = fmaxf(mx1, fmaxf(sacc[nt][2], sacc[nt][3]));
        }
        mx0 = fmaxf(mx0, __shfl_xor_sync(0xffffffffu, mx0, 1));
        mx0 = fmaxf(mx0, __shfl_xor_sync(0xffffffffu, mx0, 2));
        mx1 = fmaxf(mx1, __shfl_xor_sync(0xffffffffu, mx1, 1));
        mx1 = fmaxf(mx1, __shfl_xor_sync(0xffffffffu, mx1, 2));

        const float alpha0 = __expf(m0 - mx0);
        const float alpha1 = __expf(m1 - mx1);

        float ps0 = 0.f, ps1 = 0.f;
        const int prow = wid * 16 + gr;
#pragma unroll
        for (int nt = 0; nt < 8; nt++) {
            float p00 = __expf(sacc[nt][0] - mx0);
            float p01 = __expf(sacc[nt][1] - mx0);
            float p10 = __expf(sacc[nt][2] - mx1);
            float p11 = __expf(sacc[nt][3] - mx1);
            ps0 += p00 + p01;
            ps1 += p10 + p11;
            *(uint2*)&Ps[prow][nt * 8 + 2 * tc]     = make_uint2(f2tf(p00), f2tf(p01));
            *(uint2*)&Ps[prow + 8][nt * 8 + 2 * tc] = make_uint2(f2tf(p10), f2tf(p11));
        }
        ps0 += __shfl_xor_sync(0xffffffffu, ps0, 1);
        ps0 += __shfl_xor_sync(0xffffffffu, ps0, 2);
        ps1 += __shfl_xor_sync(0xffffffffu, ps1, 1);
        ps1 += __shfl_xor_sync(0xffffffffu, ps1, 2);

        l0 = l0 * alpha0 + ps0;  m0 = mx0;
        l1 = l1 * alpha1 + ps1;  m1 = mx1;

#pragma unroll
        for (int nt = 0; nt < 8; nt++) {
            oacc[nt][0] *= alpha0; oacc[nt][1] *= alpha0;
            oacc[nt][2] *= alpha1; oacc[nt][3] *= alpha1;
        }

        __syncwarp();

#pragma unroll
        for (int ks = 0; ks < 8; ks++) {
            uint32_t af0 = Ps[prow][ks * 8 + tc];
            uint32_t af1 = Ps[prow + 8][ks * 8 + tc];
            uint32_t af2 = Ps[prow][ks * 8 + tc + 4];
            uint32_t af3 = Ps[prow + 8][ks * 8 + tc + 4];
#pragma unroll
            for (int nt = 0; nt < 8; nt++) {
                uint32_t b0 = Vs[ks * 8 + tc][nt * 8 + gr];
                uint32_t b1 = Vs[ks * 8 + tc + 4][nt * 8 + gr];
                mma_tf32(oacc[nt][0], oacc[nt][1], oacc[nt][2], oacc[nt][3],
                         af0, af1, af2, af3, b0, b1);
            }
        }
    }

    const float inv0 = 1.0f / l0;
    const float inv1 = 1.0f / l1;
    const size_t row0g = (size_t)(b * S_LEN) + qr0;
#pragma unroll
    for (int nt = 0; nt < 8; nt++) {
        const int col = h * DHE + nt * 8 + 2 * tc;
        *(float2*)(g_attn + row0g * D_DIM + col) =
            make_float2(oacc[nt][0] * inv0, oacc[nt][1] * inv0);
        *(float2*)(g_attn + (row0g + 8) * D_DIM + col) =
            make_float2(oacc[nt][2] * inv1, oacc[nt][3] * inv1);
    }
}

// ---------------- fused add + LayerNorm (float4) ----------------
__global__ void __launch_bounds__(256) add_ln_kernel(
    const float* __restrict__ A, const float* __restrict__ Bv,
    const float* __restrict__ g, const float* __restrict__ beta,
    float* __restrict__ out)
{
    __shared__ float red[8];
    const int row = blockIdx.x;
    const int t   = threadIdx.x;

    float4 a = *(const float4*)(A  + (size_t)row * D_DIM + t * 4);
    float4 b = *(const float4*)(Bv + (size_t)row * D_DIM + t * 4);
    float4 v = make_float4(a.x + b.x, a.y + b.y, a.z + b.z, a.w + b.w);

    float s = v.x + v.y + v.z + v.w;
#pragma unroll
    for (int o = 16; o; o >>= 1) s += __shfl_xor_sync(0xffffffffu, s, o);
    if ((t & 31) == 0) red[t >> 5] = s;
    __syncthreads();
    float tot = 0.f;
#pragma unroll
    for (int i = 0; i < 8; i++) tot += red[i];
    const float mu = tot * (1.f / (float)D_DIM);
    __syncthreads();

    float dx = v.x - mu, dy = v.y - mu, dz = v.z - mu, dw = v.w - mu;
    float s2 = dx * dx + dy * dy + dz * dz + dw * dw;
#pragma unroll
    for (int o = 16; o; o >>= 1) s2 += __shfl_xor_sync(0xffffffffu, s2, o);
    if ((t & 31) == 0) red[t >> 5] = s2;
    __syncthreads();
    float tot2 = 0.f;
#pragma unroll
    for (int i = 0; i < 8; i++) tot2 += red[i];
    const float inv = rsqrtf(tot2 * (1.f / (float)D_DIM) + 1e-5f);

    float4 gg = *(const float4*)(g    + t * 4);
    float4 bb = *(const float4*)(beta + t * 4);
    float4 o4 = make_float4(dx * inv * gg.x + bb.x, dy * inv * gg.y + bb.y,
                            dz * inv * gg.z + bb.z, dw * inv * gg.w + bb.w);
    *(float4*)(out + (size_t)row * D_DIM + t * 4) = o4;
}

// ---------------- spectral block ----------------
__device__ __forceinline__ float2 cmul(float2 a, float2 b) {
    return make_float2(a.x * b.x - a.y * b.y, a.x * b.y + a.y * b.x);
}

template<int SIGN>
__device__ __forceinline__ void fft2048_r4(float2*& cur, float2*& oth)
{
    int n = 2048, ls = 0;
#pragma unroll
    for (int st = 0; st < 5; st++) {
        const int ss = 1 << ls;
        const float fn = (2.0f * 3.14159265358979f * (float)SIGN) / (float)n;
#pragma unroll
        for (int ii = 0; ii < 2; ii++) {
            const int idx = threadIdx.x + 256 * ii;
            const int p = idx >> ls;
            const int q = idx & (ss - 1);
            float2 x0 = cur[SMAP(idx)];
            float2 x1 = cur[SMAP(idx + 512)];
            float2 x2 = cur[SMAP(idx + 1024)];
            float2 x3 = cur[SMAP(idx + 1536)];
            float sn, cs;
            __sincosf(fn * (float)p, &sn, &cs);
            const float2 wA = make_float2(cs, sn);
            const float2 wB = cmul(wA, wA);
            float2 a0 = make_float2(x0.x + x2.x, x0.y + x2.y);
            float2 a1 = make_float2(x0.x - x2.x, x0.y - x2.y);
            float2 b0 = make_float2(x1.x + x3.x, x1.y + x3.y);
            float2 u  = make_float2(x1.x - x3.x, x1.y - x3.y);
            float2 b1 = make_float2(-(float)SIGN * u.y, (float)SIGN * u.x);
            float2 A1p = cmul(a1, wA);
            float2 A1q = cmul(b1, wA);
            const int ob = q + 4 * ss * p;
            oth[SMAP(ob)]          = make_float2(a0.x + b0.x, a0.y + b0.y);
            float2 d0v = make_float2(a0.x - b0.x, a0.y - b0.y);
            oth[SMAP(ob + 2 * ss)] = cmul(d0v, wB);
            oth[SMAP(ob + ss)]     = make_float2(A1p.x + A1q.x, A1p.y + A1q.y);
            float2 d1v = make_float2(A1p.x - A1q.x, A1p.y - A1q.y);
            oth[SMAP(ob + 3 * ss)] = cmul(d1v, wB);
        }
        __syncthreads();
        float2* t = cur; cur = oth; oth = t;
        n >>= 2; ls += 2;
    }
#pragma unroll
    for (int ii = 0; ii < 4; ii++) {
        const int q = threadIdx.x + 256 * ii;
        float2 a = cur[SMAP(q)];
        float2 b = cur[SMAP(q + 1024)];
        oth[SMAP(q)]        = make_float2(a.x + b.x, a.y + b.y);
        oth[SMAP(q + 1024)] = make_float2(a.x - b.x, a.y - b.y);
    }
    __syncthreads();
    { float2* t = cur; cur = oth; oth = t; }
}

__global__ void __launch_bounds__(256) spectral_kernel(
    const float* __restrict__ x, const float* __restrict__ wr,
    const float* __restrict__ wi, float* __restrict__ xwave)
{
    __shared__ float2 bufA[2176];
    __shared__ float2 bufB[2176];
    const int d0 = blockIdx.x * 2;
    const int b  = blockIdx.y;

    const float* xp = x + (size_t)b * S_LEN * D_DIM + d0;
    for (int s = threadIdx.x; s < 2048; s += 256)
        bufA[SMAP(s)] = *(const float2*)(xp + (size_t)s * D_DIM);
    __syncthreads();

    float2* cur = bufA;
    float2* oth = bufB;
    fft2048_r4<-1>(cur, oth);

    for (int k = threadIdx.x; k < 2048; k += 256) {
        const int km = (2048 - k) & 2047;
        float2 Zk = cur[SMAP(k)];
        float2 Zm = cur[SMAP(km)];
        float2 Av = make_float2(0.5f * (Zk.x + Zm.x), 0.5f * (Zk.y - Zm.y));
        float2 Bc = make_float2(0.5f * (Zk.y + Zm.y), -0.5f * (Zk.x - Zm.x));
        const int   kf  = (k <= 1024) ? k : 2048 - k;
        const float sgn = (k <= 1024) ? 1.f : -1.f;
        float2 wrp = *(const float2*)(wr + (size_t)kf * D_DIM + d0);
        float2 wip = *(const float2*)(wi + (size_t)kf * D_DIM + d0);
        float2 c1 = make_float2(wrp.x, sgn * wip.x);
        float2 c2 = make_float2(wrp.y, sgn * wip.y);
        if (k == 0 || k == 1024) { c1.y = 0.f; c2.y = 0.f; }
        float2 Y1 = cmul(Av, c1);
        float2 Y2 = cmul(Bc, c2);
        oth[SMAP(k)] = make_float2(Y1.x - Y2.y, Y1.y + Y2.x);
    }
    __syncthreads();
    { float2* t = cur; cur = oth; oth = t; }

    fft2048_r4<1>(cur, oth);

    float* dst = xwave + (size_t)b * S_LEN * D_DIM + d0;
    const float invn = 1.0f / 2048.0f;
    for (int s = threadIdx.x; s < 2048; s += 256) {
        float2 r = cur[SMAP(s)];
        *(float2*)(dst + (size_t)s * D_DIM) = make_float2(r.x * invn, r.y * invn);
    }
}

// ---------------- launcher ----------------
extern "C" void kernel_launch(void* const* d_in, const int* in_sizes, int n_in,
                              void* d_out, int out_size)
{
    const float* x     = (const float*)d_in[0];
    const float* in_w  = (const float*)d_in[1];
    const float* in_b  = (const float*)d_in[2];
    const float* out_w = (const float*)d_in[3];
    const float* out_b = (const float*)d_in[4];
    const float* ln1g  = (const float*)d_in[5];
    const float* ln1b  = (const float*)d_in[6];
    const float* wr    = (const float*)d_in[7];
    const float* wi    = (const float*)d_in[8];
    const float* ln2g  = (const float*)d_in[9];
    const float* ln2b  = (const float*)d_in[10];
    float* out = (float*)d_out;

    float *qkv, *attn, *attnout, *xattn, *xwave;
    cudaGetSymbolAddress((void**)&qkv,     g_qkv);
    cudaGetSymbolAddress((void**)&attn,    g_attn);
    cudaGetSymbolAddress((void**)&attnout, g_attnout);
    cudaGetSymbolAddress((void**)&xattn,   g_xattn);
    cudaGetSymbolAddress((void**)&xwave,   g_xwave);

    // spectral path (independent)
    spectral_kernel<<<dim3(D_DIM / 2, B_SZ), 256>>>(x, wr, wi, xwave);

    // QKV projection (fp16 m16n8k16 tensor cores)
    gemm_fp16_db<<<dim3(D3 / 128, NTOK / 128), 256>>>(x, in_w, in_b, qkv,
                                                      NTOK, D3, D_DIM);

    // windowed flash attention (tf32 mma.sync)
    attn_tc_kernel<<<dim3(S_LEN / 64, NH, B_SZ), 128>>>();

    // output projection (fp16)
    gemm_fp16_db<<<dim3(D_DIM / 128, NTOK / 128), 256>>>(attn, out_w, out_b, attnout,
                                                         NTOK, D_DIM, D_DIM);

    // x_attn = LN1(x + attn_out)
    add_ln_kernel<<<NTOK, 256>>>(x, attnout, ln1g, ln1b, xattn);

    // out = LN2(x_attn + x_wave)
    add_ln_kernel<<<NTOK, 256>>>(xattn, xwave, ln2g, ln2b, out);
}

// round 12
// speedup vs baseline: 6.4272x; 1.0926x over previous
#include <cuda_runtime.h>
#include <cuda_fp16.h>
#include <math.h>
#include <stdint.h>

#define S_LEN 2048
#define D_DIM 1024
#define B_SZ  2
#define NH    16
#define DHE   64
#define WIN   128
#define NTOK  (B_SZ * S_LEN)   // 4096
#define D3    (3 * D_DIM)      // 3072

#define SMAP(i) ((i) + ((i) >> 4))

// ---------------- scratch ----------------
__device__ float  g_qkv[(size_t)NTOK * D3];
__device__ __half g_attn_h[(size_t)NTOK * D_DIM];   // attention out, half (A of out-proj)
__device__ float  g_attnout[(size_t)NTOK * D_DIM];
__device__ float  g_xattn[(size_t)NTOK * D_DIM];
__device__ float  g_xwave[(size_t)NTOK * D_DIM];
__device__ __half g_xh[(size_t)NTOK * D_DIM];       // x in half (A of QKV)
__device__ __half g_wh_in[(size_t)D3 * D_DIM];      // in_proj_w half
__device__ __half g_wh_out[(size_t)D_DIM * D_DIM];  // out_proj_w half

// ---------------- helpers ----------------
__device__ __forceinline__ uint32_t smem_u32(const void* p) {
    uint32_t a;
    asm("{ .reg .u64 t; cvta.to.shared.u64 t, %1; cvt.u32.u64 %0, t; }" : "=r"(a) : "l"(p));
    return a;
}
__device__ __forceinline__ void cpasync16(uint32_t dst, const void* src) {
    asm volatile("cp.async.ca.shared.global [%0], [%1], 16;" :: "r"(dst), "l"(src));
}
#define CP_COMMIT() asm volatile("cp.async.commit_group;" ::: "memory")
#define CP_WAIT1()  asm volatile("cp.async.wait_group 1;" ::: "memory")

__device__ __forceinline__ uint32_t f22h2(float a, float b) {
    __half2 h = __floats2half2_rn(a, b);
    return *(uint32_t*)&h;
}
__device__ __forceinline__ uint32_t f2tf(float f) {
    uint32_t u;
    asm("cvt.rna.tf32.f32 %0, %1;" : "=r"(u) : "f"(f));
    return u;
}
__device__ __forceinline__ void mma_fp16(
    float& c0, float& c1, float& c2, float& c3,
    uint32_t a0, uint32_t a1, uint32_t a2, uint32_t a3,
    uint32_t b0, uint32_t b1)
{
    asm volatile(
        "mma.sync.aligned.m16n8k16.row.col.f32.f16.f16.f32 "
        "{%0,%1,%2,%3}, {%4,%5,%6,%7}, {%8,%9}, {%0,%1,%2,%3};\n"
        : "+f"(c0), "+f"(c1), "+f"(c2), "+f"(c3)
        : "r"(a0), "r"(a1), "r"(a2), "r"(a3), "r"(b0), "r"(b1));
}
__device__ __forceinline__ void mma_tf32(
    float& c0, float& c1, float& c2, float& c3,
    uint32_t a0, uint32_t a1, uint32_t a2, uint32_t a3,
    uint32_t b0, uint32_t b1)
{
    asm volatile(
        "mma.sync.aligned.m16n8k8.row.col.f32.tf32.tf32.f32 "
        "{%0,%1,%2,%3}, {%4,%5,%6,%7}, {%8,%9}, {%0,%1,%2,%3};\n"
        : "+f"(c0), "+f"(c1), "+f"(c2), "+f"(c3)
        : "r"(a0), "r"(a1), "r"(a2), "r"(a3), "r"(b0), "r"(b1));
}

// ---------------- f32 -> f16 convert (n % 4 == 0) ----------------
__global__ void __launch_bounds__(256) conv_f2h(const float* __restrict__ src,
                                               __half* __restrict__ dst, int n)
{
    int i = (blockIdx.x * 256 + threadIdx.x) * 4;
    if (i < n) {
        float4 v = *(const float4*)(src + i);
        *(uint2*)(dst + i) = make_uint2(f22h2(v.x, v.y), f22h2(v.z, v.w));
    }
}

// ---------------- fp16 GEMM, 3-stage cp.async pipeline ----------------
// C[M,N] = A[M,K] @ W[N,K]^T + bias.  A, W are half in GMEM.
// BM=BN=128, BK=32 halves (64 B/row), rows padded to LDP u32 (80 B).
#define LDP 20
#define STG 3
__global__ void __launch_bounds__(256, 2) gemm_fp16_pipe(
    const __half* __restrict__ A, const __half* __restrict__ W,
    const float* __restrict__ bias, float* __restrict__ C,
    int M, int N, int K)
{
    __shared__ uint32_t As2[STG][128][LDP];
    __shared__ uint32_t Ws2[STG][128][LDP];

    const int row0 = blockIdx.y * 128;
    const int col0 = blockIdx.x * 128;
    const int t    = threadIdx.x;
    const int warp = t >> 5;
    const int lane = t & 31;
    const int gr   = lane >> 2;
    const int tc   = lane & 3;
    const int m0w  = (warp >> 2) * 64;
    const int n0w  = (warp & 3) * 32;

    // 512 16B-chunks per matrix per stage; thread handles chunks t and t+256.
    // chunk c -> row = c>>2, col16 = c&3 (16B units = 8 halves)
    const int r0c = t >> 2;          const int c0c = t & 3;
    const int r1c = (t + 256) >> 2;  const int c1c = (t + 256) & 3;

    const __half* Ar0 = A + (size_t)(row0 + r0c) * K + c0c * 8;
    const __half* Ar1 = A + (size_t)(row0 + r1c) * K + c1c * 8;
    const __half* Wr0 = W + (size_t)(col0 + r0c) * K + c0c * 8;
    const __half* Wr1 = W + (size_t)(col0 + r1c) * K + c1c * 8;

    float acc[4][4][4];
#pragma unroll
    for (int mi = 0; mi < 4; mi++)
#pragma unroll
        for (int ni = 0; ni < 4; ni++)
#pragma unroll
            for (int r = 0; r < 4; r++) acc[mi][ni][r] = 0.f;

    const int ntiles = K >> 5;   // BK = 32 halves

    // prologue: stages 0, 1 in flight
#pragma unroll
    for (int s = 0; s < 2; s++) {
        const int k0 = s << 5;
        cpasync16(smem_u32(&As2[s][r0c][c0c * 4]), Ar0 + k0);
        cpasync16(smem_u32(&As2[s][r1c][c1c * 4]), Ar1 + k0);
        cpasync16(smem_u32(&Ws2[s][r0c][c0c * 4]), Wr0 + k0);
        cpasync16(smem_u32(&Ws2[s][r1c][c1c * 4]), Wr1 + k0);
        CP_COMMIT();
    }

    int cb = 0, nst = 2;
    for (int kt = 0; kt < ntiles; kt++) {
        CP_WAIT1();
        __syncthreads();

        if (kt + 2 < ntiles) {
            const int k0 = (kt + 2) << 5;
            cpasync16(smem_u32(&As2[nst][r0c][c0c * 4]), Ar0 + k0);
            cpasync16(smem_u32(&As2[nst][r1c][c1c * 4]), Ar1 + k0);
            cpasync16(smem_u32(&Ws2[nst][r0c][c0c * 4]), Wr0 + k0);
            cpasync16(smem_u32(&Ws2[nst][r1c][c1c * 4]), Wr1 + k0);
        }
        CP_COMMIT();

#pragma unroll
        for (int kk = 0; kk < 2; kk++) {       // two k16 steps
            uint32_t af[4][4];
#pragma unroll
            for (int mi = 0; mi < 4; mi++) {
                const int br = m0w + mi * 16;
                af[mi][0] = As2[cb][br + gr][kk * 8 + tc];
                af[mi][1] = As2[cb][br + gr + 8][kk * 8 + tc];
                af[mi][2] = As2[cb][br + gr][kk * 8 + tc + 4];
                af[mi][3] = As2[cb][br + gr + 8][kk * 8 + tc + 4];
            }
            uint32_t bf[4][2];
#pragma unroll
            for (int ni = 0; ni < 4; ni++) {
                const int bn = n0w + ni * 8 + gr;
                bf[ni][0] = Ws2[cb][bn][kk * 8 + tc];
                bf[ni][1] = Ws2[cb][bn][kk * 8 + tc + 4];
            }
#pragma unroll
            for (int mi = 0; mi < 4; mi++)
#pragma unroll
                for (int ni = 0; ni < 4; ni++)
                    mma_fp16(acc[mi][ni][0], acc[mi][ni][1], acc[mi][ni][2], acc[mi][ni][3],
                             af[mi][0], af[mi][1], af[mi][2], af[mi][3],
                             bf[ni][0], bf[ni][1]);
        }

        cb  = (cb  + 1) % STG;
        nst = (nst + 1) % STG;
    }

    // epilogue (C frag: rows gr/gr+8, cols 2tc,2tc+1)
#pragma unroll
    for (int mi = 0; mi < 4; mi++) {
#pragma unroll
        for (int ni = 0; ni < 4; ni++) {
            const int r = row0 + m0w + mi * 16 + gr;
            const int c = col0 + n0w + ni * 8 + tc * 2;
            float2 bs = *(const float2*)(bias + c);
            float2 v0 = make_float2(acc[mi][ni][0] + bs.x, acc[mi][ni][1] + bs.y);
            float2 v1 = make_float2(acc[mi][ni][2] + bs.x, acc[mi][ni][3] + bs.y);
            *(float2*)(C + (size_t)r * N + c)       = v0;
            *(float2*)(C + (size_t)(r + 8) * N + c) = v1;
        }
    }
}

// ---------------- tensor-core windowed flash attention (tf32) ----------------
// Epilogue writes g_attn_h (half) directly.
#define QPAD 68
#define VPAD 72
__global__ void __launch_bounds__(128) attn_tc_kernel()
{
    __shared__ uint32_t Qs[64][QPAD];
    __shared__ uint32_t Ks[64][QPAD];
    __shared__ uint32_t Vs[64][VPAD];
    __shared__ uint32_t Ps[64][QPAD];

    const int q0  = blockIdx.x * 64;
    const int h   = blockIdx.y;
    const int b   = blockIdx.z;
    const int t   = threadIdx.x;
    const int wid = t >> 5;
    const int lane = t & 31;
    const int gr  = lane >> 2;
    const int tc  = lane & 3;

#pragma unroll
    for (int i = 0; i < 8; i++) {
        int lin = t + 128 * i;
        int row = lin >> 4;
        int c4  = (lin & 15) * 4;
        const float* src = g_qkv + (size_t)(b * S_LEN + q0 + row) * D3 + h * DHE + c4;
        float4 v = *(const float4*)src;
        *(uint4*)&Qs[row][c4] = make_uint4(f2tf(v.x * 0.125f), f2tf(v.y * 0.125f),
                                           f2tf(v.z * 0.125f), f2tf(v.w * 0.125f));
    }

    const int qr0 = q0 + wid * 16 + gr;
    const int qr1 = qr0 + 8;

    float m0 = -1e30f, m1 = -1e30f, l0 = 0.f, l1 = 0.f;
    float oacc[8][4];
#pragma unroll
    for (int nt = 0; nt < 8; nt++)
#pragma unroll
        for (int r = 0; r < 4; r++) oacc[nt][r] = 0.f;

    const int kstart = (q0 - WIN > 0) ? (q0 - WIN) : 0;
    const int kend   = (q0 + 64 + WIN < S_LEN) ? (q0 + 64 + WIN) : S_LEN;

    for (int kc = kstart; kc < kend; kc += 64) {
        __syncthreads();
#pragma unroll
        for (int i = 0; i < 8; i++) {
            int lin = t + 128 * i;
            int row = lin >> 4;
            int c4  = (lin & 15) * 4;
            const float* kp = g_qkv + (size_t)(b * S_LEN + kc + row) * D3 + D_DIM + h * DHE + c4;
            float4 kv = *(const float4*)kp;
            float4 vv = *(const float4*)(kp + D_DIM);
            *(uint4*)&Ks[row][c4] = make_uint4(f2tf(kv.x), f2tf(kv.y), f2tf(kv.z), f2tf(kv.w));
            *(uint4*)&Vs[row][c4] = make_uint4(f2tf(vv.x), f2tf(vv.y), f2tf(vv.z), f2tf(vv.w));
        }
        __syncthreads();

        float sacc[8][4];
#pragma unroll
        for (int nt = 0; nt < 8; nt++)
#pragma unroll
            for (int r = 0; r < 4; r++) sacc[nt][r] = 0.f;

#pragma unroll
        for (int ks = 0; ks < 8; ks++) {
            const int qrow = wid * 16 + gr;
            uint32_t af0 = Qs[qrow][ks * 8 + tc];
            uint32_t af1 = Qs[qrow + 8][ks * 8 + tc];
            uint32_t af2 = Qs[qrow][ks * 8 + tc + 4];
            uint32_t af3 = Qs[qrow + 8][ks * 8 + tc + 4];
#pragma unroll
            for (int nt = 0; nt < 8; nt++) {
                uint32_t b0 = Ks[nt * 8 + gr][ks * 8 + tc];
                uint32_t b1 = Ks[nt * 8 + gr][ks * 8 + tc + 4];
                mma_tf32(sacc[nt][0], sacc[nt][1], sacc[nt][2], sacc[nt][3],
                         af0, af1, af2, af3, b0, b1);
            }
        }

        float mx0 = m0, mx1 = m1;
#pragma unroll
        for (int nt = 0; nt < 8; nt++) {
            const int c = kc + nt * 8 + 2 * tc;
            if (c     < qr0 - WIN || c     > qr0 + WIN) sacc[nt][0] = -1e30f;
            if (c + 1 < qr0 - WIN || c + 1 > qr0 + WIN) sacc[nt][1] = -1e30f;
            if (c     < qr1 - WIN || c     > qr1 + WIN) sacc[nt][2] = -1e30f;
            if (c + 1 < qr1 - WIN || c + 1 > qr1 + WIN) sacc[nt][3] = -1e30f;
            mx0 = fmaxf(mx0, fmaxf(sacc[nt][0], sacc[nt][1]));
            mx1 = fmaxf(mx1, fmaxf(sacc[nt][2], sacc[nt][3]));
        }
        mx0 = fmaxf(mx0, __shfl_xor_sync(0xffffffffu, mx0, 1));
        mx0 = fmaxf(mx0, __shfl_xor_sync(0xffffffffu, mx0, 2));
        mx1 = fmaxf(mx1, __shfl_xor_sync(0xffffffffu, mx1, 1));
        mx1 = fmaxf(mx1, __shfl_xor_sync(0xffffffffu, mx1, 2));

        const float alpha0 = __expf(m0 - mx0);
        const float alpha1 = __expf(m1 - mx1);

        float ps0 = 0.f, ps1 = 0.f;
        const int prow = wid * 16 + gr;
#pragma unroll
        for (int nt = 0; nt < 8; nt++) {
            float p00 = __expf(sacc[nt][0] - mx0);
            float p01 = __expf(sacc[nt][1] - mx0);
            float p10 = __expf(sacc[nt][2] - mx1);
            float p11 = __expf(sacc[nt][3] - mx1);
            ps0 += p00 + p01;
            ps1 += p10 + p11;
            *(uint2*)&Ps[prow][nt * 8 + 2 * tc]     = make_uint2(f2tf(p00), f2tf(p01));
            *(uint2*)&Ps[prow + 8][nt * 8 + 2 * tc] = make_uint2(f2tf(p10), f2tf(p11));
        }
        ps0 += __shfl_xor_sync(0xffffffffu, ps0, 1);
        ps0 += __shfl_xor_sync(0xffffffffu, ps0, 2);
        ps1 += __shfl_xor_sync(0xffffffffu, ps1, 1);
        ps1 += __shfl_xor_sync(0xffffffffu, ps1, 2);

        l0 = l0 * alpha0 + ps0;  m0 = mx0;
        l1 = l1 * alpha1 + ps1;  m1 = mx1;

#pragma unroll
        for (int nt = 0; nt < 8; nt++) {
            oacc[nt][0] *= alpha0; oacc[nt][1] *= alpha0;
            oacc[nt][2] *= alpha1; oacc[nt][3] *= alpha1;
        }

        __syncwarp();

#pragma unroll
        for (int ks = 0; ks < 8; ks++) {
            uint32_t af0 = Ps[prow][ks * 8 + tc];
            uint32_t af1 = Ps[prow + 8][ks * 8 + tc];
            uint32_t af2 = Ps[prow][ks * 8 + tc + 4];
            uint32_t af3 = Ps[prow + 8][ks * 8 + tc + 4];
#pragma unroll
            for (int nt = 0; nt < 8; nt++) {
                uint32_t b0 = Vs[ks * 8 + tc][nt * 8 + gr];
                uint32_t b1 = Vs[ks * 8 + tc + 4][nt * 8 + gr];
                mma_tf32(oacc[nt][0], oacc[nt][1], oacc[nt][2], oacc[nt][3],
                         af0, af1, af2, af3, b0, b1);
            }
        }
    }

    // epilogue: divide by l, write half to g_attn_h
    const float inv0 = 1.0f / l0;
    const float inv1 = 1.0f / l1;
    const size_t row0g = (size_t)(b * S_LEN) + qr0;
#pragma unroll
    for (int nt = 0; nt < 8; nt++) {
        const int col = h * DHE + nt * 8 + 2 * tc;
        *(uint32_t*)(g_attn_h + row0g * D_DIM + col) =
            f22h2(oacc[nt][0] * inv0, oacc[nt][1] * inv0);
        *(uint32_t*)(g_attn_h + (row0g + 8) * D_DIM + col) =
            f22h2(oacc[nt][2] * inv1, oacc[nt][3] * inv1);
    }
}

// ---------------- fused add + LayerNorm (float4) ----------------
__global__ void __launch_bounds__(256) add_ln_kernel(
    const float* __restrict__ A, const float* __restrict__ Bv,
    const float* __restrict__ g, const float* __restrict__ beta,
    float* __restrict__ out)
{
    __shared__ float red[8];
    const int row = blockIdx.x;
    const int t   = threadIdx.x;

    float4 a = *(const float4*)(A  + (size_t)row * D_DIM + t * 4);
    float4 b = *(const float4*)(Bv + (size_t)row * D_DIM + t * 4);
    float4 v = make_float4(a.x + b.x, a.y + b.y, a.z + b.z, a.w + b.w);

    float s = v.x + v.y + v.z + v.w;
#pragma unroll
    for (int o = 16; o; o >>= 1) s += __shfl_xor_sync(0xffffffffu, s, o);
    if ((t & 31) == 0) red[t >> 5] = s;
    __syncthreads();
    float tot = 0.f;
#pragma unroll
    for (int i = 0; i < 8; i++) tot += red[i];
    const float mu = tot * (1.f / (float)D_DIM);
    __syncthreads();

    float dx = v.x - mu, dy = v.y - mu, dz = v.z - mu, dw = v.w - mu;
    float s2 = dx * dx + dy * dy + dz * dz + dw * dw;
#pragma unroll
    for (int o = 16; o; o >>= 1) s2 += __shfl_xor_sync(0xffffffffu, s2, o);
    if ((t & 31) == 0) red[t >> 5] = s2;
    __syncthreads();
    float tot2 = 0.f;
#pragma unroll
    for (int i = 0; i < 8; i++) tot2 += red[i];
    const float inv = rsqrtf(tot2 * (1.f / (float)D_DIM) + 1e-5f);

    float4 gg = *(const float4*)(g    + t * 4);
    float4 bb = *(const float4*)(beta + t * 4);
    float4 o4 = make_float4(dx * inv * gg.x + bb.x, dy * inv * gg.y + bb.y,
                            dz * inv * gg.z + bb.z, dw * inv * gg.w + bb.w);
    *(float4*)(out + (size_t)row * D_DIM + t * 4) = o4;
}

// ---------------- spectral block ----------------
__device__ __forceinline__ float2 cmul(float2 a, float2 b) {
    return make_float2(a.x * b.x - a.y * b.y, a.x * b.y + a.y * b.x);
}

template<int SIGN>
__device__ __forceinline__ void fft2048_r4(float2*& cur, float2*& oth)
{
    int n = 2048, ls = 0;
#pragma unroll
    for (int st = 0; st < 5; st++) {
        const int ss = 1 << ls;
        const float fn = (2.0f * 3.14159265358979f * (float)SIGN) / (float)n;
#pragma unroll
        for (int ii = 0; ii < 2; ii++) {
            const int idx = threadIdx.x + 256 * ii;
            const int p = idx >> ls;
            const int q = idx & (ss - 1);
            float2 x0 = cur[SMAP(idx)];
            float2 x1 = cur[SMAP(idx + 512)];
            float2 x2 = cur[SMAP(idx + 1024)];
            float2 x3 = cur[SMAP(idx + 1536)];
            float sn, cs;
            __sincosf(fn * (float)p, &sn, &cs);
            const float2 wA = make_float2(cs, sn);
            const float2 wB = cmul(wA, wA);
            float2 a0 = make_float2(x0.x + x2.x, x0.y + x2.y);
            float2 a1 = make_float2(x0.x - x2.x, x0.y - x2.y);
            float2 b0 = make_float2(x1.x + x3.x, x1.y + x3.y);
            float2 u  = make_float2(x1.x - x3.x, x1.y - x3.y);
            float2 b1 = make_float2(-(float)SIGN * u.y, (float)SIGN * u.x);
            float2 A1p = cmul(a1, wA);
            float2 A1q = cmul(b1, wA);
            const int ob = q + 4 * ss * p;
            oth[SMAP(ob)]          = make_float2(a0.x + b0.x, a0.y + b0.y);
            float2 d0v = make_float2(a0.x - b0.x, a0.y - b0.y);
            oth[SMAP(ob + 2 * ss)] = cmul(d0v, wB);
            oth[SMAP(ob + ss)]     = make_float2(A1p.x + A1q.x, A1p.y + A1q.y);
            float2 d1v = make_float2(A1p.x - A1q.x, A1p.y - A1q.y);
            oth[SMAP(ob + 3 * ss)] = cmul(d1v, wB);
        }
        __syncthreads();
        float2* t = cur; cur = oth; oth = t;
        n >>= 2; ls += 2;
    }
#pragma unroll
    for (int ii = 0; ii < 4; ii++) {
        const int q = threadIdx.x + 256 * ii;
        float2 a = cur[SMAP(q)];
        float2 b = cur[SMAP(q + 1024)];
        oth[SMAP(q)]        = make_float2(a.x + b.x, a.y + b.y);
        oth[SMAP(q + 1024)] = make_float2(a.x - b.x, a.y - b.y);
    }
    __syncthreads();
    { float2* t = cur; cur = oth; oth = t; }
}

__global__ void __launch_bounds__(256) spectral_kernel(
    const float* __restrict__ x, const float* __restrict__ wr,
    const float* __restrict__ wi, float* __restrict__ xwave)
{
    __shared__ float2 bufA[2176];
    __shared__ float2 bufB[2176];
    const int d0 = blockIdx.x * 2;
    const int b  = blockIdx.y;

    const float* xp = x + (size_t)b * S_LEN * D_DIM + d0;
    for (int s = threadIdx.x; s < 2048; s += 256)
        bufA[SMAP(s)] = *(const float2*)(xp + (size_t)s * D_DIM);
    __syncthreads();

    float2* cur = bufA;
    float2* oth = bufB;
    fft2048_r4<-1>(cur, oth);

    for (int k = threadIdx.x; k < 2048; k += 256) {
        const int km = (2048 - k) & 2047;
        float2 Zk = cur[SMAP(k)];
        float2 Zm = cur[SMAP(km)];
        float2 Av = make_float2(0.5f * (Zk.x + Zm.x), 0.5f * (Zk.y - Zm.y));
        float2 Bc = make_float2(0.5f * (Zk.y + Zm.y), -0.5f * (Zk.x - Zm.x));
        const int   kf  = (k <= 1024) ? k : 2048 - k;
        const float sgn = (k <= 1024) ? 1.f : -1.f;
        float2 wrp = *(const float2*)(wr + (size_t)kf * D_DIM + d0);
        float2 wip = *(const float2*)(wi + (size_t)kf * D_DIM + d0);
        float2 c1 = make_float2(wrp.x, sgn * wip.x);
        float2 c2 = make_float2(wrp.y, sgn * wip.y);
        if (k == 0 || k == 1024) { c1.y = 0.f; c2.y = 0.f; }
        float2 Y1 = cmul(Av, c1);
        float2 Y2 = cmul(Bc, c2);
        oth[SMAP(k)] = make_float2(Y1.x - Y2.y, Y1.y + Y2.x);
    }
    __syncthreads();
    { float2* t = cur; cur = oth; oth = t; }

    fft2048_r4<1>(cur, oth);

    float* dst = xwave + (size_t)b * S_LEN * D_DIM + d0;
    const float invn = 1.0f / 2048.0f;
    for (int s = threadIdx.x; s < 2048; s += 256) {
        float2 r = cur[SMAP(s)];
        *(float2*)(dst + (size_t)s * D_DIM) = make_float2(r.x * invn, r.y * invn);
    }
}

// ---------------- launcher ----------------
extern "C" void kernel_launch(void* const* d_in, const int* in_sizes, int n_in,
                              void* d_out, int out_size)
{
    const float* x     = (const float*)d_in[0];
    const float* in_w  = (const float*)d_in[1];
    const float* in_b  = (const float*)d_in[2];
    const float* out_w = (const float*)d_in[3];
    const float* out_b = (const float*)d_in[4];
    const float* ln1g  = (const float*)d_in[5];
    const float* ln1b  = (const float*)d_in[6];
    const float* wr    = (const float*)d_in[7];
    const float* wi    = (const float*)d_in[8];
    const float* ln2g  = (const float*)d_in[9];
    const float* ln2b  = (const float*)d_in[10];
    float* out = (float*)d_out;

    float *qkv, *attnout, *xattn, *xwave;
    __half *xh, *wh_in, *wh_out, *attn_h;
    cudaGetSymbolAddress((void**)&qkv,     g_qkv);
    cudaGetSymbolAddress((void**)&attnout, g_attnout);
    cudaGetSymbolAddress((void**)&xattn,   g_xattn);
    cudaGetSymbolAddress((void**)&xwave,   g_xwave);
    cudaGetSymbolAddress((void**)&xh,      g_xh);
    cudaGetSymbolAddress((void**)&wh_in,   g_wh_in);
    cudaGetSymbolAddress((void**)&wh_out,  g_wh_out);
    cudaGetSymbolAddress((void**)&attn_h,  g_attn_h);

    // converts (bandwidth-bound, tiny)
    conv_f2h<<<(NTOK * D_DIM / 4 + 255) / 256, 256>>>(x, xh, NTOK * D_DIM);
    conv_f2h<<<(D3 * D_DIM / 4 + 255) / 256, 256>>>(in_w, wh_in, D3 * D_DIM);
    conv_f2h<<<(D_DIM * D_DIM / 4 + 255) / 256, 256>>>(out_w, wh_out, D_DIM * D_DIM);

    // spectral path (independent)
    spectral_kernel<<<dim3(D_DIM / 2, B_SZ), 256>>>(x, wr, wi, xwave);

    // QKV projection (fp16, cp.async pipeline)
    gemm_fp16_pipe<<<dim3(D3 / 128, NTOK / 128), 256>>>(xh, wh_in, in_b, qkv,
                                                        NTOK, D3, D_DIM);

    // windowed flash attention (tf32 mma.sync; writes half attn)
    attn_tc_kernel<<<dim3(S_LEN / 64, NH, B_SZ), 128>>>();

    // output projection (fp16)
    gemm_fp16_pipe<<<dim3(D_DIM / 128, NTOK / 128), 256>>>(attn_h, wh_out, out_b, attnout,
                                                           NTOK, D_DIM, D_DIM);

    // x_attn = LN1(x + attn_out)
    add_ln_kernel<<<NTOK, 256>>>(x, attnout, ln1g, ln1b, xattn);

    // out = LN2(x_attn + x_wave)
    add_ln_kernel<<<NTOK, 256>>>(xattn, xwave, ln2g, ln2b, out);
}

// round 13
// speedup vs baseline: 6.6558x; 1.0356x over previous
#include <cuda_runtime.h>
#include <cuda_fp16.h>
#include <math.h>
#include <stdint.h>

#define S_LEN 2048
#define D_DIM 1024
#define B_SZ  2
#define NH    16
#define DHE   64
#define WIN   128
#define NTOK  (B_SZ * S_LEN)   // 4096
#define D3    (3 * D_DIM)      // 3072

#define SMAP(i) ((i) + ((i) >> 4))

// ---------------- scratch ----------------
__device__ float  g_qkv[(size_t)NTOK * D3];
__device__ __half g_attn_h[(size_t)NTOK * D_DIM];
__device__ float  g_attnout[(size_t)NTOK * D_DIM];
__device__ float  g_xwave[(size_t)NTOK * D_DIM];
__device__ __half g_xh[(size_t)NTOK * D_DIM];
__device__ __half g_wh_in[(size_t)D3 * D_DIM];
__device__ __half g_wh_out[(size_t)D_DIM * D_DIM];

// ---------------- helpers ----------------
__device__ __forceinline__ uint32_t smem_u32(const void* p) {
    uint32_t a;
    asm("{ .reg .u64 t; cvta.to.shared.u64 t, %1; cvt.u32.u64 %0, t; }" : "=r"(a) : "l"(p));
    return a;
}
__device__ __forceinline__ void cpasync16(uint32_t dst, const void* src) {
    asm volatile("cp.async.ca.shared.global [%0], [%1], 16;" :: "r"(dst), "l"(src));
}
#define CP_COMMIT() asm volatile("cp.async.commit_group;" ::: "memory")
#define CP_WAIT1()  asm volatile("cp.async.wait_group 1;" ::: "memory")

__device__ __forceinline__ uint32_t f22h2(float a, float b) {
    __half2 h = __floats2half2_rn(a, b);
    return *(uint32_t*)&h;
}
__device__ __forceinline__ uint32_t f2tf(float f) {
    uint32_t u;
    asm("cvt.rna.tf32.f32 %0, %1;" : "=r"(u) : "f"(f));
    return u;
}
__device__ __forceinline__ void mma_fp16(
    float& c0, float& c1, float& c2, float& c3,
    uint32_t a0, uint32_t a1, uint32_t a2, uint32_t a3,
    uint32_t b0, uint32_t b1)
{
    asm volatile(
        "mma.sync.aligned.m16n8k16.row.col.f32.f16.f16.f32 "
        "{%0,%1,%2,%3}, {%4,%5,%6,%7}, {%8,%9}, {%0,%1,%2,%3};\n"
        : "+f"(c0), "+f"(c1), "+f"(c2), "+f"(c3)
        : "r"(a0), "r"(a1), "r"(a2), "r"(a3), "r"(b0), "r"(b1));
}
__device__ __forceinline__ void mma_tf32(
    float& c0, float& c1, float& c2, float& c3,
    uint32_t a0, uint32_t a1, uint32_t a2, uint32_t a3,
    uint32_t b0, uint32_t b1)
{
    asm volatile(
        "mma.sync.aligned.m16n8k8.row.col.f32.tf32.tf32.f32 "
        "{%0,%1,%2,%3}, {%4,%5,%6,%7}, {%8,%9}, {%0,%1,%2,%3};\n"
        : "+f"(c0), "+f"(c1), "+f"(c2), "+f"(c3)
        : "r"(a0), "r"(a1), "r"(a2), "r"(a3), "r"(b0), "r"(b1));
}

// ---------------- f32 -> f16 convert ----------------
__global__ void __launch_bounds__(256) conv_f2h(const float* __restrict__ src,
                                               __half* __restrict__ dst, int n)
{
    int i = (blockIdx.x * 256 + threadIdx.x) * 4;
    if (i < n) {
        float4 v = *(const float4*)(src + i);
        *(uint2*)(dst + i) = make_uint2(f22h2(v.x, v.y), f22h2(v.z, v.w));
    }
}

// ---------------- fp16 GEMM, 3-stage cp.async pipeline (unchanged) ----------------
#define LDP 20
#define STG 3
__global__ void __launch_bounds__(256, 2) gemm_fp16_pipe(
    const __half* __restrict__ A, const __half* __restrict__ W,
    const float* __restrict__ bias, float* __restrict__ C,
    int M, int N, int K)
{
    __shared__ uint32_t As2[STG][128][LDP];
    __shared__ uint32_t Ws2[STG][128][LDP];

    const int row0 = blockIdx.y * 128;
    const int col0 = blockIdx.x * 128;
    const int t    = threadIdx.x;
    const int warp = t >> 5;
    const int lane = t & 31;
    const int gr   = lane >> 2;
    const int tc   = lane & 3;
    const int m0w  = (warp >> 2) * 64;
    const int n0w  = (warp & 3) * 32;

    const int r0c = t >> 2;          const int c0c = t & 3;
    const int r1c = (t + 256) >> 2;  const int c1c = (t + 256) & 3;

    const __half* Ar0 = A + (size_t)(row0 + r0c) * K + c0c * 8;
    const __half* Ar1 = A + (size_t)(row0 + r1c) * K + c1c * 8;
    const __half* Wr0 = W + (size_t)(col0 + r0c) * K + c0c * 8;
    const __half* Wr1 = W + (size_t)(col0 + r1c) * K + c1c * 8;

    float acc[4][4][4];
#pragma unroll
    for (int mi = 0; mi < 4; mi++)
#pragma unroll
        for (int ni = 0; ni < 4; ni++)
#pragma unroll
            for (int r = 0; r < 4; r++) acc[mi][ni][r] = 0.f;

    const int ntiles = K >> 5;

#pragma unroll
    for (int s = 0; s < 2; s++) {
        const int k0 = s << 5;
        cpasync16(smem_u32(&As2[s][r0c][c0c * 4]), Ar0 + k0);
        cpasync16(smem_u32(&As2[s][r1c][c1c * 4]), Ar1 + k0);
        cpasync16(smem_u32(&Ws2[s][r0c][c0c * 4]), Wr0 + k0);
        cpasync16(smem_u32(&Ws2[s][r1c][c1c * 4]), Wr1 + k0);
        CP_COMMIT();
    }

    int cb = 0, nst = 2;
    for (int kt = 0; kt < ntiles; kt++) {
        CP_WAIT1();
        __syncthreads();

        if (kt + 2 < ntiles) {
            const int k0 = (kt + 2) << 5;
            cpasync16(smem_u32(&As2[nst][r0c][c0c * 4]), Ar0 + k0);
            cpasync16(smem_u32(&As2[nst][r1c][c1c * 4]), Ar1 + k0);
            cpasync16(smem_u32(&Ws2[nst][r0c][c0c * 4]), Wr0 + k0);
            cpasync16(smem_u32(&Ws2[nst][r1c][c1c * 4]), Wr1 + k0);
        }
        CP_COMMIT();

#pragma unroll
        for (int kk = 0; kk < 2; kk++) {
            uint32_t af[4][4];
#pragma unroll
            for (int mi = 0; mi < 4; mi++) {
                const int br = m0w + mi * 16;
                af[mi][0] = As2[cb][br + gr][kk * 8 + tc];
                af[mi][1] = As2[cb][br + gr + 8][kk * 8 + tc];
                af[mi][2] = As2[cb][br + gr][kk * 8 + tc + 4];
                af[mi][3] = As2[cb][br + gr + 8][kk * 8 + tc + 4];
            }
            uint32_t bf[4][2];
#pragma unroll
            for (int ni = 0; ni < 4; ni++) {
                const int bn = n0w + ni * 8 + gr;
                bf[ni][0] = Ws2[cb][bn][kk * 8 + tc];
                bf[ni][1] = Ws2[cb][bn][kk * 8 + tc + 4];
            }
#pragma unroll
            for (int mi = 0; mi < 4; mi++)
#pragma unroll
                for (int ni = 0; ni < 4; ni++)
                    mma_fp16(acc[mi][ni][0], acc[mi][ni][1], acc[mi][ni][2], acc[mi][ni][3],
                             af[mi][0], af[mi][1], af[mi][2], af[mi][3],
                             bf[ni][0], bf[ni][1]);
        }

        cb  = (cb  + 1) % STG;
        nst = (nst + 1) % STG;
    }

#pragma unroll
    for (int mi = 0; mi < 4; mi++) {
#pragma unroll
        for (int ni = 0; ni < 4; ni++) {
            const int r = row0 + m0w + mi * 16 + gr;
            const int c = col0 + n0w + ni * 8 + tc * 2;
            float2 bs = *(const float2*)(bias + c);
            float2 v0 = make_float2(acc[mi][ni][0] + bs.x, acc[mi][ni][1] + bs.y);
            float2 v1 = make_float2(acc[mi][ni][2] + bs.x, acc[mi][ni][3] + bs.y);
            *(float2*)(C + (size_t)r * N + c)       = v0;
            *(float2*)(C + (size_t)(r + 8) * N + c) = v1;
        }
    }
}

// ---------------- tensor-core windowed flash attention (tf32, unchanged) ----------------
#define QPAD 68
#define VPAD 72
__global__ void __launch_bounds__(128) attn_tc_kernel()
{
    __shared__ uint32_t Qs[64][QPAD];
    __shared__ uint32_t Ks[64][QPAD];
    __shared__ uint32_t Vs[64][VPAD];
    __shared__ uint32_t Ps[64][QPAD];

    const int q0  = blockIdx.x * 64;
    const int h   = blockIdx.y;
    const int b   = blockIdx.z;
    const int t   = threadIdx.x;
    const int wid = t >> 5;
    const int lane = t & 31;
    const int gr  = lane >> 2;
    const int tc  = lane & 3;

#pragma unroll
    for (int i = 0; i < 8; i++) {
        int lin = t + 128 * i;
        int row = lin >> 4;
        int c4  = (lin & 15) * 4;
        const float* src = g_qkv + (size_t)(b * S_LEN + q0 + row) * D3 + h * DHE + c4;
        float4 v = *(const float4*)src;
        *(uint4*)&Qs[row][c4] = make_uint4(f2tf(v.x * 0.125f), f2tf(v.y * 0.125f),
                                           f2tf(v.z * 0.125f), f2tf(v.w * 0.125f));
    }

    const int qr0 = q0 + wid * 16 + gr;
    const int qr1 = qr0 + 8;

    float m0 = -1e30f, m1 = -1e30f, l0 = 0.f, l1 = 0.f;
    float oacc[8][4];
#pragma unroll
    for (int nt = 0; nt < 8; nt++)
#pragma unroll
        for (int r = 0; r < 4; r++) oacc[nt][r] = 0.f;

    const int kstart = (q0 - WIN > 0) ? (q0 - WIN) : 0;
    const int kend   = (q0 + 64 + WIN < S_LEN) ? (q0 + 64 + WIN) : S_LEN;

    for (int kc = kstart; kc < kend; kc += 64) {
        __syncthreads();
#pragma unroll
        for (int i = 0; i < 8; i++) {
            int lin = t + 128 * i;
            int row = lin >> 4;
            int c4  = (lin & 15) * 4;
            const float* kp = g_qkv + (size_t)(b * S_LEN + kc + row) * D3 + D_DIM + h * DHE + c4;
            float4 kv = *(const float4*)kp;
            float4 vv = *(const float4*)(kp + D_DIM);
            *(uint4*)&Ks[row][c4] = make_uint4(f2tf(kv.x), f2tf(kv.y), f2tf(kv.z), f2tf(kv.w));
            *(uint4*)&Vs[row][c4] = make_uint4(f2tf(vv.x), f2tf(vv.y), f2tf(vv.z), f2tf(vv.w));
        }
        __syncthreads();

        float sacc[8][4];
#pragma unroll
        for (int nt = 0; nt < 8; nt++)
#pragma unroll
            for (int r = 0; r < 4; r++) sacc[nt][r] = 0.f;

#pragma unroll
        for (int ks = 0; ks < 8; ks++) {
            const int qrow = wid * 16 + gr;
            uint32_t af0 = Qs[qrow][ks * 8 + tc];
            uint32_t af1 = Qs[qrow + 8][ks * 8 + tc];
            uint32_t af2 = Qs[qrow][ks * 8 + tc + 4];
            uint32_t af3 = Qs[qrow + 8][ks * 8 + tc + 4];
#pragma unroll
            for (int nt = 0; nt < 8; nt++) {
                uint32_t b0 = Ks[nt * 8 + gr][ks * 8 + tc];
                uint32_t b1 = Ks[nt * 8 + gr][ks * 8 + tc + 4];
                mma_tf32(sacc[nt][0], sacc[nt][1], sacc[nt][2], sacc[nt][3],
                         af0, af1, af2, af3, b0, b1);
            }
        }

        float mx0 = m0, mx1 = m1;
#pragma unroll
        for (int nt = 0; nt < 8; nt++) {
            const int c = kc + nt * 8 + 2 * tc;
            if (c     < qr0 - WIN || c     > qr0 + WIN) sacc[nt][0] = -1e30f;
            if (c + 1 < qr0 - WIN || c + 1 > qr0 + WIN) sacc[nt][1] = -1e30f;
            if (c     < qr1 - WIN || c     > qr1 + WIN) sacc[nt][2] = -1e30f;
            if (c + 1 < qr1 - WIN || c + 1 > qr1 + WIN) sacc[nt][3] = -1e30f;
            mx0 = fmaxf(mx0, fmaxf(sacc[nt][0], sacc[nt][1]));
            mx1 = fmaxf(mx1, fmaxf(sacc[nt][2], sacc[nt][3]));
        }
        mx0 = fmaxf(mx0, __shfl_xor_sync(0xffffffffu, mx0, 1));
        mx0 = fmaxf(mx0, __shfl_xor_sync(0xffffffffu, mx0, 2));
        mx1 = fmaxf(mx1, __shfl_xor_sync(0xffffffffu, mx1, 1));
        mx1 = fmaxf(mx1, __shfl_xor_sync(0xffffffffu, mx1, 2));

        const float alpha0 = __expf(m0 - mx0);
        const float alpha1 = __expf(m1 - mx1);

        float ps0 = 0.f, ps1 = 0.f;
        const int prow = wid * 16 + gr;
#pragma unroll
        for (int nt = 0; nt < 8; nt++) {
            float p00 = __expf(sacc[nt][0] - mx0);
            float p01 = __expf(sacc[nt][1] - mx0);
            float p10 = __expf(sacc[nt][2] - mx1);
            float p11 = __expf(sacc[nt][3] - mx1);
            ps0 += p00 + p01;
            ps1 += p10 + p11;
            *(uint2*)&Ps[prow][nt * 8 + 2 * tc]     = make_uint2(f2tf(p00), f2tf(p01));
            *(uint2*)&Ps[prow + 8][nt * 8 + 2 * tc] = make_uint2(f2tf(p10), f2tf(p11));
        }
        ps0 += __shfl_xor_sync(0xffffffffu, ps0, 1);
        ps0 += __shfl_xor_sync(0xffffffffu, ps0, 2);
        ps1 += __shfl_xor_sync(0xffffffffu, ps1, 1);
        ps1 += __shfl_xor_sync(0xffffffffu, ps1, 2);

        l0 = l0 * alpha0 + ps0;  m0 = mx0;
        l1 = l1 * alpha1 + ps1;  m1 = mx1;

#pragma unroll
        for (int nt = 0; nt < 8; nt++) {
            oacc[nt][0] *= alpha0; oacc[nt][1] *= alpha0;
            oacc[nt][2] *= alpha1; oacc[nt][3] *= alpha1;
        }

        __syncwarp();

#pragma unroll
        for (int ks = 0; ks < 8; ks++) {
            uint32_t af0 = Ps[prow][ks * 8 + tc];
            uint32_t af1 = Ps[prow + 8][ks * 8 + tc];
            uint32_t af2 = Ps[prow][ks * 8 + tc + 4];
            uint32_t af3 = Ps[prow + 8][ks * 8 + tc + 4];
#pragma unroll
            for (int nt = 0; nt < 8; nt++) {
                uint32_t b0 = Vs[ks * 8 + tc][nt * 8 + gr];
                uint32_t b1 = Vs[ks * 8 + tc + 4][nt * 8 + gr];
                mma_tf32(oacc[nt][0], oacc[nt][1], oacc[nt][2], oacc[nt][3],
                         af0, af1, af2, af3, b0, b1);
            }
        }
    }

    const float inv0 = 1.0f / l0;
    const float inv1 = 1.0f / l1;
    const size_t row0g = (size_t)(b * S_LEN) + qr0;
#pragma unroll
    for (int nt = 0; nt < 8; nt++) {
        const int col = h * DHE + nt * 8 + 2 * tc;
        *(uint32_t*)(g_attn_h + row0g * D_DIM + col) =
            f22h2(oacc[nt][0] * inv0, oacc[nt][1] * inv0);
        *(uint32_t*)(g_attn_h + (row0g + 8) * D_DIM + col) =
            f22h2(oacc[nt][2] * inv1, oacc[nt][3] * inv1);
    }
}

// ---------------- fused double LayerNorm ----------------
// out = LN2( LN1(x + attnout) + xwave )
__global__ void __launch_bounds__(256) fused_ln2_kernel(
    const float* __restrict__ X, const float* __restrict__ AO,
    const float* __restrict__ g1, const float* __restrict__ b1,
    const float* __restrict__ XW,
    const float* __restrict__ g2, const float* __restrict__ b2,
    float* __restrict__ out)
{
    __shared__ float red[8];
    const int row = blockIdx.x;
    const int t   = threadIdx.x;
    const float invD = 1.f / (float)D_DIM;

    float4 a = *(const float4*)(X  + (size_t)row * D_DIM + t * 4);
    float4 b = *(const float4*)(AO + (size_t)row * D_DIM + t * 4);
    float4 v = make_float4(a.x + b.x, a.y + b.y, a.z + b.z, a.w + b.w);

    // LN1 stats
    float s = v.x + v.y + v.z + v.w;
#pragma unroll
    for (int o = 16; o; o >>= 1) s += __shfl_xor_sync(0xffffffffu, s, o);
    if ((t & 31) == 0) red[t >> 5] = s;
    __syncthreads();
    float tot = 0.f;
#pragma unroll
    for (int i = 0; i < 8; i++) tot += red[i];
    const float mu1 = tot * invD;
    __syncthreads();

    float dx = v.x - mu1, dy = v.y - mu1, dz = v.z - mu1, dw = v.w - mu1;
    float s2 = dx * dx + dy * dy + dz * dz + dw * dw;
#pragma unroll
    for (int o = 16; o; o >>= 1) s2 += __shfl_xor_sync(0xffffffffu, s2, o);
    if ((t & 31) == 0) red[t >> 5] = s2;
    __syncthreads();
    float tot2 = 0.f;
#pragma unroll
    for (int i = 0; i < 8; i++) tot2 += red[i];
    const float inv1v = rsqrtf(tot2 * invD + 1e-5f);
    __syncthreads();

    float4 gg = *(const float4*)(g1 + t * 4);
    float4 bb = *(const float4*)(b1 + t * 4);
    float4 w  = *(const float4*)(XW + (size_t)row * D_DIM + t * 4);
    // v2 = LN1 result + xwave
    float4 v2 = make_float4(dx * inv1v * gg.x + bb.x + w.x,
                            dy * inv1v * gg.y + bb.y + w.y,
                            dz * inv1v * gg.z + bb.z + w.z,
                            dw * inv1v * gg.w + bb.w + w.w);

    // LN2 stats
    float s3 = v2.x + v2.y + v2.z + v2.w;
#pragma unroll
    for (int o = 16; o; o >>= 1) s3 += __shfl_xor_sync(0xffffffffu, s3, o);
    if ((t & 31) == 0) red[t >> 5] = s3;
    __syncthreads();
    float tot3 = 0.f;
#pragma unroll
    for (int i = 0; i < 8; i++) tot3 += red[i];
    const float mu2 = tot3 * invD;
    __syncthreads();

    float ex = v2.x - mu2, ey = v2.y - mu2, ez = v2.z - mu2, ew = v2.w - mu2;
    float s4 = ex * ex + ey * ey + ez * ez + ew * ew;
#pragma unroll
    for (int o = 16; o; o >>= 1) s4 += __shfl_xor_sync(0xffffffffu, s4, o);
    if ((t & 31) == 0) red[t >> 5] = s4;
    __syncthreads();
    float tot4 = 0.f;
#pragma unroll
    for (int i = 0; i < 8; i++) tot4 += red[i];
    const float inv2v = rsqrtf(tot4 * invD + 1e-5f);

    float4 g2v = *(const float4*)(g2 + t * 4);
    float4 b2v = *(const float4*)(b2 + t * 4);
    float4 o4 = make_float4(ex * inv2v * g2v.x + b2v.x, ey * inv2v * g2v.y + b2v.y,
                            ez * inv2v * g2v.z + b2v.z, ew * inv2v * g2v.w + b2v.w);
    *(float4*)(out + (size_t)row * D_DIM + t * 4) = o4;
}

// ---------------- spectral block: radix-8 register FFT ----------------
__device__ __forceinline__ float2 cmul(float2 a, float2 b) {
    return make_float2(a.x * b.x - a.y * b.y, a.x * b.y + a.y * b.x);
}
__device__ __forceinline__ float2 cadd(float2 a, float2 b) {
    return make_float2(a.x + b.x, a.y + b.y);
}
__device__ __forceinline__ float2 csub(float2 a, float2 b) {
    return make_float2(a.x - b.x, a.y - b.y);
}

// fused radix-8 Stockham: out[q + 8*ss*p + j*ss] = X_j * w^j, w = exp(SIGN*2pi*i*p/n)
template<int SIGN>
__device__ __forceinline__ void fft2048_r8(float2*& cur, float2*& oth)
{
    const float C8 = 0.70710678118654752f;
    const float SG = (float)SIGN;
#pragma unroll
    for (int st = 0; st < 3; st++) {
        const int ls = st * 3;
        const int ss = 1 << ls;
        const int n  = 2048 >> ls;
        const float fn = (2.0f * 3.14159265358979f * SG) / (float)n;
        const int idx = threadIdx.x;
        const int p = idx >> ls;
        const int q = idx & (ss - 1);

        float2 x0 = cur[SMAP(idx)];
        float2 x1 = cur[SMAP(idx + 256)];
        float2 x2 = cur[SMAP(idx + 512)];
        float2 x3 = cur[SMAP(idx + 768)];
        float2 x4 = cur[SMAP(idx + 1024)];
        float2 x5 = cur[SMAP(idx + 1280)];
        float2 x6 = cur[SMAP(idx + 1536)];
        float2 x7 = cur[SMAP(idx + 1792)];

        // DFT4 of evens (x0,x2,x4,x6)
        float2 es = cadd(x0, x4), ed = csub(x0, x4);
        float2 fs = cadd(x2, x6), fd = csub(x2, x6);
        float2 E0 = cadd(es, fs);
        float2 E2 = csub(es, fs);
        float2 E1 = make_float2(ed.x - SG * fd.y, ed.y + SG * fd.x);
        float2 E3 = make_float2(ed.x + SG * fd.y, ed.y - SG * fd.x);
        // DFT4 of odds (x1,x3,x5,x7)
        float2 os = cadd(x1, x5), od = csub(x1, x5);
        float2 gs = cadd(x3, x7), gd = csub(x3, x7);
        float2 O0 = cadd(os, gs);
        float2 O2 = csub(os, gs);
        float2 O1 = make_float2(od.x - SG * gd.y, od.y + SG * gd.x);
        float2 O3 = make_float2(od.x + SG * gd.y, od.y - SG * gd.x);
        // omega8^j * O_j
        float2 t0 = O0;
        float2 t1 = make_float2(C8 * (O1.x - SG * O1.y), C8 * (SG * O1.x + O1.y));
        float2 t2 = make_float2(-SG * O2.y, SG * O2.x);
        float2 t3 = make_float2(C8 * (-O3.x - SG * O3.y), C8 * (SG * O3.x - O3.y));

        float2 X0 = cadd(E0, t0), X4 = csub(E0, t0);
        float2 X1 = cadd(E1, t1), X5 = csub(E1, t1);
        float2 X2 = cadd(E2, t2), X6 = csub(E2, t2);
        float2 X3 = cadd(E3, t3), X7 = csub(E3, t3);

        float sn, cs;
        __sincosf(fn * (float)p, &sn, &cs);
        const float2 w1 = make_float2(cs, sn);
        const float2 w2 = cmul(w1, w1);
        const float2 w3 = cmul(w1, w2);
        const float2 w4 = cmul(w2, w2);
        const float2 w5 = cmul(w2, w3);
        const float2 w6 = cmul(w3, w3);
        const float2 w7 = cmul(w3, w4);

        const int ob = q + 8 * ss * p;
        oth[SMAP(ob)]          = X0;
        oth[SMAP(ob + ss)]     = cmul(X1, w1);
        oth[SMAP(ob + 2 * ss)] = cmul(X2, w2);
        oth[SMAP(ob + 3 * ss)] = cmul(X3, w3);
        oth[SMAP(ob + 4 * ss)] = cmul(X4, w4);
        oth[SMAP(ob + 5 * ss)] = cmul(X5, w5);
        oth[SMAP(ob + 6 * ss)] = cmul(X6, w6);
        oth[SMAP(ob + 7 * ss)] = cmul(X7, w7);

        __syncthreads();
        float2* tmp = cur; cur = oth; oth = tmp;
    }
    // final radix-4 stage: ss=512, p=0 -> unit twiddles
#pragma unroll
    for (int ii = 0; ii < 2; ii++) {
        const int qq = threadIdx.x + 256 * ii;
        float2 x0 = cur[SMAP(qq)];
        float2 x1 = cur[SMAP(qq + 512)];
        float2 x2 = cur[SMAP(qq + 1024)];
        float2 x3 = cur[SMAP(qq + 1536)];
        float2 a0 = cadd(x0, x2), a1 = csub(x0, x2);
        float2 b0 = cadd(x1, x3), u = csub(x1, x3);
        float2 b1 = make_float2(-SG * u.y, SG * u.x);
        oth[SMAP(qq)]        = cadd(a0, b0);
        oth[SMAP(qq + 512)]  = cadd(a1, b1);
        oth[SMAP(qq + 1024)] = csub(a0, b0);
        oth[SMAP(qq + 1536)] = csub(a1, b1);
    }
    __syncthreads();
    { float2* tmp = cur; cur = oth; oth = tmp; }
}

__global__ void __launch_bounds__(256) spectral_kernel(
    const float* __restrict__ x, const float* __restrict__ wr,
    const float* __restrict__ wi, float* __restrict__ xwave)
{
    __shared__ float2 bufA[2176];
    __shared__ float2 bufB[2176];
    const int d0 = blockIdx.x * 2;
    const int b  = blockIdx.y;

    const float* xp = x + (size_t)b * S_LEN * D_DIM + d0;
    for (int s = threadIdx.x; s < 2048; s += 256)
        bufA[SMAP(s)] = *(const float2*)(xp + (size_t)s * D_DIM);
    __syncthreads();

    float2* cur = bufA;
    float2* oth = bufB;
    fft2048_r8<-1>(cur, oth);

    for (int k = threadIdx.x; k < 2048; k += 256) {
        const int km = (2048 - k) & 2047;
        float2 Zk = cur[SMAP(k)];
        float2 Zm = cur[SMAP(km)];
        float2 Av = make_float2(0.5f * (Zk.x + Zm.x), 0.5f * (Zk.y - Zm.y));
        float2 Bc = make_float2(0.5f * (Zk.y + Zm.y), -0.5f * (Zk.x - Zm.x));
        const int   kf  = (k <= 1024) ? k : 2048 - k;
        const float sgn = (k <= 1024) ? 1.f : -1.f;
        float2 wrp = *(const float2*)(wr + (size_t)kf * D_DIM + d0);
        float2 wip = *(const float2*)(wi + (size_t)kf * D_DIM + d0);
        float2 c1 = make_float2(wrp.x, sgn * wip.x);
        float2 c2 = make_float2(wrp.y, sgn * wip.y);
        if (k == 0 || k == 1024) { c1.y = 0.f; c2.y = 0.f; }
        float2 Y1 = cmul(Av, c1);
        float2 Y2 = cmul(Bc, c2);
        oth[SMAP(k)] = make_float2(Y1.x - Y2.y, Y1.y + Y2.x);
    }
    __syncthreads();
    { float2* tmp = cur; cur = oth; oth = tmp; }

    fft2048_r8<1>(cur, oth);

    float* dst = xwave + (size_t)b * S_LEN * D_DIM + d0;
    const float invn = 1.0f / 2048.0f;
    for (int s = threadIdx.x; s < 2048; s += 256) {
        float2 r = cur[SMAP(s)];
        *(float2*)(dst + (size_t)s * D_DIM) = make_float2(r.x * invn, r.y * invn);
    }
}

// ---------------- launcher ----------------
extern "C" void kernel_launch(void* const* d_in, const int* in_sizes, int n_in,
                              void* d_out, int out_size)
{
    const float* x     = (const float*)d_in[0];
    const float* in_w  = (const float*)d_in[1];
    const float* in_b  = (const float*)d_in[2];
    const float* out_w = (const float*)d_in[3];
    const float* out_b = (const float*)d_in[4];
    const float* ln1g  = (const float*)d_in[5];
    const float* ln1b  = (const float*)d_in[6];
    const float* wr    = (const float*)d_in[7];
    const float* wi    = (const float*)d_in[8];
    const float* ln2g  = (const float*)d_in[9];
    const float* ln2b  = (const float*)d_in[10];
    float* out = (float*)d_out;

    float *qkv, *attnout, *xwave;
    __half *xh, *wh_in, *wh_out, *attn_h;
    cudaGetSymbolAddress((void**)&qkv,     g_qkv);
    cudaGetSymbolAddress((void**)&attnout, g_attnout);
    cudaGetSymbolAddress((void**)&xwave,   g_xwave);
    cudaGetSymbolAddress((void**)&xh,      g_xh);
    cudaGetSymbolAddress((void**)&wh_in,   g_wh_in);
    cudaGetSymbolAddress((void**)&wh_out,  g_wh_out);
    cudaGetSymbolAddress((void**)&attn_h,  g_attn_h);

    // converts (bandwidth-bound, tiny)
    conv_f2h<<<(NTOK * D_DIM / 4 + 255) / 256, 256>>>(x, xh, NTOK * D_DIM);
    conv_f2h<<<(D3 * D_DIM / 4 + 255) / 256, 256>>>(in_w, wh_in, D3 * D_DIM);
    conv_f2h<<<(D_DIM * D_DIM / 4 + 255) / 256, 256>>>(out_w, wh_out, D_DIM * D_DIM);

    // spectral path (independent)
    spectral_kernel<<<dim3(D_DIM / 2, B_SZ), 256>>>(x, wr, wi, xwave);

    // QKV projection (fp16, cp.async pipeline)
    gemm_fp16_pipe<<<dim3(D3 / 128, NTOK / 128), 256>>>(xh, wh_in, in_b, qkv,
                                                        NTOK, D3, D_DIM);

    // windowed flash attention (tf32 mma.sync; writes half attn)
    attn_tc_kernel<<<dim3(S_LEN / 64, NH, B_SZ), 128>>>();

    // output projection (fp16)
    gemm_fp16_pipe<<<dim3(D_DIM / 128, NTOK / 128), 256>>>(attn_h, wh_out, out_b, attnout,
                                                           NTOK, D_DIM, D_DIM);

    // out = LN2( LN1(x + attnout) + xwave )  -- fused
    fused_ln2_kernel<<<NTOK, 256>>>(x, attnout, ln1g, ln1b, xwave, ln2g, ln2b, out);
}

// round 14
// speedup vs baseline: 6.8904x; 1.0353x over previous
#include <cuda_runtime.h>
#include <cuda_fp16.h>
#include <math.h>
#include <stdint.h>

#define S_LEN 2048
#define D_DIM 1024
#define B_SZ  2
#define NH    16
#define DHE   64
#define WIN   128
#define NTOK  (B_SZ * S_LEN)   // 4096
#define D3    (3 * D_DIM)      // 3072

#define SMAP(i) ((i) + ((i) >> 4))

// ---------------- scratch ----------------
__device__ float  g_qkv[(size_t)NTOK * D3];
__device__ __half g_attn_h[(size_t)NTOK * D_DIM];
__device__ float  g_attnout[(size_t)NTOK * D_DIM];
__device__ float  g_xwave[(size_t)NTOK * D_DIM];
__device__ __half g_xh[(size_t)NTOK * D_DIM];
__device__ __half g_wh_in[(size_t)D3 * D_DIM];
__device__ __half g_wh_out[(size_t)D_DIM * D_DIM];

// ---------------- helpers ----------------
__device__ __forceinline__ uint32_t smem_u32(const void* p) {
    uint32_t a;
    asm("{ .reg .u64 t; cvta.to.shared.u64 t, %1; cvt.u32.u64 %0, t; }" : "=r"(a) : "l"(p));
    return a;
}
__device__ __forceinline__ void cpasync16(uint32_t dst, const void* src) {
    asm volatile("cp.async.ca.shared.global [%0], [%1], 16;" :: "r"(dst), "l"(src));
}
#define CP_COMMIT() asm volatile("cp.async.commit_group;" ::: "memory")
#define CP_WAIT1()  asm volatile("cp.async.wait_group 1;" ::: "memory")

__device__ __forceinline__ uint32_t f22h2(float a, float b) {
    __half2 h = __floats2half2_rn(a, b);
    return *(uint32_t*)&h;
}
__device__ __forceinline__ uint32_t f2tf(float f) {
    uint32_t u;
    asm("cvt.rna.tf32.f32 %0, %1;" : "=r"(u) : "f"(f));
    return u;
}
__device__ __forceinline__ void mma_fp16(
    float& c0, float& c1, float& c2, float& c3,
    uint32_t a0, uint32_t a1, uint32_t a2, uint32_t a3,
    uint32_t b0, uint32_t b1)
{
    asm volatile(
        "mma.sync.aligned.m16n8k16.row.col.f32.f16.f16.f32 "
        "{%0,%1,%2,%3}, {%4,%5,%6,%7}, {%8,%9}, {%0,%1,%2,%3};\n"
        : "+f"(c0), "+f"(c1), "+f"(c2), "+f"(c3)
        : "r"(a0), "r"(a1), "r"(a2), "r"(a3), "r"(b0), "r"(b1));
}
__device__ __forceinline__ void mma_tf32(
    float& c0, float& c1, float& c2, float& c3,
    uint32_t a0, uint32_t a1, uint32_t a2, uint32_t a3,
    uint32_t b0, uint32_t b1)
{
    asm volatile(
        "mma.sync.aligned.m16n8k8.row.col.f32.tf32.tf32.f32 "
        "{%0,%1,%2,%3}, {%4,%5,%6,%7}, {%8,%9}, {%0,%1,%2,%3};\n"
        : "+f"(c0), "+f"(c1), "+f"(c2), "+f"(c3)
        : "r"(a0), "r"(a1), "r"(a2), "r"(a3), "r"(b0), "r"(b1));
}

// ---------------- f32 -> f16 convert ----------------
__global__ void __launch_bounds__(256) conv_f2h(const float* __restrict__ src,
                                               __half* __restrict__ dst, int n)
{
    int i = (blockIdx.x * 256 + threadIdx.x) * 4;
    if (i < n) {
        float4 v = *(const float4*)(src + i);
        *(uint2*)(dst + i) = make_uint2(f22h2(v.x, v.y), f22h2(v.z, v.w));
    }
}

// ---------------- complex helpers ----------------
__device__ __forceinline__ float2 cmul(float2 a, float2 b) {
    return make_float2(a.x * b.x - a.y * b.y, a.x * b.y + a.y * b.x);
}
__device__ __forceinline__ float2 cadd(float2 a, float2 b) {
    return make_float2(a.x + b.x, a.y + b.y);
}
__device__ __forceinline__ float2 csub(float2 a, float2 b) {
    return make_float2(a.x - b.x, a.y - b.y);
}

// fused radix-8 Stockham (validated round 13)
template<int SIGN>
__device__ __forceinline__ void fft2048_r8(float2*& cur, float2*& oth)
{
    const float C8 = 0.70710678118654752f;
    const float SG = (float)SIGN;
#pragma unroll
    for (int st = 0; st < 3; st++) {
        const int ls = st * 3;
        const int ss = 1 << ls;
        const int n  = 2048 >> ls;
        const float fn = (2.0f * 3.14159265358979f * SG) / (float)n;
        const int idx = threadIdx.x;
        const int p = idx >> ls;
        const int q = idx & (ss - 1);

        float2 x0 = cur[SMAP(idx)];
        float2 x1 = cur[SMAP(idx + 256)];
        float2 x2 = cur[SMAP(idx + 512)];
        float2 x3 = cur[SMAP(idx + 768)];
        float2 x4 = cur[SMAP(idx + 1024)];
        float2 x5 = cur[SMAP(idx + 1280)];
        float2 x6 = cur[SMAP(idx + 1536)];
        float2 x7 = cur[SMAP(idx + 1792)];

        float2 es = cadd(x0, x4), ed = csub(x0, x4);
        float2 fs = cadd(x2, x6), fd = csub(x2, x6);
        float2 E0 = cadd(es, fs);
        float2 E2 = csub(es, fs);
        float2 E1 = make_float2(ed.x - SG * fd.y, ed.y + SG * fd.x);
        float2 E3 = make_float2(ed.x + SG * fd.y, ed.y - SG * fd.x);
        float2 os = cadd(x1, x5), od = csub(x1, x5);
        float2 gs = cadd(x3, x7), gd = csub(x3, x7);
        float2 O0 = cadd(os, gs);
        float2 O2 = csub(os, gs);
        float2 O1 = make_float2(od.x - SG * gd.y, od.y + SG * gd.x);
        float2 O3 = make_float2(od.x + SG * gd.y, od.y - SG * gd.x);
        float2 t0 = O0;
        float2 t1 = make_float2(C8 * (O1.x - SG * O1.y), C8 * (SG * O1.x + O1.y));
        float2 t2 = make_float2(-SG * O2.y, SG * O2.x);
        float2 t3 = make_float2(C8 * (-O3.x - SG * O3.y), C8 * (SG * O3.x - O3.y));

        float2 X0 = cadd(E0, t0), X4 = csub(E0, t0);
        float2 X1 = cadd(E1, t1), X5 = csub(E1, t1);
        float2 X2 = cadd(E2, t2), X6 = csub(E2, t2);
        float2 X3 = cadd(E3, t3), X7 = csub(E3, t3);

        float sn, cs;
        __sincosf(fn * (float)p, &sn, &cs);
        const float2 w1 = make_float2(cs, sn);
        const float2 w2 = cmul(w1, w1);
        const float2 w3 = cmul(w1, w2);
        const float2 w4 = cmul(w2, w2);
        const float2 w5 = cmul(w2, w3);
        const float2 w6 = cmul(w3, w3);
        const float2 w7 = cmul(w3, w4);

        const int ob = q + 8 * ss * p;
        oth[SMAP(ob)]          = X0;
        oth[SMAP(ob + ss)]     = cmul(X1, w1);
        oth[SMAP(ob + 2 * ss)] = cmul(X2, w2);
        oth[SMAP(ob + 3 * ss)] = cmul(X3, w3);
        oth[SMAP(ob + 4 * ss)] = cmul(X4, w4);
        oth[SMAP(ob + 5 * ss)] = cmul(X5, w5);
        oth[SMAP(ob + 6 * ss)] = cmul(X6, w6);
        oth[SMAP(ob + 7 * ss)] = cmul(X7, w7);

        __syncthreads();
        float2* tmp = cur; cur = oth; oth = tmp;
    }
#pragma unroll
    for (int ii = 0; ii < 2; ii++) {
        const int qq = threadIdx.x + 256 * ii;
        float2 x0 = cur[SMAP(qq)];
        float2 x1 = cur[SMAP(qq + 512)];
        float2 x2 = cur[SMAP(qq + 1024)];
        float2 x3 = cur[SMAP(qq + 1536)];
        float2 a0 = cadd(x0, x2), a1 = csub(x0, x2);
        float2 b0 = cadd(x1, x3), u = csub(x1, x3);
        float2 b1 = make_float2(-SG * u.y, SG * u.x);
        oth[SMAP(qq)]        = cadd(a0, b0);
        oth[SMAP(qq + 512)]  = cadd(a1, b1);
        oth[SMAP(qq + 1024)] = csub(a0, b0);
        oth[SMAP(qq + 1536)] = csub(a1, b1);
    }
    __syncthreads();
    { float2* tmp = cur; cur = oth; oth = tmp; }
}

// ---------------- fused QKV GEMM + spectral (one launch -> HW overlap) ----------------
#define LDP 20
#define STG 3
#define GEMM_BX (D3 / 128)                 // 24
#define GEMM_BLOCKS (GEMM_BX * (NTOK / 128))   // 768

union SmemU {
    struct { uint32_t As2[STG][128][LDP]; uint32_t Ws2[STG][128][LDP]; } g;  // 61440 B
    struct { float2 bufA[2176]; float2 bufB[2176]; } s;                      // 34816 B
};

__global__ void __launch_bounds__(256, 2) fused_qkv_spec(
    const __half* __restrict__ A, const __half* __restrict__ W,
    const float* __restrict__ bias, float* __restrict__ C,
    const float* __restrict__ x, const float* __restrict__ wr,
    const float* __restrict__ wi, float* __restrict__ xwave)
{
    __shared__ SmemU u;
    const int t = threadIdx.x;

    if (blockIdx.x < GEMM_BLOCKS) {
        // ================= QKV GEMM path (M=NTOK, N=D3, K=D_DIM) =================
        const int  N = D3, K = D_DIM;
        const int row0 = (blockIdx.x / GEMM_BX) * 128;
        const int col0 = (blockIdx.x % GEMM_BX) * 128;
        const int warp = t >> 5;
        const int lane = t & 31;
        const int gr   = lane >> 2;
        const int tc   = lane & 3;
        const int m0w  = (warp >> 2) * 64;
        const int n0w  = (warp & 3) * 32;

        const int r0c = t >> 2;          const int c0c = t & 3;
        const int r1c = (t + 256) >> 2;  const int c1c = (t + 256) & 3;

        const __half* Ar0 = A + (size_t)(row0 + r0c) * K + c0c * 8;
        const __half* Ar1 = A + (size_t)(row0 + r1c) * K + c1c * 8;
        const __half* Wr0 = W + (size_t)(col0 + r0c) * K + c0c * 8;
        const __half* Wr1 = W + (size_t)(col0 + r1c) * K + c1c * 8;

        float acc[4][4][4];
#pragma unroll
        for (int mi = 0; mi < 4; mi++)
#pragma unroll
            for (int ni = 0; ni < 4; ni++)
#pragma unroll
                for (int r = 0; r < 4; r++) acc[mi][ni][r] = 0.f;

        const int ntiles = K >> 5;

#pragma unroll
        for (int s = 0; s < 2; s++) {
            const int k0 = s << 5;
            cpasync16(smem_u32(&u.g.As2[s][r0c][c0c * 4]), Ar0 + k0);
            cpasync16(smem_u32(&u.g.As2[s][r1c][c1c * 4]), Ar1 + k0);
            cpasync16(smem_u32(&u.g.Ws2[s][r0c][c0c * 4]), Wr0 + k0);
            cpasync16(smem_u32(&u.g.Ws2[s][r1c][c1c * 4]), Wr1 + k0);
            CP_COMMIT();
        }

        int cb = 0, nst = 2;
        for (int kt = 0; kt < ntiles; kt++) {
            CP_WAIT1();
            __syncthreads();

            if (kt + 2 < ntiles) {
                const int k0 = (kt + 2) << 5;
                cpasync16(smem_u32(&u.g.As2[nst][r0c][c0c * 4]), Ar0 + k0);
                cpasync16(smem_u32(&u.g.As2[nst][r1c][c1c * 4]), Ar1 + k0);
                cpasync16(smem_u32(&u.g.Ws2[nst][r0c][c0c * 4]), Wr0 + k0);
                cpasync16(smem_u32(&u.g.Ws2[nst][r1c][c1c * 4]), Wr1 + k0);
            }
            CP_COMMIT();

#pragma unroll
            for (int kk = 0; kk < 2; kk++) {
                uint32_t af[4][4];
#pragma unroll
                for (int mi = 0; mi < 4; mi++) {
                    const int br = m0w + mi * 16;
                    af[mi][0] = u.g.As2[cb][br + gr][kk * 8 + tc];
                    af[mi][1] = u.g.As2[cb][br + gr + 8][kk * 8 + tc];
                    af[mi][2] = u.g.As2[cb][br + gr][kk * 8 + tc + 4];
                    af[mi][3] = u.g.As2[cb][br + gr + 8][kk * 8 + tc + 4];
                }
                uint32_t bf[4][2];
#pragma unroll
                for (int ni = 0; ni < 4; ni++) {
                    const int bn = n0w + ni * 8 + gr;
                    bf[ni][0] = u.g.Ws2[cb][bn][kk * 8 + tc];
                    bf[ni][1] = u.g.Ws2[cb][bn][kk * 8 + tc + 4];
                }
#pragma unroll
                for (int mi = 0; mi < 4; mi++)
#pragma unroll
                    for (int ni = 0; ni < 4; ni++)
                        mma_fp16(acc[mi][ni][0], acc[mi][ni][1], acc[mi][ni][2], acc[mi][ni][3],
                                 af[mi][0], af[mi][1], af[mi][2], af[mi][3],
                                 bf[ni][0], bf[ni][1]);
            }

            cb  = (cb  + 1) % STG;
            nst = (nst + 1) % STG;
        }

#pragma unroll
        for (int mi = 0; mi < 4; mi++) {
#pragma unroll
            for (int ni = 0; ni < 4; ni++) {
                const int r = row0 + m0w + mi * 16 + gr;
                const int c = col0 + n0w + ni * 8 + tc * 2;
                float2 bs = *(const float2*)(bias + c);
                float2 v0 = make_float2(acc[mi][ni][0] + bs.x, acc[mi][ni][1] + bs.y);
                float2 v1 = make_float2(acc[mi][ni][2] + bs.x, acc[mi][ni][3] + bs.y);
                *(float2*)(C + (size_t)r * N + c)       = v0;
                *(float2*)(C + (size_t)(r + 8) * N + c) = v1;
            }
        }
    } else {
        // ================= spectral path =================
        const int sid = blockIdx.x - GEMM_BLOCKS;
        const int d0 = (sid & 511) * 2;
        const int b  = sid >> 9;

        float2* bufA = u.s.bufA;
        float2* bufB = u.s.bufB;

        const float* xp = x + (size_t)b * S_LEN * D_DIM + d0;
        for (int s = t; s < 2048; s += 256)
            bufA[SMAP(s)] = *(const float2*)(xp + (size_t)s * D_DIM);
        __syncthreads();

        float2* cur = bufA;
        float2* oth = bufB;
        fft2048_r8<-1>(cur, oth);

        for (int k = t; k < 2048; k += 256) {
            const int km = (2048 - k) & 2047;
            float2 Zk = cur[SMAP(k)];
            float2 Zm = cur[SMAP(km)];
            float2 Av = make_float2(0.5f * (Zk.x + Zm.x), 0.5f * (Zk.y - Zm.y));
            float2 Bc = make_float2(0.5f * (Zk.y + Zm.y), -0.5f * (Zk.x - Zm.x));
            const int   kf  = (k <= 1024) ? k : 2048 - k;
            const float sgn = (k <= 1024) ? 1.f : -1.f;
            float2 wrp = *(const float2*)(wr + (size_t)kf * D_DIM + d0);
            float2 wip = *(const float2*)(wi + (size_t)kf * D_DIM + d0);
            float2 c1 = make_float2(wrp.x, sgn * wip.x);
            float2 c2 = make_float2(wrp.y, sgn * wip.y);
            if (k == 0 || k == 1024) { c1.y = 0.f; c2.y = 0.f; }
            float2 Y1 = cmul(Av, c1);
            float2 Y2 = cmul(Bc, c2);
            oth[SMAP(k)] = make_float2(Y1.x - Y2.y, Y1.y + Y2.x);
        }
        __syncthreads();
        { float2* tmp = cur; cur = oth; oth = tmp; }

        fft2048_r8<1>(cur, oth);

        float* dst = xwave + (size_t)b * S_LEN * D_DIM + d0;
        const float invn = 1.0f / 2048.0f;
        for (int s = t; s < 2048; s += 256) {
            float2 r = cur[SMAP(s)];
            *(float2*)(dst + (size_t)s * D_DIM) = make_float2(r.x * invn, r.y * invn);
        }
    }
}

// ---------------- fp16 GEMM, 3-stage cp.async pipeline (out-proj) ----------------
__global__ void __launch_bounds__(256, 2) gemm_fp16_pipe(
    const __half* __restrict__ A, const __half* __restrict__ W,
    const float* __restrict__ bias, float* __restrict__ C,
    int M, int N, int K)
{
    __shared__ uint32_t As2[STG][128][LDP];
    __shared__ uint32_t Ws2[STG][128][LDP];

    const int row0 = blockIdx.y * 128;
    const int col0 = blockIdx.x * 128;
    const int t    = threadIdx.x;
    const int warp = t >> 5;
    const int lane = t & 31;
    const int gr   = lane >> 2;
    const int tc   = lane & 3;
    const int m0w  = (warp >> 2) * 64;
    const int n0w  = (warp & 3) * 32;

    const int r0c = t >> 2;          const int c0c = t & 3;
    const int r1c = (t + 256) >> 2;  const int c1c = (t + 256) & 3;

    const __half* Ar0 = A + (size_t)(row0 + r0c) * K + c0c * 8;
    const __half* Ar1 = A + (size_t)(row0 + r1c) * K + c1c * 8;
    const __half* Wr0 = W + (size_t)(col0 + r0c) * K + c0c * 8;
    const __half* Wr1 = W + (size_t)(col0 + r1c) * K + c1c * 8;

    float acc[4][4][4];
#pragma unroll
    for (int mi = 0; mi < 4; mi++)
#pragma unroll
        for (int ni = 0; ni < 4; ni++)
#pragma unroll
            for (int r = 0; r < 4; r++) acc[mi][ni][r] = 0.f;

    const int ntiles = K >> 5;

#pragma unroll
    for (int s = 0; s < 2; s++) {
        const int k0 = s << 5;
        cpasync16(smem_u32(&As2[s][r0c][c0c * 4]), Ar0 + k0);
        cpasync16(smem_u32(&As2[s][r1c][c1c * 4]), Ar1 + k0);
        cpasync16(smem_u32(&Ws2[s][r0c][c0c * 4]), Wr0 + k0);
        cpasync16(smem_u32(&Ws2[s][r1c][c1c * 4]), Wr1 + k0);
        CP_COMMIT();
    }

    int cb = 0, nst = 2;
    for (int kt = 0; kt < ntiles; kt++) {
        CP_WAIT1();
        __syncthreads();

        if (kt + 2 < ntiles) {
            const int k0 = (kt + 2) << 5;
            cpasync16(smem_u32(&As2[nst][r0c][c0c * 4]), Ar0 + k0);
            cpasync16(smem_u32(&As2[nst][r1c][c1c * 4]), Ar1 + k0);
            cpasync16(smem_u32(&Ws2[nst][r0c][c0c * 4]), Wr0 + k0);
            cpasync16(smem_u32(&Ws2[nst][r1c][c1c * 4]), Wr1 + k0);
        }
        CP_COMMIT();

#pragma unroll
        for (int kk = 0; kk < 2; kk++) {
            uint32_t af[4][4];
#pragma unroll
            for (int mi = 0; mi < 4; mi++) {
                const int br = m0w + mi * 16;
                af[mi][0] = As2[cb][br + gr][kk * 8 + tc];
                af[mi][1] = As2[cb][br + gr + 8][kk * 8 + tc];
                af[mi][2] = As2[cb][br + gr][kk * 8 + tc + 4];
                af[mi][3] = As2[cb][br + gr + 8][kk * 8 + tc + 4];
            }
            uint32_t bf[4][2];
#pragma unroll
            for (int ni = 0; ni < 4; ni++) {
                const int bn = n0w + ni * 8 + gr;
                bf[ni][0] = Ws2[cb][bn][kk * 8 + tc];
                bf[ni][1] = Ws2[cb][bn][kk * 8 + tc + 4];
            }
#pragma unroll
            for (int mi = 0; mi < 4; mi++)
#pragma unroll
                for (int ni = 0; ni < 4; ni++)
                    mma_fp16(acc[mi][ni][0], acc[mi][ni][1], acc[mi][ni][2], acc[mi][ni][3],
                             af[mi][0], af[mi][1], af[mi][2], af[mi][3],
                             bf[ni][0], bf[ni][1]);
        }

        cb  = (cb  + 1) % STG;
        nst = (nst + 1) % STG;
    }

#pragma unroll
    for (int mi = 0; mi < 4; mi++) {
#pragma unroll
        for (int ni = 0; ni < 4; ni++) {
            const int r = row0 + m0w + mi * 16 + gr;
            const int c = col0 + n0w + ni * 8 + tc * 2;
            float2 bs = *(const float2*)(bias + c);
            float2 v0 = make_float2(acc[mi][ni][0] + bs.x, acc[mi][ni][1] + bs.y);
            float2 v1 = make_float2(acc[mi][ni][2] + bs.x, acc[mi][ni][3] + bs.y);
            *(float2*)(C + (size_t)r * N + c)       = v0;
            *(float2*)(C + (size_t)(r + 8) * N + c) = v1;
        }
    }
}

// ---------------- tensor-core windowed flash attention (tf32, unchanged) ----------------
#define QPAD 68
#define VPAD 72
__global__ void __launch_bounds__(128) attn_tc_kernel()
{
    __shared__ uint32_t Qs[64][QPAD];
    __shared__ uint32_t Ks[64][QPAD];
    __shared__ uint32_t Vs[64][VPAD];
    __shared__ uint32_t Ps[64][QPAD];

    const int q0  = blockIdx.x * 64;
    const int h   = blockIdx.y;
    const int b   = blockIdx.z;
    const int t   = threadIdx.x;
    const int wid = t >> 5;
    const int lane = t & 31;
    const int gr  = lane >> 2;
    const int tc  = lane & 3;

#pragma unroll
    for (int i = 0; i < 8; i++) {
        int lin = t + 128 * i;
        int row = lin >> 4;
        int c4  = (lin & 15) * 4;
        const float* src = g_qkv + (size_t)(b * S_LEN + q0 + row) * D3 + h * DHE + c4;
        float4 v = *(const float4*)src;
        *(uint4*)&Qs[row][c4] = make_uint4(f2tf(v.x * 0.125f), f2tf(v.y * 0.125f),
                                           f2tf(v.z * 0.125f), f2tf(v.w * 0.125f));
    }

    const int qr0 = q0 + wid * 16 + gr;
    const int qr1 = qr0 + 8;

    float m0 = -1e30f, m1 = -1e30f, l0 = 0.f, l1 = 0.f;
    float oacc[8][4];
#pragma unroll
    for (int nt = 0; nt < 8; nt++)
#pragma unroll
        for (int r = 0; r < 4; r++) oacc[nt][r] = 0.f;

    const int kstart = (q0 - WIN > 0) ? (q0 - WIN) : 0;
    const int kend   = (q0 + 64 + WIN < S_LEN) ? (q0 + 64 + WIN) : S_LEN;

    for (int kc = kstart; kc < kend; kc += 64) {
        __syncthreads();
#pragma unroll
        for (int i = 0; i < 8; i++) {
            int lin = t + 128 * i;
            int row = lin >> 4;
            int c4  = (lin & 15) * 4;
            const float* kp = g_qkv + (size_t)(b * S_LEN + kc + row) * D3 + D_DIM + h * DHE + c4;
            float4 kv = *(const float4*)kp;
            float4 vv = *(const float4*)(kp + D_DIM);
            *(uint4*)&Ks[row][c4] = make_uint4(f2tf(kv.x), f2tf(kv.y), f2tf(kv.z), f2tf(kv.w));
            *(uint4*)&Vs[row][c4] = make_uint4(f2tf(vv.x), f2tf(vv.y), f2tf(vv.z), f2tf(vv.w));
        }
        __syncthreads();

        float sacc[8][4];
#pragma unroll
        for (int nt = 0; nt < 8; nt++)
#pragma unroll
            for (int r = 0; r < 4; r++) sacc[nt][r] = 0.f;

#pragma unroll
        for (int ks = 0; ks < 8; ks++) {
            const int qrow = wid * 16 + gr;
            uint32_t af0 = Qs[qrow][ks * 8 + tc];
            uint32_t af1 = Qs[qrow + 8][ks * 8 + tc];
            uint32_t af2 = Qs[qrow][ks * 8 + tc + 4];
            uint32_t af3 = Qs[qrow + 8][ks * 8 + tc + 4];
#pragma unroll
            for (int nt = 0; nt < 8; nt++) {
                uint32_t b0 = Ks[nt * 8 + gr][ks * 8 + tc];
                uint32_t b1 = Ks[nt * 8 + gr][ks * 8 + tc + 4];
                mma_tf32(sacc[nt][0], sacc[nt][1], sacc[nt][2], sacc[nt][3],
                         af0, af1, af2, af3, b0, b1);
            }
        }

        float mx0 = m0, mx1 = m1;
#pragma unroll
        for (int nt = 0; nt < 8; nt++) {
            const int c = kc + nt * 8 + 2 * tc;
            if (c     < qr0 - WIN || c     > qr0 + WIN) sacc[nt][0] = -1e30f;
            if (c + 1 < qr0 - WIN || c + 1 > qr0 + WIN) sacc[nt][1] = -1e30f;
            if (c     < qr1 - WIN || c     > qr1 + WIN) sacc[nt][2] = -1e30f;
            if (c + 1 < qr1 - WIN || c + 1 > qr1 + WIN) sacc[nt][3] = -1e30f;
            mx0 = fmaxf(mx0, fmaxf(sacc[nt][0], sacc[nt][1]));
            mx1 = fmaxf(mx1, fmaxf(sacc[nt][2], sacc[nt][3]));
        }
        mx0 = fmaxf(mx0, __shfl_xor_sync(0xffffffffu, mx0, 1));
        mx0 = fmaxf(mx0, __shfl_xor_sync(0xffffffffu, mx0, 2));
        mx1 = fmaxf(mx1, __shfl_xor_sync(0xffffffffu, mx1, 1));
        mx1 = fmaxf(mx1, __shfl_xor_sync(0xffffffffu, mx1, 2));

        const float alpha0 = __expf(m0 - mx0);
        const float alpha1 = __expf(m1 - mx1);

        float ps0 = 0.f, ps1 = 0.f;
        const int prow = wid * 16 + gr;
#pragma unroll
        for (int nt = 0; nt < 8; nt++) {
            float p00 = __expf(sacc[nt][0] - mx0);
            float p01 = __expf(sacc[nt][1] - mx0);
            float p10 = __expf(sacc[nt][2] - mx1);
            float p11 = __expf(sacc[nt][3] - mx1);
            ps0 += p00 + p01;
            ps1 += p10 + p11;
            *(uint2*)&Ps[prow][nt * 8 + 2 * tc]     = make_uint2(f2tf(p00), f2tf(p01));
            *(uint2*)&Ps[prow + 8][nt * 8 + 2 * tc] = make_uint2(f2tf(p10), f2tf(p11));
        }
        ps0 += __shfl_xor_sync(0xffffffffu, ps0, 1);
        ps0 += __shfl_xor_sync(0xffffffffu, ps0, 2);
        ps1 += __shfl_xor_sync(0xffffffffu, ps1, 1);
        ps1 += __shfl_xor_sync(0xffffffffu, ps1, 2);

        l0 = l0 * alpha0 + ps0;  m0 = mx0;
        l1 = l1 * alpha1 + ps1;  m1 = mx1;

#pragma unroll
        for (int nt = 0; nt < 8; nt++) {
            oacc[nt][0] *= alpha0; oacc[nt][1] *= alpha0;
            oacc[nt][2] *= alpha1; oacc[nt][3] *= alpha1;
        }

        __syncwarp();

#pragma unroll
        for (int ks = 0; ks < 8; ks++) {
            uint32_t af0 = Ps[prow][ks * 8 + tc];
            uint32_t af1 = Ps[prow + 8][ks * 8 + tc];
            uint32_t af2 = Ps[prow][ks * 8 + tc + 4];
            uint32_t af3 = Ps[prow + 8][ks * 8 + tc + 4];
#pragma unroll
            for (int nt = 0; nt < 8; nt++) {
                uint32_t b0 = Vs[ks * 8 + tc][nt * 8 + gr];
                uint32_t b1 = Vs[ks * 8 + tc + 4][nt * 8 + gr];
                mma_tf32(oacc[nt][0], oacc[nt][1], oacc[nt][2], oacc[nt][3],
                         af0, af1, af2, af3, b0, b1);
            }
        }
    }

    const float inv0 = 1.0f / l0;
    const float inv1 = 1.0f / l1;
    const size_t row0g = (size_t)(b * S_LEN) + qr0;
#pragma unroll
    for (int nt = 0; nt < 8; nt++) {
        const int col = h * DHE + nt * 8 + 2 * tc;
        *(uint32_t*)(g_attn_h + row0g * D_DIM + col) =
            f22h2(oacc[nt][0] * inv0, oacc[nt][1] * inv0);
        *(uint32_t*)(g_attn_h + (row0g + 8) * D_DIM + col) =
            f22h2(oacc[nt][2] * inv1, oacc[nt][3] * inv1);
    }
}

// ---------------- fused double LayerNorm ----------------
__global__ void __launch_bounds__(256) fused_ln2_kernel(
    const float* __restrict__ X, const float* __restrict__ AO,
    const float* __restrict__ g1, const float* __restrict__ b1,
    const float* __restrict__ XW,
    const float* __restrict__ g2, const float* __restrict__ b2,
    float* __restrict__ out)
{
    __shared__ float red[8];
    const int row = blockIdx.x;
    const int t   = threadIdx.x;
    const float invD = 1.f / (float)D_DIM;

    float4 a = *(const float4*)(X  + (size_t)row * D_DIM + t * 4);
    float4 b = *(const float4*)(AO + (size_t)row * D_DIM + t * 4);
    float4 v = make_float4(a.x + b.x, a.y + b.y, a.z + b.z, a.w + b.w);

    float s = v.x + v.y + v.z + v.w;
#pragma unroll
    for (int o = 16; o; o >>= 1) s += __shfl_xor_sync(0xffffffffu, s, o);
    if ((t & 31) == 0) red[t >> 5] = s;
    __syncthreads();
    float tot = 0.f;
#pragma unroll
    for (int i = 0; i < 8; i++) tot += red[i];
    const float mu1 = tot * invD;
    __syncthreads();

    float dx = v.x - mu1, dy = v.y - mu1, dz = v.z - mu1, dw = v.w - mu1;
    float s2 = dx * dx + dy * dy + dz * dz + dw * dw;
#pragma unroll
    for (int o = 16; o; o >>= 1) s2 += __shfl_xor_sync(0xffffffffu, s2, o);
    if ((t & 31) == 0) red[t >> 5] = s2;
    __syncthreads();
    float tot2 = 0.f;
#pragma unroll
    for (int i = 0; i < 8; i++) tot2 += red[i];
    const float inv1v = rsqrtf(tot2 * invD + 1e-5f);
    __syncthreads();

    float4 gg = *(const float4*)(g1 + t * 4);
    float4 bb = *(const float4*)(b1 + t * 4);
    float4 w  = *(const float4*)(XW + (size_t)row * D_DIM + t * 4);
    float4 v2 = make_float4(dx * inv1v * gg.x + bb.x + w.x,
                            dy * inv1v * gg.y + bb.y + w.y,
                            dz * inv1v * gg.z + bb.z + w.z,
                            dw * inv1v * gg.w + bb.w + w.w);

    float s3 = v2.x + v2.y + v2.z + v2.w;
#pragma unroll
    for (int o = 16; o; o >>= 1) s3 += __shfl_xor_sync(0xffffffffu, s3, o);
    if ((t & 31) == 0) red[t >> 5] = s3;
    __syncthreads();
    float tot3 = 0.f;
#pragma unroll
    for (int i = 0; i < 8; i++) tot3 += red[i];
    const float mu2 = tot3 * invD;
    __syncthreads();

    float ex = v2.x - mu2, ey = v2.y - mu2, ez = v2.z - mu2, ew = v2.w - mu2;
    float s4 = ex * ex + ey * ey + ez * ez + ew * ew;
#pragma unroll
    for (int o = 16; o; o >>= 1) s4 += __shfl_xor_sync(0xffffffffu, s4, o);
    if ((t & 31) == 0) red[t >> 5] = s4;
    __syncthreads();
    float tot4 = 0.f;
#pragma unroll
    for (int i = 0; i < 8; i++) tot4 += red[i];
    const float inv2v = rsqrtf(tot4 * invD + 1e-5f);

    float4 g2v = *(const float4*)(g2 + t * 4);
    float4 b2v = *(const float4*)(b2 + t * 4);
    float4 o4 = make_float4(ex * inv2v * g2v.x + b2v.x, ey * inv2v * g2v.y + b2v.y,
                            ez * inv2v * g2v.z + b2v.z, ew * inv2v * g2v.w + b2v.w);
    *(float4*)(out + (size_t)row * D_DIM + t * 4) = o4;
}

// ---------------- launcher ----------------
extern "C" void kernel_launch(void* const* d_in, const int* in_sizes, int n_in,
                              void* d_out, int out_size)
{
    const float* x     = (const float*)d_in[0];
    const float* in_w  = (const float*)d_in[1];
    const float* in_b  = (const float*)d_in[2];
    const float* out_w = (const float*)d_in[3];
    const float* out_b = (const float*)d_in[4];
    const float* ln1g  = (const float*)d_in[5];
    const float* ln1b  = (const float*)d_in[6];
    const float* wr    = (const float*)d_in[7];
    const float* wi    = (const float*)d_in[8];
    const float* ln2g  = (const float*)d_in[9];
    const float* ln2b  = (const float*)d_in[10];
    float* out = (float*)d_out;

    float *qkv, *attnout, *xwave;
    __half *xh, *wh_in, *wh_out, *attn_h;
    cudaGetSymbolAddress((void**)&qkv,     g_qkv);
    cudaGetSymbolAddress((void**)&attnout, g_attnout);
    cudaGetSymbolAddress((void**)&xwave,   g_xwave);
    cudaGetSymbolAddress((void**)&xh,      g_xh);
    cudaGetSymbolAddress((void**)&wh_in,   g_wh_in);
    cudaGetSymbolAddress((void**)&wh_out,  g_wh_out);
    cudaGetSymbolAddress((void**)&attn_h,  g_attn_h);

    // converts (bandwidth-bound, tiny)
    conv_f2h<<<(NTOK * D_DIM / 4 + 255) / 256, 256>>>(x, xh, NTOK * D_DIM);
    conv_f2h<<<(D3 * D_DIM / 4 + 255) / 256, 256>>>(in_w, wh_in, D3 * D_DIM);
    conv_f2h<<<(D_DIM * D_DIM / 4 + 255) / 256, 256>>>(out_w, wh_out, D_DIM * D_DIM);

    // QKV GEMM + spectral FFT in ONE launch (HW overlap)
    fused_qkv_spec<<<GEMM_BLOCKS + 1024, 256>>>(xh, wh_in, in_b, qkv,
                                                x, wr, wi, xwave);

    // windowed flash attention (tf32 mma.sync; writes half attn)
    attn_tc_kernel<<<dim3(S_LEN / 64, NH, B_SZ), 128>>>();

    // output projection (fp16)
    gemm_fp16_pipe<<<dim3(D_DIM / 128, NTOK / 128), 256>>>(attn_h, wh_out, out_b, attnout,
                                                           NTOK, D_DIM, D_DIM);

    // out = LN2( LN1(x + attnout) + xwave )  -- fused
    fused_ln2_kernel<<<NTOK, 256>>>(x, attnout, ln1g, ln1b, xwave, ln2g, ln2b, out);
}